// round 1
// baseline (speedup 1.0000x reference)
#include <cuda_runtime.h>
#include <math.h>

#define NB 256
#define NT 128
#define ND 1024
#define NH 512
#define NG 2048
#define NBT (NB*NT)
#define NE 64
#define NCC 128
#define NCK 8
#define CKS 16
#define NP 50
#define NF2 3123
#define NF3 3173

// ---------------- scratch (device globals; no runtime allocation) ----------------
__device__ float g_xg_f[(size_t)NBT*NG];   // 268 MB
__device__ float g_xg_b[(size_t)NBT*NG];   // 268 MB
__device__ float g_Hseq[(size_t)NBT*ND];   // 134 MB
__device__ float g_z[(size_t)NBT*ND];      // 134 MB
__device__ float g_hbuf[2][2][NB*NH];
__device__ float g_cbuf[2][NB*NH];
__device__ int   g_rev[NBT];
__device__ float g_biasf[NG];
__device__ float g_biasb[NG];
__device__ float g_colsum[ND];
__device__ float g_colsq[ND];
__device__ float g_mu[ND];
__device__ float g_rs[ND];
__device__ float g_alpha[NBT];
__device__ float g_asum[NB];
__device__ float g_U[NB*ND];
__device__ float g_chunk[NE*NCK*ND];
__device__ float g_delta2[NE*NCK*NF2];
__device__ float g_hid2[NE*NCK*ND];
__device__ float g_extra[NE*NCK];
__device__ float g_delta3[(size_t)NE*NCC*NF3]; // 104 MB
__device__ float g_h3[(size_t)NE*NCC*ND];      // 33 MB

// ---------------- helpers ----------------
__device__ __forceinline__ float blockReduceSum(float v) {
    __shared__ float sh[33];
    int lane = threadIdx.x & 31, wid = threadIdx.x >> 5;
    #pragma unroll
    for (int o = 16; o; o >>= 1) v += __shfl_down_sync(0xffffffffu, v, o);
    __syncthreads();                // protect sh from a previous call
    if (lane == 0) sh[wid] = v;
    __syncthreads();
    float r = 0.f;
    int nw = blockDim.x >> 5;
    if (threadIdx.x < nw) r = sh[threadIdx.x];
    if (wid == 0) {
        #pragma unroll
        for (int o = 16; o; o >>= 1) r += __shfl_down_sync(0xffffffffu, r, o);
        if (lane == 0) sh[32] = r;
    }
    __syncthreads();
    return sh[32];
}

__device__ __forceinline__ float leakyf(float v) { return v >= 0.f ? v : 0.01f * v; }
__device__ __forceinline__ float sigm(float v) { return 1.f / (1.f + expf(-v)); }

// ---------------- prep: rev index, combined biases, state init, colstat zero ----------------
__global__ void k_prep(const float* __restrict__ bihf, const float* __restrict__ bhhf,
                       const float* __restrict__ bihb, const float* __restrict__ bhhb,
                       const int* __restrict__ lens) {
    int i = blockIdx.x * blockDim.x + threadIdx.x;
    if (i < NBT) {
        int b = i / NT, t = i % NT, L = lens[b];
        g_rev[i] = b * NT + (t < L ? L - 1 - t : t);
    }
    if (i < NG) { g_biasf[i] = bihf[i] + bhhf[i]; g_biasb[i] = bihb[i] + bhhb[i]; }
    if (i < ND) { g_colsum[i] = 0.f; g_colsq[i] = 0.f; }
    if (i < NB * NH) {
        g_hbuf[0][0][i] = 0.f; g_hbuf[1][0][i] = 0.f;
        g_cbuf[0][i] = 0.f;    g_cbuf[1][i] = 0.f;
    }
}

// ---------------- generic fp32 GEMM: C[M,N] = A[M,K] (row-gathered) * Bw[N,K]^T + bias ----------------
// M, N always multiples of 128 at call sites; K arbitrary (guarded).
__global__ __launch_bounds__(256) void k_sgemm(
    const float* __restrict__ A, const float* __restrict__ Bw,
    const float* __restrict__ bias, float* __restrict__ C,
    int M, int N, int K, const int* __restrict__ gather)
{
    __shared__ float As[8][132];
    __shared__ float Bs[8][132];
    const int tid = threadIdx.x;
    const int m0 = blockIdx.y * 128, n0 = blockIdx.x * 128;
    const int tr = tid >> 4, tc = tid & 15;
    const int lk = tid & 7, lm = tid >> 3;
    float acc[8][8];
    #pragma unroll
    for (int i = 0; i < 8; i++)
        #pragma unroll
        for (int j = 0; j < 8; j++) acc[i][j] = 0.f;

    for (int k0 = 0; k0 < K; k0 += 8) {
        bool kin = (k0 + lk) < K;
        #pragma unroll
        for (int i = 0; i < 4; i++) {
            int m = lm + i * 32;
            float va = 0.f, vb = 0.f;
            if (kin) {
                int row = gather ? gather[m0 + m] : (m0 + m);
                va = A[(size_t)row * K + k0 + lk];
                vb = Bw[(size_t)(n0 + m) * K + k0 + lk];
            }
            As[lk][m] = va;
            Bs[lk][m] = vb;
        }
        __syncthreads();
        #pragma unroll
        for (int kk = 0; kk < 8; kk++) {
            float a[8], b[8];
            #pragma unroll
            for (int i = 0; i < 8; i++) a[i] = As[kk][tr * 8 + i];
            #pragma unroll
            for (int j = 0; j < 8; j++) b[j] = Bs[kk][tc * 8 + j];
            #pragma unroll
            for (int i = 0; i < 8; i++)
                #pragma unroll
                for (int j = 0; j < 8; j++)
                    acc[i][j] = fmaf(a[i], b[j], acc[i][j]);
        }
        __syncthreads();
    }
    #pragma unroll
    for (int i = 0; i < 8; i++) {
        size_t m = (size_t)m0 + tr * 8 + i;
        #pragma unroll
        for (int j = 0; j < 8; j++) {
            int n = n0 + tc * 8 + j;
            C[m * N + n] = acc[i][j] + (bias ? bias[n] : 0.f);
        }
    }
}

// ---------------- per-step LSTM: g += h@Whh^T, gates, state update, output scatter ----------------
// grid (NH/16, NB/64, 2), 256 threads. Forward writes Hseq[:, :, 0:512],
// backward writes reversed-in-time rows at offset 512.
__global__ __launch_bounds__(256) void k_lstm(
    int t, const float* __restrict__ Whhf, const float* __restrict__ Whhb,
    const int* __restrict__ lens)
{
    const int dir = blockIdx.z;
    const float* __restrict__ Whh = dir ? Whhb : Whhf;
    const float* __restrict__ xg  = dir ? g_xg_b : g_xg_f;
    const float* __restrict__ hr  = g_hbuf[dir][t & 1];
    float* __restrict__ hw        = g_hbuf[dir][(t + 1) & 1];
    float* __restrict__ cc        = g_cbuf[dir];
    __shared__ float Hs[16][66];
    __shared__ float Ws[16][66];
    const int tid = threadIdx.x;
    const int tx = tid & 15, ty = tid >> 4;
    const int b0 = blockIdx.y * 64, u0 = blockIdx.x * 16;
    const int lk = tid & 15, lr = tid >> 4;
    float acc[4][4];
    #pragma unroll
    for (int i = 0; i < 4; i++)
        #pragma unroll
        for (int j = 0; j < 4; j++) acc[i][j] = 0.f;

    for (int k0 = 0; k0 < NH; k0 += 16) {
        #pragma unroll
        for (int i = 0; i < 4; i++) {
            int rr = lr + i * 16;
            Hs[lk][rr] = hr[(size_t)(b0 + rr) * NH + k0 + lk];
            int g = rr >> 4, uu = rr & 15;
            Ws[lk][rr] = Whh[(size_t)(g * NH + u0 + uu) * NH + k0 + lk];
        }
        __syncthreads();
        #pragma unroll
        for (int kk = 0; kk < 16; kk++) {
            float hv[4];
            #pragma unroll
            for (int bi = 0; bi < 4; bi++) hv[bi] = Hs[kk][ty * 4 + bi];
            #pragma unroll
            for (int g = 0; g < 4; g++) {
                float w = Ws[kk][g * 16 + tx];
                #pragma unroll
                for (int bi = 0; bi < 4; bi++) acc[bi][g] = fmaf(hv[bi], w, acc[bi][g]);
            }
        }
        __syncthreads();
    }
    #pragma unroll
    for (int bi = 0; bi < 4; bi++) {
        int b = b0 + ty * 4 + bi;
        int u = u0 + tx;
        int L = lens[b];
        bool msk = t < L;
        size_t xrow = ((size_t)b * NT + t) * NG;
        float pi = xg[xrow + u]          + acc[bi][0];
        float pf = xg[xrow + NH + u]     + acc[bi][1];
        float pg = xg[xrow + 2 * NH + u] + acc[bi][2];
        float po = xg[xrow + 3 * NH + u] + acc[bi][3];
        float ig = sigm(pi), fg = sigm(pf), gv = tanhf(pg), og = sigm(po);
        size_t hidx = (size_t)b * NH + u;
        float cold = cc[hidx];
        float cnew = fg * cold + ig * gv;
        float hnew = og * tanhf(cnew);
        cc[hidx] = msk ? cnew : cold;
        hw[hidx] = msk ? hnew : hr[hidx];
        int tout = dir ? (msk ? (L - 1 - t) : t) : t;
        g_Hseq[((size_t)b * NT + tout) * ND + dir * NH + u] = msk ? hnew : 0.f;
    }
}

// ---------------- BN column stats over [NBT, ND] ----------------
__global__ void k_colstats() {  // grid (ND/32, 32), block (32,8)
    int col = blockIdx.x * 32 + threadIdx.x;
    int r0 = blockIdx.y * (NBT / 32);
    float s = 0.f, q = 0.f;
    for (int r = r0 + threadIdx.y; r < r0 + NBT / 32; r += 8) {
        float v = g_z[(size_t)r * ND + col];
        s += v; q += v * v;
    }
    __shared__ float ss[8][33], qq[8][33];
    ss[threadIdx.y][threadIdx.x] = s;
    qq[threadIdx.y][threadIdx.x] = q;
    __syncthreads();
    if (threadIdx.y == 0) {
        #pragma unroll
        for (int k = 1; k < 8; k++) { s += ss[k][threadIdx.x]; q += qq[k][threadIdx.x]; }
        atomicAdd(&g_colsum[col], s);
        atomicAdd(&g_colsq[col], q);
    }
}

__global__ void k_finalize() {  // grid 4 x 256
    int d = blockIdx.x * 256 + threadIdx.x;
    if (d < ND) {
        float mean = g_colsum[d] / (float)NBT;
        float var  = g_colsq[d] / (float)NBT - mean * mean;
        g_mu[d] = mean;
        g_rs[d] = rsqrtf(var + 1e-5f);
    }
}

// alpha[m] = sum_d leaky(bn(z[m,d])) * s2w[d]
__global__ void k_alpha(const float* __restrict__ s2w) {  // grid NBT x 256
    size_t row = blockIdx.x;
    float p = 0.f;
    for (int d = threadIdx.x; d < ND; d += 256) {
        float v = (g_z[row * ND + d] - g_mu[d]) * g_rs[d];
        p += leakyf(v) * s2w[d];
    }
    p = blockReduceSum(p);
    if (threadIdx.x == 0) g_alpha[row] = p;
}

__global__ void k_asum(const int* __restrict__ lens) {  // grid NB x 128
    int b = blockIdx.x;
    int L = lens[b];
    float s = 0.f;
    for (int t = threadIdx.x; t < L; t += 128) s += g_alpha[b * NT + t];
    s = blockReduceSum(s);
    if (threadIdx.x == 0) g_asum[b] = s + 1e-9f;
}

// U[b,d] = sum_{t<L} (alpha[b,t]/asum[b]) * Hseq[b,t,d]
__global__ void k_U(const int* __restrict__ lens) {  // grid (ND/256, NB) x 256
    int b = blockIdx.y;
    int d = blockIdx.x * 256 + threadIdx.x;
    int L = lens[b];
    float inv = 1.f / g_asum[b];
    float s = 0.f;
    for (int t = 0; t < L; t++)
        s += g_alpha[b * NT + t] * g_Hseq[((size_t)b * NT + t) * ND + d];
    g_U[(size_t)b * ND + d] = s * inv;
}

// L output: zeros, then scatter ones at label positions
__global__ void k_L(const int* __restrict__ label3, float* __restrict__ outL) { // 1 block x 256
    for (int i = threadIdx.x; i < NE * NCC; i += 256) outL[i] = 0.f;
    __syncthreads();
    if (threadIdx.x < NE) {
        for (int j = 0; j < 3; j++) {
            int v = label3[threadIdx.x * 3 + j];
            if (v >= 0) outL[threadIdx.x * NCC + v] = 1.f;
        }
    }
}

// chunk attention: sc = softmax_c(emo . cau_chunk), chunkEmb = sc @ chunk
__global__ void k_chunk() {  // grid (NCK, NE) x 256
    int e = blockIdx.y, n = blockIdx.x;
    const float* __restrict__ emo  = g_U + (size_t)e * ND;
    const float* __restrict__ cau0 = g_U + (size_t)(NE + n * CKS) * ND;
    __shared__ float logits[CKS];
    __shared__ float sc[CKS];
    int w = threadIdx.x >> 5, lane = threadIdx.x & 31;
    float a0 = 0.f, a1 = 0.f;
    for (int d = lane; d < ND; d += 32) {
        float ed = emo[d];
        a0 += ed * cau0[(size_t)(2 * w) * ND + d];
        a1 += ed * cau0[(size_t)(2 * w + 1) * ND + d];
    }
    #pragma unroll
    for (int o = 16; o; o >>= 1) {
        a0 += __shfl_down_sync(0xffffffffu, a0, o);
        a1 += __shfl_down_sync(0xffffffffu, a1, o);
    }
    if (lane == 0) { logits[2 * w] = a0; logits[2 * w + 1] = a1; }
    __syncthreads();
    if (threadIdx.x == 0) {
        float mx = logits[0];
        for (int c = 1; c < CKS; c++) mx = fmaxf(mx, logits[c]);
        float s = 0.f;
        for (int c = 0; c < CKS; c++) { sc[c] = expf(logits[c] - mx); s += sc[c]; }
        float si = 1.f / s;
        for (int c = 0; c < CKS; c++) sc[c] *= si;
    }
    __syncthreads();
    for (int d = threadIdx.x; d < ND; d += 256) {
        float v = 0.f;
        #pragma unroll
        for (int c = 0; c < CKS; c++) v += sc[c] * cau0[(size_t)c * ND + d];
        g_chunk[(size_t)(e * NCK + n) * ND + d] = v;
    }
}

// delta2[e,n,:] = [emo, chunk, dist, emo*chunk, pos]
__global__ void k_delta2(const float* __restrict__ pos) {  // grid (NCK, NE) x 256
    int e = blockIdx.y, n = blockIdx.x;
    int row = e * NCK + n;
    const float* __restrict__ emo = g_U + (size_t)e * ND;
    const float* __restrict__ ch  = g_chunk + (size_t)row * ND;
    float p = 0.f;
    for (int d = threadIdx.x; d < ND; d += 256) {
        float dd = emo[d] - ch[d];
        p += dd * dd;
    }
    p = blockReduceSum(p);
    float dist = sqrtf(p);
    size_t base = (size_t)row * NF2;
    for (int f = threadIdx.x; f < NF2; f += 256) {
        float v;
        if (f < ND) v = emo[f];
        else if (f < 2 * ND) v = ch[f - ND];
        else if (f == 2 * ND) v = dist;
        else if (f < 3 * ND + 1) v = emo[f - 2 * ND - 1] * ch[f - 2 * ND - 1];
        else v = pos[(size_t)row * NP + (f - (3 * ND + 1))];
        g_delta2[base + f] = v;
    }
}

// per-emo BN over 8 rows + leaky (in place)
__global__ void k_bn2() {  // grid (ND/256, NE) x 256
    int e = blockIdx.y;
    int d = blockIdx.x * 256 + threadIdx.x;
    float vals[NCK];
    float s = 0.f, q = 0.f;
    #pragma unroll
    for (int n = 0; n < NCK; n++) {
        float v = g_hid2[(size_t)(e * NCK + n) * ND + d];
        vals[n] = v; s += v; q += v * v;
    }
    float mean = s / (float)NCK;
    float var = q / (float)NCK - mean * mean;
    float r = rsqrtf(var + 1e-5f);
    #pragma unroll
    for (int n = 0; n < NCK; n++)
        g_hid2[(size_t)(e * NCK + n) * ND + d] = leakyf((vals[n] - mean) * r);
}

// out2 = log_softmax(hidden @ Wo^T + b); extra = argmax
__global__ void k_out2(const float* __restrict__ Wow, const float* __restrict__ Wob,
                       float* __restrict__ out) {  // grid NE*NCK x 256
    int row = blockIdx.x;
    float p0 = 0.f, p1 = 0.f;
    for (int d = threadIdx.x; d < ND; d += 256) {
        float h = g_hid2[(size_t)row * ND + d];
        p0 += h * Wow[d];
        p1 += h * Wow[ND + d];
    }
    p0 = blockReduceSum(p0);
    p1 = blockReduceSum(p1);
    if (threadIdx.x == 0) {
        float l0 = p0 + Wob[0], l1 = p1 + Wob[1];
        float mx = fmaxf(l0, l1);
        float lse = mx + logf(expf(l0 - mx) + expf(l1 - mx));
        out[row * 2 + 0] = l0 - lse;
        out[row * 2 + 1] = l1 - lse;
        g_extra[row] = (l1 > l0) ? 1.f : 0.f;
    }
}

// delta3[e,j,:] = [emo, cau_j, dist, emo*cau_j, dis, extra*50]
__global__ void k_delta3(const float* __restrict__ dis) {  // grid (NCC, NE) x 256
    int e = blockIdx.y, j = blockIdx.x;
    const float* __restrict__ emo = g_U + (size_t)e * ND;
    const float* __restrict__ y   = g_U + (size_t)(NE + j) * ND;
    float p = 0.f;
    for (int d = threadIdx.x; d < ND; d += 256) {
        float dd = emo[d] - y[d];
        p += dd * dd;
    }
    p = blockReduceSum(p);
    float dist = sqrtf(p);
    float ext = g_extra[e * NCK + (j >> 4)];
    size_t base = (size_t)(e * NCC + j) * NF3;
    for (int f = threadIdx.x; f < NF3; f += 256) {
        float v;
        if (f < ND) v = emo[f];
        else if (f < 2 * ND) v = y[f - ND];
        else if (f == 2 * ND) v = dist;
        else if (f < 3 * ND + 1) v = emo[f - 2 * ND - 1] * y[f - 2 * ND - 1];
        else if (f < 3 * ND + 1 + NP) v = dis[(size_t)(e * NCC + j) * NP + (f - (3 * ND + 1))];
        else v = ext;
        g_delta3[base + f] = v;
    }
}

// per-emo BN over 128 rows + leaky (in place)
__global__ void k_bn3() {  // grid (ND/256, NE) x 256
    int e = blockIdx.y;
    int d = blockIdx.x * 256 + threadIdx.x;
    float s = 0.f, q = 0.f;
    for (int j = 0; j < NCC; j++) {
        float v = g_h3[(size_t)(e * NCC + j) * ND + d];
        s += v; q += v * v;
    }
    float mean = s / (float)NCC;
    float var = q / (float)NCC - mean * mean;
    float r = rsqrtf(var + 1e-5f);
    for (int j = 0; j < NCC; j++) {
        size_t idx = (size_t)(e * NCC + j) * ND + d;
        g_h3[idx] = leakyf((g_h3[idx] - mean) * r);
    }
}

// p3 = log_softmax(h3 @ cls^T + b)
__global__ void k_cls(const float* __restrict__ clsw, const float* __restrict__ clsb,
                      float* __restrict__ outp) {  // grid (NCC, NE) x 256
    int e = blockIdx.y, j = blockIdx.x;
    int row = e * NCC + j;
    float p0 = 0.f, p1 = 0.f;
    for (int d = threadIdx.x; d < ND; d += 256) {
        float h = g_h3[(size_t)row * ND + d];
        p0 += h * clsw[d];
        p1 += h * clsw[ND + d];
    }
    p0 = blockReduceSum(p0);
    p1 = blockReduceSum(p1);
    if (threadIdx.x == 0) {
        float l0 = p0 + clsb[0], l1 = p1 + clsb[1];
        float mx = fmaxf(l0, l1);
        float lse = mx + logf(expf(l0 - mx) + expf(l1 - mx));
        outp[row * 2 + 0] = l0 - lse;
        outp[row * 2 + 1] = l1 - lse;
    }
}

// ---------------- host launcher ----------------
extern "C" void kernel_launch(void* const* d_in, const int* in_sizes, int n_in,
                              void* d_out, int out_size) {
    const float *word, *pos, *dis, *Wihf, *Whhf, *bihf, *bhhf, *Wihb, *Whhb, *bihb, *bhhb;
    const float *s1w, *s1b, *s2w, *W2w, *W2b, *Wow, *Wob, *W3w, *W3b, *clsw, *clsb;
    const int *lens, *label3;
    if (in_sizes[3] == 256) {
        // setup_inputs dict insertion order
        word = (const float*)d_in[0];  pos = (const float*)d_in[1];  dis = (const float*)d_in[2];
        lens = (const int*)d_in[3];    label3 = (const int*)d_in[4];
        Wihf = (const float*)d_in[7];  Whhf = (const float*)d_in[8];
        bihf = (const float*)d_in[9];  bhhf = (const float*)d_in[10];
        Wihb = (const float*)d_in[11]; Whhb = (const float*)d_in[12];
        bihb = (const float*)d_in[13]; bhhb = (const float*)d_in[14];
        s1w = (const float*)d_in[15];  s1b = (const float*)d_in[16]; s2w = (const float*)d_in[17];
        W2w = (const float*)d_in[18];  W2b = (const float*)d_in[19];
        Wow = (const float*)d_in[20];  Wob = (const float*)d_in[21];
        W3w = (const float*)d_in[22];  W3b = (const float*)d_in[23];
        clsw = (const float*)d_in[24]; clsb = (const float*)d_in[25];
    } else {
        // reference() signature order
        word = (const float*)d_in[0];  pos = (const float*)d_in[1];  dis = (const float*)d_in[2];
        Wihf = (const float*)d_in[3];  Whhf = (const float*)d_in[4];
        bihf = (const float*)d_in[5];  bhhf = (const float*)d_in[6];
        Wihb = (const float*)d_in[7];  Whhb = (const float*)d_in[8];
        bihb = (const float*)d_in[9];  bhhb = (const float*)d_in[10];
        s1w = (const float*)d_in[11];  s1b = (const float*)d_in[12]; s2w = (const float*)d_in[13];
        W2w = (const float*)d_in[14];  W2b = (const float*)d_in[15];
        Wow = (const float*)d_in[16];  Wob = (const float*)d_in[17];
        W3w = (const float*)d_in[18];  W3b = (const float*)d_in[19];
        clsw = (const float*)d_in[20]; clsb = (const float*)d_in[21];
        lens = (const int*)d_in[22];   label3 = (const int*)d_in[23];
    }
    float* out = (float*)d_out;
    float* out_p3 = out + NE * NCK * 2;           // 1024
    float* out_L  = out_p3 + NE * NCC * 2;        // 1024 + 16384

    void *p_xgf, *p_xgb, *p_Hseq, *p_z, *p_rev, *p_bf, *p_bb, *p_d2, *p_h2, *p_d3, *p_h3;
    cudaGetSymbolAddress(&p_xgf, g_xg_f);
    cudaGetSymbolAddress(&p_xgb, g_xg_b);
    cudaGetSymbolAddress(&p_Hseq, g_Hseq);
    cudaGetSymbolAddress(&p_z, g_z);
    cudaGetSymbolAddress(&p_rev, g_rev);
    cudaGetSymbolAddress(&p_bf, g_biasf);
    cudaGetSymbolAddress(&p_bb, g_biasb);
    cudaGetSymbolAddress(&p_d2, g_delta2);
    cudaGetSymbolAddress(&p_h2, g_hid2);
    cudaGetSymbolAddress(&p_d3, g_delta3);
    cudaGetSymbolAddress(&p_h3, g_h3);

    // 1. prep
    k_prep<<<512, 256>>>(bihf, bhhf, bihb, bhhb, lens);

    // 2-3. input projections (xg = x @ Wih^T + bih + bhh), backward uses reversed rows
    k_sgemm<<<dim3(NG / 128, NBT / 128), 256>>>(word, Wihf, (const float*)p_bf, (float*)p_xgf,
                                                NBT, NG, ND, nullptr);
    k_sgemm<<<dim3(NG / 128, NBT / 128), 256>>>(word, Wihb, (const float*)p_bb, (float*)p_xgb,
                                                NBT, NG, ND, (const int*)p_rev);

    // 4. recurrence: 128 steps, both directions per launch
    for (int t = 0; t < NT; t++)
        k_lstm<<<dim3(NH / 16, NB / 64, 2), 256>>>(t, Whhf, Whhb, lens);

    // 5. attention projection z = Hseq @ s1_w^T + s1_b
    k_sgemm<<<dim3(ND / 128, NBT / 128), 256>>>((const float*)p_Hseq, s1w, s1b, (float*)p_z,
                                                NBT, ND, ND, nullptr);

    // 6-9. BN stats, alpha, normalization, U
    k_colstats<<<dim3(ND / 32, 32), dim3(32, 8)>>>();
    k_finalize<<<4, 256>>>();
    k_alpha<<<NBT, 256>>>(s2w);
    k_asum<<<NB, 128>>>(lens);
    k_U<<<dim3(ND / 256, NB), 256>>>(lens);

    // 10. ground-truth label matrix
    k_L<<<1, 256>>>(label3, out_L);

    // 11-15. phase 2
    k_chunk<<<dim3(NCK, NE), 256>>>();
    k_delta2<<<dim3(NCK, NE), 256>>>(pos);
    k_sgemm<<<dim3(ND / 128, (NE * NCK) / 128), 256>>>((const float*)p_d2, W2w, W2b,
                                                       (float*)p_h2, NE * NCK, ND, NF2, nullptr);
    k_bn2<<<dim3(ND / 256, NE), 256>>>();
    k_out2<<<NE * NCK, 256>>>(Wow, Wob, out);

    // 16-19. phase 3
    k_delta3<<<dim3(NCC, NE), 256>>>(dis);
    k_sgemm<<<dim3(ND / 128, (NE * NCC) / 128), 256>>>((const float*)p_d3, W3w, W3b,
                                                       (float*)p_h3, NE * NCC, ND, NF3, nullptr);
    k_bn3<<<dim3(ND / 256, NE), 256>>>();
    k_cls<<<dim3(NCC, NE), 256>>>(clsw, clsb, out_p3);
}

// round 3
// speedup vs baseline: 1.6995x; 1.6995x over previous
#include <cuda_runtime.h>
#include <cuda_bf16.h>
#include <math.h>
#include <stdint.h>

#define NB 256
#define NT 128
#define ND 1024
#define NH 512
#define NG 2048
#define NBT (NB*NT)
#define NE 64
#define NCC 128
#define NCK 8
#define CKS 16
#define NP 50
#define NF2 3123
#define NF3 3173
#define KP2 3136   // NF2 padded to 32
#define KP3 3200   // NF3 padded to 32

// ---------------- scratch (device globals; no runtime allocation) ----------------
__device__ float g_xg_f[(size_t)NBT*NG];
__device__ float g_xg_b[(size_t)NBT*NG];
__device__ float g_Hseq[(size_t)NBT*ND];
__device__ float g_z[(size_t)NBT*ND];
__device__ float g_hbuf[2][2][NB*NH];
__device__ float g_cbuf[2][NB*NH];
__device__ int   g_rev[NBT];
__device__ float g_biasf[NG];
__device__ float g_biasb[NG];
__device__ float g_colsum[ND];
__device__ float g_colsq[ND];
__device__ float g_mu[ND];
__device__ float g_rs[ND];
__device__ float g_alpha[NBT];
__device__ float g_asum[NB];
__device__ float g_U[NB*ND];
__device__ float g_chunk[NE*NCK*ND];
__device__ float g_delta2[NE*NCK*NF2];
__device__ float g_hid2[NE*NCK*ND];
__device__ float g_extra[NE*NCK];
__device__ float g_delta3[(size_t)NE*NCC*NF3];
__device__ float g_h3[(size_t)NE*NCC*ND];
// bf16 split scratch
__device__ __nv_bfloat16 g_Ahi[(size_t)NBT*ND];
__device__ __nv_bfloat16 g_Alo[(size_t)NBT*ND];
__device__ __nv_bfloat16 g_Bhi[3276800];
__device__ __nv_bfloat16 g_Blo[3276800];

// ---------------- mma.sync helpers (arch-portable, sm_80+) ----------------
__device__ __forceinline__ uint32_t smem_u32(const void* p) {
    uint32_t a;
    asm("{ .reg .u64 t; cvta.to.shared.u64 t, %1; cvt.u32.u64 %0, t; }" : "=r"(a) : "l"(p));
    return a;
}
__device__ __forceinline__ void ldsm4(uint32_t* r, uint32_t a) {
    asm volatile("ldmatrix.sync.aligned.m8n8.x4.shared.b16 {%0,%1,%2,%3}, [%4];"
        : "=r"(r[0]), "=r"(r[1]), "=r"(r[2]), "=r"(r[3]) : "r"(a));
}
__device__ __forceinline__ void mma16816(float* c, const uint32_t* a, uint32_t b0, uint32_t b1) {
    asm volatile("mma.sync.aligned.m16n8k16.row.col.f32.bf16.bf16.f32 "
        "{%0,%1,%2,%3}, {%4,%5,%6,%7}, {%8,%9}, {%0,%1,%2,%3};"
        : "+f"(c[0]), "+f"(c[1]), "+f"(c[2]), "+f"(c[3])
        : "r"(a[0]), "r"(a[1]), "r"(a[2]), "r"(a[3]), "r"(b0), "r"(b1));
}
__device__ __forceinline__ void cpa16(uint32_t d, const void* s) {
    asm volatile("cp.async.cg.shared.global [%0], [%1], 16;" :: "r"(d), "l"(s));
}
#define CP_COMMIT() asm volatile("cp.async.commit_group;" ::: "memory")

// ---------------- helpers ----------------
__device__ __forceinline__ float blockReduceSum(float v) {
    __shared__ float sh[33];
    int lane = threadIdx.x & 31, wid = threadIdx.x >> 5;
    #pragma unroll
    for (int o = 16; o; o >>= 1) v += __shfl_down_sync(0xffffffffu, v, o);
    __syncthreads();
    if (lane == 0) sh[wid] = v;
    __syncthreads();
    float r = 0.f;
    int nw = blockDim.x >> 5;
    if (threadIdx.x < nw) r = sh[threadIdx.x];
    if (wid == 0) {
        #pragma unroll
        for (int o = 16; o; o >>= 1) r += __shfl_down_sync(0xffffffffu, r, o);
        if (lane == 0) sh[32] = r;
    }
    __syncthreads();
    return sh[32];
}
__device__ __forceinline__ float leakyf(float v) { return v >= 0.f ? v : 0.01f * v; }
__device__ __forceinline__ float sigm(float v) { return 1.f / (1.f + expf(-v)); }

// ---------------- prep ----------------
__global__ void k_prep(const float* __restrict__ bihf, const float* __restrict__ bhhf,
                       const float* __restrict__ bihb, const float* __restrict__ bhhb,
                       const int* __restrict__ lens) {
    int i = blockIdx.x * blockDim.x + threadIdx.x;
    if (i < NBT) {
        int b = i / NT, t = i % NT, L = lens[b];
        g_rev[i] = b * NT + (t < L ? L - 1 - t : t);
    }
    if (i < NG) { g_biasf[i] = bihf[i] + bhhf[i]; g_biasb[i] = bihb[i] + bhhb[i]; }
    if (i < ND) { g_colsum[i] = 0.f; g_colsq[i] = 0.f; }
    if (i < NB * NH) {
        g_hbuf[0][0][i] = 0.f; g_hbuf[1][0][i] = 0.f;
        g_cbuf[0][i] = 0.f;    g_cbuf[1][i] = 0.f;
    }
}

// ---------------- fp32 -> (hi,lo) bf16 split with K padding ----------------
__global__ void k_split(const float* __restrict__ src, __nv_bfloat16* __restrict__ hi,
                        __nv_bfloat16* __restrict__ lo, int R, int K, int Kp) {
    int i = blockIdx.x * 256 + threadIdx.x;
    if (i >= R * Kp) return;
    int r = i / Kp, k = i - r * Kp;
    float v = (k < K) ? src[(size_t)r * K + k] : 0.f;
    __nv_bfloat16 h = __float2bfloat16_rn(v);
    hi[i] = h;
    lo[i] = __float2bfloat16_rn(v - __bfloat162float(h));
}

// ---------------- mma.sync split-bf16 GEMM: C[M,N] = A[M,Kp]*B[N,Kp]^T + bias ----------------
// CTA tile 128x128, 8 warps (4M x 2N), warp tile 32x64, K chunks of 32,
// cp.async double buffer. A,B pre-split hi/lo bf16, Kp mult of 32, M,N mult of 128.
#define SROWB 80
#define ARRB (128*SROWB)
#define BUFB (4*ARRB)
#define MG_SMEM (2*BUFB)
__global__ __launch_bounds__(256, 1) void k_mgemm(
    const __nv_bfloat16* __restrict__ Ah, const __nv_bfloat16* __restrict__ Al,
    const __nv_bfloat16* __restrict__ Bh, const __nv_bfloat16* __restrict__ Bl,
    const float* __restrict__ bias, float* __restrict__ C,
    int M, int N, int Kp, const int* __restrict__ gather)
{
    extern __shared__ char smem[];
    uint32_t sb = smem_u32(smem);
    const int tid = threadIdx.x, wid = tid >> 5, lane = tid & 31;
    const int m0 = blockIdx.y * 128, n0 = blockIdx.x * 128;
    const int wm = wid & 3, wn = wid >> 2;

    size_t aoff[2], boff[2];
    uint32_t soff[2];
    #pragma unroll
    for (int s = 0; s < 2; s++) {
        int idx = tid + s * 256;
        int r = idx >> 2, j = idx & 3;
        int ra = gather ? gather[m0 + r] : (m0 + r);
        aoff[s] = (size_t)ra * Kp + j * 8;
        boff[s] = (size_t)(n0 + r) * Kp + j * 8;
        soff[s] = r * SROWB + j * 16;
    }

    float acc[2][8][4];
    #pragma unroll
    for (int i = 0; i < 2; i++)
        #pragma unroll
        for (int j = 0; j < 8; j++)
            #pragma unroll
            for (int k = 0; k < 4; k++) acc[i][j][k] = 0.f;

    const int NC = Kp >> 5;
    // issue chunk 0
    {
        uint32_t bb = sb;
        #pragma unroll
        for (int s = 0; s < 2; s++) {
            cpa16(bb + soff[s],            Ah + aoff[s]);
            cpa16(bb + ARRB + soff[s],     Al + aoff[s]);
            cpa16(bb + 2 * ARRB + soff[s], Bh + boff[s]);
            cpa16(bb + 3 * ARRB + soff[s], Bl + boff[s]);
        }
        CP_COMMIT();
    }
    for (int i = 0; i < NC; i++) {
        int buf = i & 1;
        if (i + 1 < NC) {
            int k0 = (i + 1) << 5;
            uint32_t bb = sb + (buf ^ 1) * BUFB;
            #pragma unroll
            for (int s = 0; s < 2; s++) {
                cpa16(bb + soff[s],            Ah + aoff[s] + k0);
                cpa16(bb + ARRB + soff[s],     Al + aoff[s] + k0);
                cpa16(bb + 2 * ARRB + soff[s], Bh + boff[s] + k0);
                cpa16(bb + 3 * ARRB + soff[s], Bl + boff[s] + k0);
            }
            CP_COMMIT();
            asm volatile("cp.async.wait_group 1;" ::: "memory");
        } else {
            asm volatile("cp.async.wait_group 0;" ::: "memory");
        }
        __syncthreads();
        uint32_t bufb = sb + buf * BUFB;
        #pragma unroll
        for (int pass = 0; pass < 3; pass++) {
            uint32_t aB = bufb + (pass == 2 ? ARRB : 0);
            uint32_t bB = bufb + 2 * ARRB + (pass == 1 ? ARRB : 0);
            #pragma unroll
            for (int ks = 0; ks < 2; ks++) {
                uint32_t ar = aB + (wm * 32 + (lane & 15)) * SROWB + ks * 32 + ((lane >> 4) << 4);
                uint32_t a0[4], a1[4];
                ldsm4(a0, ar);
                ldsm4(a1, ar + 16 * SROWB);
                #pragma unroll
                for (int nt = 0; nt < 4; nt++) {
                    uint32_t br = bB + (wn * 64 + nt * 16 + (lane & 15)) * SROWB + ks * 32 + ((lane >> 4) << 4);
                    uint32_t bf[4];
                    ldsm4(bf, br);
                    mma16816(acc[0][nt * 2],     a0, bf[0], bf[2]);
                    mma16816(acc[0][nt * 2 + 1], a0, bf[1], bf[3]);
                    mma16816(acc[1][nt * 2],     a1, bf[0], bf[2]);
                    mma16816(acc[1][nt * 2 + 1], a1, bf[1], bf[3]);
                }
            }
        }
        __syncthreads();
    }
    // epilogue
    #pragma unroll
    for (int mt = 0; mt < 2; mt++) {
        int m = m0 + wm * 32 + mt * 16 + (lane >> 2);
        #pragma unroll
        for (int nt = 0; nt < 8; nt++) {
            int n = n0 + wn * 64 + nt * 8 + (lane & 3) * 2;
            float b0 = bias ? bias[n] : 0.f, b1 = bias ? bias[n + 1] : 0.f;
            float2 v0 = make_float2(acc[mt][nt][0] + b0, acc[mt][nt][1] + b1);
            float2 v1 = make_float2(acc[mt][nt][2] + b0, acc[mt][nt][3] + b1);
            *(float2*)&C[(size_t)m * N + n] = v0;
            *(float2*)&C[(size_t)(m + 8) * N + n] = v1;
        }
    }
}

// ---------------- per-step LSTM (unchanged from R1) ----------------
__global__ __launch_bounds__(256) void k_lstm(
    int t, const float* __restrict__ Whhf, const float* __restrict__ Whhb,
    const int* __restrict__ lens)
{
    const int dir = blockIdx.z;
    const float* __restrict__ Whh = dir ? Whhb : Whhf;
    const float* __restrict__ xg  = dir ? g_xg_b : g_xg_f;
    const float* __restrict__ hr  = g_hbuf[dir][t & 1];
    float* __restrict__ hw        = g_hbuf[dir][(t + 1) & 1];
    float* __restrict__ cc        = g_cbuf[dir];
    __shared__ float Hs[16][66];
    __shared__ float Ws[16][66];
    const int tid = threadIdx.x;
    const int tx = tid & 15, ty = tid >> 4;
    const int b0 = blockIdx.y * 64, u0 = blockIdx.x * 16;
    const int lk = tid & 15, lr = tid >> 4;
    float acc[4][4];
    #pragma unroll
    for (int i = 0; i < 4; i++)
        #pragma unroll
        for (int j = 0; j < 4; j++) acc[i][j] = 0.f;

    for (int k0 = 0; k0 < NH; k0 += 16) {
        #pragma unroll
        for (int i = 0; i < 4; i++) {
            int rr = lr + i * 16;
            Hs[lk][rr] = hr[(size_t)(b0 + rr) * NH + k0 + lk];
            int g = rr >> 4, uu = rr & 15;
            Ws[lk][rr] = Whh[(size_t)(g * NH + u0 + uu) * NH + k0 + lk];
        }
        __syncthreads();
        #pragma unroll
        for (int kk = 0; kk < 16; kk++) {
            float hv[4];
            #pragma unroll
            for (int bi = 0; bi < 4; bi++) hv[bi] = Hs[kk][ty * 4 + bi];
            #pragma unroll
            for (int g = 0; g < 4; g++) {
                float w = Ws[kk][g * 16 + tx];
                #pragma unroll
                for (int bi = 0; bi < 4; bi++) acc[bi][g] = fmaf(hv[bi], w, acc[bi][g]);
            }
        }
        __syncthreads();
    }
    #pragma unroll
    for (int bi = 0; bi < 4; bi++) {
        int b = b0 + ty * 4 + bi;
        int u = u0 + tx;
        int L = lens[b];
        bool msk = t < L;
        size_t xrow = ((size_t)b * NT + t) * NG;
        float pi = xg[xrow + u]          + acc[bi][0];
        float pf = xg[xrow + NH + u]     + acc[bi][1];
        float pg = xg[xrow + 2 * NH + u] + acc[bi][2];
        float po = xg[xrow + 3 * NH + u] + acc[bi][3];
        float ig = sigm(pi), fg = sigm(pf), gv = tanhf(pg), og = sigm(po);
        size_t hidx = (size_t)b * NH + u;
        float cold = cc[hidx];
        float cnew = fg * cold + ig * gv;
        float hnew = og * tanhf(cnew);
        cc[hidx] = msk ? cnew : cold;
        hw[hidx] = msk ? hnew : hr[hidx];
        int tout = dir ? (msk ? (L - 1 - t) : t) : t;
        g_Hseq[((size_t)b * NT + tout) * ND + dir * NH + u] = msk ? hnew : 0.f;
    }
}

// ---------------- BN / attention / phases (unchanged) ----------------
__global__ void k_colstats() {
    int col = blockIdx.x * 32 + threadIdx.x;
    int r0 = blockIdx.y * (NBT / 32);
    float s = 0.f, q = 0.f;
    for (int r = r0 + threadIdx.y; r < r0 + NBT / 32; r += 8) {
        float v = g_z[(size_t)r * ND + col];
        s += v; q += v * v;
    }
    __shared__ float ss[8][33], qq[8][33];
    ss[threadIdx.y][threadIdx.x] = s;
    qq[threadIdx.y][threadIdx.x] = q;
    __syncthreads();
    if (threadIdx.y == 0) {
        #pragma unroll
        for (int k = 1; k < 8; k++) { s += ss[k][threadIdx.x]; q += qq[k][threadIdx.x]; }
        atomicAdd(&g_colsum[col], s);
        atomicAdd(&g_colsq[col], q);
    }
}

__global__ void k_finalize() {
    int d = blockIdx.x * 256 + threadIdx.x;
    if (d < ND) {
        float mean = g_colsum[d] / (float)NBT;
        float var  = g_colsq[d] / (float)NBT - mean * mean;
        g_mu[d] = mean;
        g_rs[d] = rsqrtf(var + 1e-5f);
    }
}

__global__ void k_alpha(const float* __restrict__ s2w) {
    size_t row = blockIdx.x;
    float p = 0.f;
    for (int d = threadIdx.x; d < ND; d += 256) {
        float v = (g_z[row * ND + d] - g_mu[d]) * g_rs[d];
        p += leakyf(v) * s2w[d];
    }
    p = blockReduceSum(p);
    if (threadIdx.x == 0) g_alpha[row] = p;
}

__global__ void k_asum(const int* __restrict__ lens) {
    int b = blockIdx.x;
    int L = lens[b];
    float s = 0.f;
    for (int t = threadIdx.x; t < L; t += 128) s += g_alpha[b * NT + t];
    s = blockReduceSum(s);
    if (threadIdx.x == 0) g_asum[b] = s + 1e-9f;
}

__global__ void k_U(const int* __restrict__ lens) {
    int b = blockIdx.y;
    int d = blockIdx.x * 256 + threadIdx.x;
    int L = lens[b];
    float inv = 1.f / g_asum[b];
    float s = 0.f;
    for (int t = 0; t < L; t++)
        s += g_alpha[b * NT + t] * g_Hseq[((size_t)b * NT + t) * ND + d];
    g_U[(size_t)b * ND + d] = s * inv;
}

__global__ void k_L(const int* __restrict__ label3, float* __restrict__ outL) {
    for (int i = threadIdx.x; i < NE * NCC; i += 256) outL[i] = 0.f;
    __syncthreads();
    if (threadIdx.x < NE) {
        for (int j = 0; j < 3; j++) {
            int v = label3[threadIdx.x * 3 + j];
            if (v >= 0) outL[threadIdx.x * NCC + v] = 1.f;
        }
    }
}

__global__ void k_chunk() {
    int e = blockIdx.y, n = blockIdx.x;
    const float* __restrict__ emo  = g_U + (size_t)e * ND;
    const float* __restrict__ cau0 = g_U + (size_t)(NE + n * CKS) * ND;
    __shared__ float logits[CKS];
    __shared__ float sc[CKS];
    int w = threadIdx.x >> 5, lane = threadIdx.x & 31;
    float a0 = 0.f, a1 = 0.f;
    for (int d = lane; d < ND; d += 32) {
        float ed = emo[d];
        a0 += ed * cau0[(size_t)(2 * w) * ND + d];
        a1 += ed * cau0[(size_t)(2 * w + 1) * ND + d];
    }
    #pragma unroll
    for (int o = 16; o; o >>= 1) {
        a0 += __shfl_down_sync(0xffffffffu, a0, o);
        a1 += __shfl_down_sync(0xffffffffu, a1, o);
    }
    if (lane == 0) { logits[2 * w] = a0; logits[2 * w + 1] = a1; }
    __syncthreads();
    if (threadIdx.x == 0) {
        float mx = logits[0];
        for (int c = 1; c < CKS; c++) mx = fmaxf(mx, logits[c]);
        float s = 0.f;
        for (int c = 0; c < CKS; c++) { sc[c] = expf(logits[c] - mx); s += sc[c]; }
        float si = 1.f / s;
        for (int c = 0; c < CKS; c++) sc[c] *= si;
    }
    __syncthreads();
    for (int d = threadIdx.x; d < ND; d += 256) {
        float v = 0.f;
        #pragma unroll
        for (int c = 0; c < CKS; c++) v += sc[c] * cau0[(size_t)c * ND + d];
        g_chunk[(size_t)(e * NCK + n) * ND + d] = v;
    }
}

__global__ void k_delta2(const float* __restrict__ pos) {
    int e = blockIdx.y, n = blockIdx.x;
    int row = e * NCK + n;
    const float* __restrict__ emo = g_U + (size_t)e * ND;
    const float* __restrict__ ch  = g_chunk + (size_t)row * ND;
    float p = 0.f;
    for (int d = threadIdx.x; d < ND; d += 256) {
        float dd = emo[d] - ch[d];
        p += dd * dd;
    }
    p = blockReduceSum(p);
    float dist = sqrtf(p);
    size_t base = (size_t)row * NF2;
    for (int f = threadIdx.x; f < NF2; f += 256) {
        float v;
        if (f < ND) v = emo[f];
        else if (f < 2 * ND) v = ch[f - ND];
        else if (f == 2 * ND) v = dist;
        else if (f < 3 * ND + 1) v = emo[f - 2 * ND - 1] * ch[f - 2 * ND - 1];
        else v = pos[(size_t)row * NP + (f - (3 * ND + 1))];
        g_delta2[base + f] = v;
    }
}

__global__ void k_bn2() {
    int e = blockIdx.y;
    int d = blockIdx.x * 256 + threadIdx.x;
    float vals[NCK];
    float s = 0.f, q = 0.f;
    #pragma unroll
    for (int n = 0; n < NCK; n++) {
        float v = g_hid2[(size_t)(e * NCK + n) * ND + d];
        vals[n] = v; s += v; q += v * v;
    }
    float mean = s / (float)NCK;
    float var = q / (float)NCK - mean * mean;
    float r = rsqrtf(var + 1e-5f);
    #pragma unroll
    for (int n = 0; n < NCK; n++)
        g_hid2[(size_t)(e * NCK + n) * ND + d] = leakyf((vals[n] - mean) * r);
}

__global__ void k_out2(const float* __restrict__ Wow, const float* __restrict__ Wob,
                       float* __restrict__ out) {
    int row = blockIdx.x;
    float p0 = 0.f, p1 = 0.f;
    for (int d = threadIdx.x; d < ND; d += 256) {
        float h = g_hid2[(size_t)row * ND + d];
        p0 += h * Wow[d];
        p1 += h * Wow[ND + d];
    }
    p0 = blockReduceSum(p0);
    p1 = blockReduceSum(p1);
    if (threadIdx.x == 0) {
        float l0 = p0 + Wob[0], l1 = p1 + Wob[1];
        float mx = fmaxf(l0, l1);
        float lse = mx + logf(expf(l0 - mx) + expf(l1 - mx));
        out[row * 2 + 0] = l0 - lse;
        out[row * 2 + 1] = l1 - lse;
        g_extra[row] = (l1 > l0) ? 1.f : 0.f;
    }
}

__global__ void k_delta3(const float* __restrict__ dis) {
    int e = blockIdx.y, j = blockIdx.x;
    const float* __restrict__ emo = g_U + (size_t)e * ND;
    const float* __restrict__ y   = g_U + (size_t)(NE + j) * ND;
    float p = 0.f;
    for (int d = threadIdx.x; d < ND; d += 256) {
        float dd = emo[d] - y[d];
        p += dd * dd;
    }
    p = blockReduceSum(p);
    float dist = sqrtf(p);
    float ext = g_extra[e * NCK + (j >> 4)];
    size_t base = (size_t)(e * NCC + j) * NF3;
    for (int f = threadIdx.x; f < NF3; f += 256) {
        float v;
        if (f < ND) v = emo[f];
        else if (f < 2 * ND) v = y[f - ND];
        else if (f == 2 * ND) v = dist;
        else if (f < 3 * ND + 1) v = emo[f - 2 * ND - 1] * y[f - 2 * ND - 1];
        else if (f < 3 * ND + 1 + NP) v = dis[(size_t)(e * NCC + j) * NP + (f - (3 * ND + 1))];
        else v = ext;
        g_delta3[base + f] = v;
    }
}

__global__ void k_bn3() {
    int e = blockIdx.y;
    int d = blockIdx.x * 256 + threadIdx.x;
    float s = 0.f, q = 0.f;
    for (int j = 0; j < NCC; j++) {
        float v = g_h3[(size_t)(e * NCC + j) * ND + d];
        s += v; q += v * v;
    }
    float mean = s / (float)NCC;
    float var = q / (float)NCC - mean * mean;
    float r = rsqrtf(var + 1e-5f);
    for (int j = 0; j < NCC; j++) {
        size_t idx = (size_t)(e * NCC + j) * ND + d;
        g_h3[idx] = leakyf((g_h3[idx] - mean) * r);
    }
}

__global__ void k_cls(const float* __restrict__ clsw, const float* __restrict__ clsb,
                      float* __restrict__ outp) {
    int e = blockIdx.y, j = blockIdx.x;
    int row = e * NCC + j;
    float p0 = 0.f, p1 = 0.f;
    for (int d = threadIdx.x; d < ND; d += 256) {
        float h = g_h3[(size_t)row * ND + d];
        p0 += h * clsw[d];
        p1 += h * clsw[ND + d];
    }
    p0 = blockReduceSum(p0);
    p1 = blockReduceSum(p1);
    if (threadIdx.x == 0) {
        float l0 = p0 + clsb[0], l1 = p1 + clsb[1];
        float mx = fmaxf(l0, l1);
        float lse = mx + logf(expf(l0 - mx) + expf(l1 - mx));
        outp[row * 2 + 0] = l0 - lse;
        outp[row * 2 + 1] = l1 - lse;
    }
}

// ---------------- host launcher ----------------
static inline int cdiv(int a, int b) { return (a + b - 1) / b; }

extern "C" void kernel_launch(void* const* d_in, const int* in_sizes, int n_in,
                              void* d_out, int out_size) {
    const float *word, *pos, *dis, *Wihf, *Whhf, *bihf, *bhhf, *Wihb, *Whhb, *bihb, *bhhb;
    const float *s1w, *s1b, *s2w, *W2w, *W2b, *Wow, *Wob, *W3w, *W3b, *clsw, *clsb;
    const int *lens, *label3;
    if (in_sizes[3] == 256) {
        word = (const float*)d_in[0];  pos = (const float*)d_in[1];  dis = (const float*)d_in[2];
        lens = (const int*)d_in[3];    label3 = (const int*)d_in[4];
        Wihf = (const float*)d_in[7];  Whhf = (const float*)d_in[8];
        bihf = (const float*)d_in[9];  bhhf = (const float*)d_in[10];
        Wihb = (const float*)d_in[11]; Whhb = (const float*)d_in[12];
        bihb = (const float*)d_in[13]; bhhb = (const float*)d_in[14];
        s1w = (const float*)d_in[15];  s1b = (const float*)d_in[16]; s2w = (const float*)d_in[17];
        W2w = (const float*)d_in[18];  W2b = (const float*)d_in[19];
        Wow = (const float*)d_in[20];  Wob = (const float*)d_in[21];
        W3w = (const float*)d_in[22];  W3b = (const float*)d_in[23];
        clsw = (const float*)d_in[24]; clsb = (const float*)d_in[25];
    } else {
        word = (const float*)d_in[0];  pos = (const float*)d_in[1];  dis = (const float*)d_in[2];
        Wihf = (const float*)d_in[3];  Whhf = (const float*)d_in[4];
        bihf = (const float*)d_in[5];  bhhf = (const float*)d_in[6];
        Wihb = (const float*)d_in[7];  Whhb = (const float*)d_in[8];
        bihb = (const float*)d_in[9];  bhhb = (const float*)d_in[10];
        s1w = (const float*)d_in[11];  s1b = (const float*)d_in[12]; s2w = (const float*)d_in[13];
        W2w = (const float*)d_in[14];  W2b = (const float*)d_in[15];
        Wow = (const float*)d_in[16];  Wob = (const float*)d_in[17];
        W3w = (const float*)d_in[18];  W3b = (const float*)d_in[19];
        clsw = (const float*)d_in[20]; clsb = (const float*)d_in[21];
        lens = (const int*)d_in[22];   label3 = (const int*)d_in[23];
    }
    float* out = (float*)d_out;
    float* out_p3 = out + NE * NCK * 2;
    float* out_L  = out_p3 + NE * NCC * 2;

    void *p_xgf, *p_xgb, *p_Hseq, *p_z, *p_rev, *p_bf, *p_bb, *p_d2, *p_h2, *p_d3, *p_h3;
    void *p_Ahi, *p_Alo, *p_Bhi, *p_Blo;
    cudaGetSymbolAddress(&p_xgf, g_xg_f);
    cudaGetSymbolAddress(&p_xgb, g_xg_b);
    cudaGetSymbolAddress(&p_Hseq, g_Hseq);
    cudaGetSymbolAddress(&p_z, g_z);
    cudaGetSymbolAddress(&p_rev, g_rev);
    cudaGetSymbolAddress(&p_bf, g_biasf);
    cudaGetSymbolAddress(&p_bb, g_biasb);
    cudaGetSymbolAddress(&p_d2, g_delta2);
    cudaGetSymbolAddress(&p_h2, g_hid2);
    cudaGetSymbolAddress(&p_d3, g_delta3);
    cudaGetSymbolAddress(&p_h3, g_h3);
    cudaGetSymbolAddress(&p_Ahi, g_Ahi);
    cudaGetSymbolAddress(&p_Alo, g_Alo);
    cudaGetSymbolAddress(&p_Bhi, g_Bhi);
    cudaGetSymbolAddress(&p_Blo, g_Blo);
    __nv_bfloat16* Ahi = (__nv_bfloat16*)p_Ahi;
    __nv_bfloat16* Alo = (__nv_bfloat16*)p_Alo;
    __nv_bfloat16* Bhi = (__nv_bfloat16*)p_Bhi;
    __nv_bfloat16* Blo = (__nv_bfloat16*)p_Blo;

    cudaFuncSetAttribute(k_mgemm, cudaFuncAttributeMaxDynamicSharedMemorySize, MG_SMEM);

    // 1. prep
    k_prep<<<512, 256>>>(bihf, bhhf, bihb, bhhb, lens);

    // 2. split word + Wih_f, GEMM xg_f; then Wih_b, GEMM xg_b (gathered rows)
    k_split<<<cdiv(NBT * ND, 256), 256>>>(word, Ahi, Alo, NBT, ND, ND);
    k_split<<<cdiv(NG * ND, 256), 256>>>(Wihf, Bhi, Blo, NG, ND, ND);
    k_mgemm<<<dim3(NG / 128, NBT / 128), 256, MG_SMEM>>>(Ahi, Alo, Bhi, Blo,
        (const float*)p_bf, (float*)p_xgf, NBT, NG, ND, nullptr);
    k_split<<<cdiv(NG * ND, 256), 256>>>(Wihb, Bhi, Blo, NG, ND, ND);
    k_mgemm<<<dim3(NG / 128, NBT / 128), 256, MG_SMEM>>>(Ahi, Alo, Bhi, Blo,
        (const float*)p_bb, (float*)p_xgb, NBT, NG, ND, (const int*)p_rev);

    // 3. recurrence
    for (int t = 0; t < NT; t++)
        k_lstm<<<dim3(NH / 16, NB / 64, 2), 256>>>(t, Whhf, Whhb, lens);

    // 4. z = Hseq @ s1_w^T + s1_b
    k_split<<<cdiv(NBT * ND, 256), 256>>>((const float*)p_Hseq, Ahi, Alo, NBT, ND, ND);
    k_split<<<cdiv(ND * ND, 256), 256>>>(s1w, Bhi, Blo, ND, ND, ND);
    k_mgemm<<<dim3(ND / 128, NBT / 128), 256, MG_SMEM>>>(Ahi, Alo, Bhi, Blo,
        s1b, (float*)p_z, NBT, ND, ND, nullptr);

    // 5. BN stats, alpha, U
    k_colstats<<<dim3(ND / 32, 32), dim3(32, 8)>>>();
    k_finalize<<<4, 256>>>();
    k_alpha<<<NBT, 256>>>(s2w);
    k_asum<<<NB, 128>>>(lens);
    k_U<<<dim3(ND / 256, NB), 256>>>(lens);

    // 6. L output
    k_L<<<1, 256>>>(label3, out_L);

    // 7. phase 2
    k_chunk<<<dim3(NCK, NE), 256>>>();
    k_delta2<<<dim3(NCK, NE), 256>>>(pos);
    k_split<<<cdiv(NE * NCK * KP2, 256), 256>>>((const float*)p_d2, Ahi, Alo, NE * NCK, NF2, KP2);
    k_split<<<cdiv(ND * KP2, 256), 256>>>(W2w, Bhi, Blo, ND, NF2, KP2);
    k_mgemm<<<dim3(ND / 128, (NE * NCK) / 128), 256, MG_SMEM>>>(Ahi, Alo, Bhi, Blo,
        W2b, (float*)p_h2, NE * NCK, ND, KP2, nullptr);
    k_bn2<<<dim3(ND / 256, NE), 256>>>();
    k_out2<<<NE * NCK, 256>>>(Wow, Wob, out);

    // 8. phase 3
    k_delta3<<<dim3(NCC, NE), 256>>>(dis);
    k_split<<<cdiv(NE * NCC * KP3, 256), 256>>>((const float*)p_d3, Ahi, Alo, NE * NCC, NF3, KP3);
    k_split<<<cdiv(ND * KP3, 256), 256>>>(W3w, Bhi, Blo, ND, NF3, KP3);
    k_mgemm<<<dim3(ND / 128, (NE * NCC) / 128), 256, MG_SMEM>>>(Ahi, Alo, Bhi, Blo,
        W3b, (float*)p_h3, NE * NCC, ND, KP3, nullptr);
    k_bn3<<<dim3(ND / 256, NE), 256>>>();
    k_cls<<<dim3(NCC, NE), 256>>>(clsw, clsb, out_p3);
}

// round 4
// speedup vs baseline: 2.4526x; 1.4431x over previous
#include <cuda_runtime.h>
#include <cuda_bf16.h>
#include <math.h>
#include <stdint.h>

#define NB 256
#define NT 128
#define ND 1024
#define NH 512
#define NG 2048
#define NBT (NB*NT)
#define NE 64
#define NCC 128
#define NCK 8
#define CKS 16
#define NP 50
#define NF2 3123
#define NF3 3173
#define KP2 3136
#define KP3 3200

// ---------------- scratch (device globals) ----------------
__device__ float g_xg_f[(size_t)NBT*NG];
__device__ float g_xg_b[(size_t)NBT*NG];
__device__ float g_Hseq[(size_t)NBT*ND];
__device__ float g_z[(size_t)NBT*ND];
__device__ int   g_rev[NBT];
__device__ float g_biasf[NG];
__device__ float g_biasb[NG];
__device__ float g_colsum[ND];
__device__ float g_colsq[ND];
__device__ float g_mu[ND];
__device__ float g_rs[ND];
__device__ float g_alpha[NBT];
__device__ float g_asum[NB];
__device__ float g_U[NB*ND];
__device__ float g_chunk[NE*NCK*ND];
__device__ float g_delta2[NE*NCK*NF2];
__device__ float g_hid2[NE*NCK*ND];
__device__ float g_extra[NE*NCK];
__device__ float g_delta3[(size_t)NE*NCC*NF3];
__device__ float g_h3[(size_t)NE*NCC*ND];
// bf16 split scratch
__device__ __nv_bfloat16 g_Ahi[(size_t)NBT*ND];
__device__ __nv_bfloat16 g_Alo[(size_t)NBT*ND];
__device__ __nv_bfloat16 g_Bhi[3276800];
__device__ __nv_bfloat16 g_Blo[3276800];
// LSTM: reordered+split recurrent weights, ping-pong h state, barrier
__device__ __nv_bfloat16 g_Wrh[2*2048*512];
__device__ __nv_bfloat16 g_Wrl[2*2048*512];
__device__ __nv_bfloat16 g_hh[2][2*256*512];
__device__ __nv_bfloat16 g_hl[2][2*256*512];
__device__ unsigned g_barcnt;
__device__ volatile unsigned g_bargen;

// ---------------- mma.sync helpers ----------------
__device__ __forceinline__ uint32_t smem_u32(const void* p) {
    uint32_t a;
    asm("{ .reg .u64 t; cvta.to.shared.u64 t, %1; cvt.u32.u64 %0, t; }" : "=r"(a) : "l"(p));
    return a;
}
__device__ __forceinline__ void ldsm4(uint32_t* r, uint32_t a) {
    asm volatile("ldmatrix.sync.aligned.m8n8.x4.shared.b16 {%0,%1,%2,%3}, [%4];"
        : "=r"(r[0]), "=r"(r[1]), "=r"(r[2]), "=r"(r[3]) : "r"(a));
}
__device__ __forceinline__ void mma16816(float* c, const uint32_t* a, uint32_t b0, uint32_t b1) {
    asm volatile("mma.sync.aligned.m16n8k16.row.col.f32.bf16.bf16.f32 "
        "{%0,%1,%2,%3}, {%4,%5,%6,%7}, {%8,%9}, {%0,%1,%2,%3};"
        : "+f"(c[0]), "+f"(c[1]), "+f"(c[2]), "+f"(c[3])
        : "r"(a[0]), "r"(a[1]), "r"(a[2]), "r"(a[3]), "r"(b0), "r"(b1));
}
__device__ __forceinline__ void cpa16(uint32_t d, const void* s) {
    asm volatile("cp.async.cg.shared.global [%0], [%1], 16;" :: "r"(d), "l"(s));
}
#define CP_COMMIT() asm volatile("cp.async.commit_group;" ::: "memory")

// ---------------- helpers ----------------
__device__ __forceinline__ float blockReduceSum(float v) {
    __shared__ float sh[33];
    int lane = threadIdx.x & 31, wid = threadIdx.x >> 5;
    #pragma unroll
    for (int o = 16; o; o >>= 1) v += __shfl_down_sync(0xffffffffu, v, o);
    __syncthreads();
    if (lane == 0) sh[wid] = v;
    __syncthreads();
    float r = 0.f;
    int nw = blockDim.x >> 5;
    if (threadIdx.x < nw) r = sh[threadIdx.x];
    if (wid == 0) {
        #pragma unroll
        for (int o = 16; o; o >>= 1) r += __shfl_down_sync(0xffffffffu, r, o);
        if (lane == 0) sh[32] = r;
    }
    __syncthreads();
    return sh[32];
}
__device__ __forceinline__ float leakyf(float v) { return v >= 0.f ? v : 0.01f * v; }
__device__ __forceinline__ float sigm(float v) { return 1.f / (1.f + expf(-v)); }

// ---------------- prep ----------------
__global__ void k_prep(const float* __restrict__ bihf, const float* __restrict__ bhhf,
                       const float* __restrict__ bihb, const float* __restrict__ bhhb,
                       const int* __restrict__ lens) {
    int i = blockIdx.x * blockDim.x + threadIdx.x;
    if (i < NBT) {
        int b = i / NT, t = i % NT, L = lens[b];
        g_rev[i] = b * NT + (t < L ? L - 1 - t : t);
    }
    if (i < NG) { g_biasf[i] = bihf[i] + bhhf[i]; g_biasb[i] = bihb[i] + bhhb[i]; }
    if (i < ND) { g_colsum[i] = 0.f; g_colsq[i] = 0.f; }
    if (i < 2 * 256 * 512) {
        g_hh[0][i] = __float2bfloat16(0.f);
        g_hl[0][i] = __float2bfloat16(0.f);
    }
    if (i == 0) { g_barcnt = 0; g_bargen = 0; }
}

// ---------------- Whh reorder + hi/lo split (once) ----------------
__global__ void k_wsplit(const float* __restrict__ Wf, const float* __restrict__ Wb) {
    size_t i = (size_t)blockIdx.x * 256 + threadIdx.x;
    if (i >= (size_t)2 * 2048 * 512) return;
    int dir = (int)(i / (2048 * 512));
    size_t rem = i % (2048 * 512);
    int gr = (int)(rem / 512), k = (int)(rem % 512);
    int ty = gr >> 9, u = gr & 511;
    int r = (u >> 5) * 128 + ty * 32 + (u & 31);
    float v = (dir ? Wb : Wf)[(size_t)gr * 512 + k];
    __nv_bfloat16 h = __float2bfloat16_rn(v);
    g_Wrh[((size_t)dir * 2048 + r) * 512 + k] = h;
    g_Wrl[((size_t)dir * 2048 + r) * 512 + k] = __float2bfloat16_rn(v - __bfloat162float(h));
}

// ---------------- fp32 -> (hi,lo) bf16 split with K padding ----------------
__global__ void k_split(const float* __restrict__ src, __nv_bfloat16* __restrict__ hi,
                        __nv_bfloat16* __restrict__ lo, int R, int K, int Kp) {
    int i = blockIdx.x * 256 + threadIdx.x;
    if (i >= R * Kp) return;
    int r = i / Kp, k = i - r * Kp;
    float v = (k < K) ? src[(size_t)r * K + k] : 0.f;
    __nv_bfloat16 h = __float2bfloat16_rn(v);
    hi[i] = h;
    lo[i] = __float2bfloat16_rn(v - __bfloat162float(h));
}

// ---------------- mma.sync split-bf16 GEMM (unchanged from R3) ----------------
#define SROWB 80
#define ARRB (128*SROWB)
#define BUFB (4*ARRB)
#define MG_SMEM (2*BUFB)
__global__ __launch_bounds__(256, 1) void k_mgemm(
    const __nv_bfloat16* __restrict__ Ah, const __nv_bfloat16* __restrict__ Al,
    const __nv_bfloat16* __restrict__ Bh, const __nv_bfloat16* __restrict__ Bl,
    const float* __restrict__ bias, float* __restrict__ C,
    int M, int N, int Kp, const int* __restrict__ gather)
{
    extern __shared__ char smem[];
    uint32_t sb = smem_u32(smem);
    const int tid = threadIdx.x, wid = tid >> 5, lane = tid & 31;
    const int m0 = blockIdx.y * 128, n0 = blockIdx.x * 128;
    const int wm = wid & 3, wn = wid >> 2;

    size_t aoff[2], boff[2];
    uint32_t soff[2];
    #pragma unroll
    for (int s = 0; s < 2; s++) {
        int idx = tid + s * 256;
        int r = idx >> 2, j = idx & 3;
        int ra = gather ? gather[m0 + r] : (m0 + r);
        aoff[s] = (size_t)ra * Kp + j * 8;
        boff[s] = (size_t)(n0 + r) * Kp + j * 8;
        soff[s] = r * SROWB + j * 16;
    }

    float acc[2][8][4];
    #pragma unroll
    for (int i = 0; i < 2; i++)
        #pragma unroll
        for (int j = 0; j < 8; j++)
            #pragma unroll
            for (int k = 0; k < 4; k++) acc[i][j][k] = 0.f;

    const int NC = Kp >> 5;
    {
        uint32_t bb = sb;
        #pragma unroll
        for (int s = 0; s < 2; s++) {
            cpa16(bb + soff[s],            Ah + aoff[s]);
            cpa16(bb + ARRB + soff[s],     Al + aoff[s]);
            cpa16(bb + 2 * ARRB + soff[s], Bh + boff[s]);
            cpa16(bb + 3 * ARRB + soff[s], Bl + boff[s]);
        }
        CP_COMMIT();
    }
    for (int i = 0; i < NC; i++) {
        int buf = i & 1;
        if (i + 1 < NC) {
            int k0 = (i + 1) << 5;
            uint32_t bb = sb + (buf ^ 1) * BUFB;
            #pragma unroll
            for (int s = 0; s < 2; s++) {
                cpa16(bb + soff[s],            Ah + aoff[s] + k0);
                cpa16(bb + ARRB + soff[s],     Al + aoff[s] + k0);
                cpa16(bb + 2 * ARRB + soff[s], Bh + boff[s] + k0);
                cpa16(bb + 3 * ARRB + soff[s], Bl + boff[s] + k0);
            }
            CP_COMMIT();
            asm volatile("cp.async.wait_group 1;" ::: "memory");
        } else {
            asm volatile("cp.async.wait_group 0;" ::: "memory");
        }
        __syncthreads();
        uint32_t bufb = sb + buf * BUFB;
        #pragma unroll
        for (int pass = 0; pass < 3; pass++) {
            uint32_t aB = bufb + (pass == 2 ? ARRB : 0);
            uint32_t bB = bufb + 2 * ARRB + (pass == 1 ? ARRB : 0);
            #pragma unroll
            for (int ks = 0; ks < 2; ks++) {
                uint32_t ar = aB + (wm * 32 + (lane & 15)) * SROWB + ks * 32 + ((lane >> 4) << 4);
                uint32_t a0[4], a1[4];
                ldsm4(a0, ar);
                ldsm4(a1, ar + 16 * SROWB);
                #pragma unroll
                for (int nt = 0; nt < 4; nt++) {
                    uint32_t br = bB + (wn * 64 + nt * 16 + (lane & 15)) * SROWB + ks * 32 + ((lane >> 4) << 4);
                    uint32_t bf[4];
                    ldsm4(bf, br);
                    mma16816(acc[0][nt * 2],     a0, bf[0], bf[2]);
                    mma16816(acc[0][nt * 2 + 1], a0, bf[1], bf[3]);
                    mma16816(acc[1][nt * 2],     a1, bf[0], bf[2]);
                    mma16816(acc[1][nt * 2 + 1], a1, bf[1], bf[3]);
                }
            }
        }
        __syncthreads();
    }
    #pragma unroll
    for (int mt = 0; mt < 2; mt++) {
        int m = m0 + wm * 32 + mt * 16 + (lane >> 2);
        #pragma unroll
        for (int nt = 0; nt < 8; nt++) {
            int n = n0 + wn * 64 + nt * 8 + (lane & 3) * 2;
            float b0 = bias ? bias[n] : 0.f, b1 = bias ? bias[n + 1] : 0.f;
            float2 v0 = make_float2(acc[mt][nt][0] + b0, acc[mt][nt][1] + b1);
            float2 v1 = make_float2(acc[mt][nt][2] + b0, acc[mt][nt][3] + b1);
            *(float2*)&C[(size_t)m * N + n] = v0;
            *(float2*)&C[(size_t)(m + 8) * N + n] = v1;
        }
    }
}

// ---------------- persistent bidirectional LSTM ----------------
// 128 CTAs: (dir 2) x (mslice 4: 64 batches) x (uslice 16: 32 units -> 128 gate rows).
// Per step per CTA: mma.sync 64x128x512 split-bf16 (3 passes), fused gates,
// register-resident c/h, ping-pong h in gmem, hand-rolled grid barrier.
#define SR2 144
#define LA_SZ (64*SR2)
#define LB_SZ (128*SR2)
#define LBUF (2*LA_SZ + 2*LB_SZ)
#define LS_SMEM (2*LBUF)
#define PS 132
#define LS_CTAS 128

__device__ __forceinline__ void grid_barrier() {
    __syncthreads();
    if (threadIdx.x == 0) {
        unsigned gen = g_bargen;
        __threadfence();
        unsigned t = atomicAdd(&g_barcnt, 1u);
        if (t == LS_CTAS - 1) {
            atomicExch(&g_barcnt, 0u);
            __threadfence();
            g_bargen = gen + 1;
        } else {
            while (g_bargen == gen) { __nanosleep(40); }
            __threadfence();
        }
    }
    __syncthreads();
}

__global__ __launch_bounds__(256, 1) void k_lstm_all(const int* __restrict__ lens)
{
    extern __shared__ char sm[];
    uint32_t sb = smem_u32(sm);
    const int tid = threadIdx.x, wid = tid >> 5, lane = tid & 31;
    const int cta = blockIdx.x;
    const int dir = cta >> 6;
    const int ms = (cta & 63) >> 4;
    const int us = cta & 15;
    const int b0 = ms * 64;
    const int wm = wid & 1, wn = wid >> 1;
    const float* __restrict__ xg = dir ? g_xg_b : g_xg_f;
    const __nv_bfloat16* __restrict__ Wh = g_Wrh + ((size_t)dir * 2048 + us * 128) * 512;
    const __nv_bfloat16* __restrict__ Wl = g_Wrl + ((size_t)dir * 2048 + us * 128) * 512;

    float c_st[8], h_st[8];
    int Lb[8];
    #pragma unroll
    for (int r = 0; r < 8; r++) {
        c_st[r] = 0.f; h_st[r] = 0.f;
        Lb[r] = lens[b0 + r * 8 + wid];
    }

    // cp.async source/dest mapping (per k-chunk of 64)
    // A(h): 64 rows x 128B per split; B(W): 128 rows x 128B per split
    uint32_t aso[2], bso[4];
    int arow[2], brow[4];
    #pragma unroll
    for (int s = 0; s < 2; s++) {
        int idx = tid + s * 256;
        arow[s] = idx >> 3;
        aso[s] = (idx >> 3) * SR2 + (idx & 7) * 16;
    }
    #pragma unroll
    for (int s = 0; s < 4; s++) {
        int idx = tid + s * 256;
        brow[s] = idx >> 3;
        bso[s] = (idx >> 3) * SR2 + (idx & 7) * 16;
    }
    int aj[2], bj[4];
    #pragma unroll
    for (int s = 0; s < 2; s++) aj[s] = ((tid + s * 256) & 7) * 8;
    #pragma unroll
    for (int s = 0; s < 4; s++) bj[s] = ((tid + s * 256) & 7) * 8;

    for (int t = 0; t < NT; t++) {
        const int rbuf = t & 1, wbuf = rbuf ^ 1;
        const __nv_bfloat16* __restrict__ hhp = g_hh[rbuf];
        const __nv_bfloat16* __restrict__ hlp = g_hl[rbuf];

        float acc[2][4][4];
        #pragma unroll
        for (int i = 0; i < 2; i++)
            #pragma unroll
            for (int j = 0; j < 4; j++)
                #pragma unroll
                for (int k = 0; k < 4; k++) acc[i][j][k] = 0.f;

        // prologue: chunk 0
        {
            uint32_t bb = sb;
            #pragma unroll
            for (int s = 0; s < 2; s++) {
                size_t ho = ((size_t)(dir * 256 + b0 + arow[s])) * 512 + aj[s];
                cpa16(bb + aso[s],         hhp + ho);
                cpa16(bb + LA_SZ + aso[s], hlp + ho);
            }
            #pragma unroll
            for (int s = 0; s < 4; s++) {
                size_t wo = (size_t)brow[s] * 512 + bj[s];
                cpa16(bb + 2 * LA_SZ + bso[s],         Wh + wo);
                cpa16(bb + 2 * LA_SZ + LB_SZ + bso[s], Wl + wo);
            }
            CP_COMMIT();
        }
        for (int ch = 0; ch < 8; ch++) {
            int buf = ch & 1;
            if (ch + 1 < 8) {
                int k0 = (ch + 1) << 6;
                uint32_t bb = sb + (buf ^ 1) * LBUF;
                #pragma unroll
                for (int s = 0; s < 2; s++) {
                    size_t ho = ((size_t)(dir * 256 + b0 + arow[s])) * 512 + k0 + aj[s];
                    cpa16(bb + aso[s],         hhp + ho);
                    cpa16(bb + LA_SZ + aso[s], hlp + ho);
                }
                #pragma unroll
                for (int s = 0; s < 4; s++) {
                    size_t wo = (size_t)brow[s] * 512 + k0 + bj[s];
                    cpa16(bb + 2 * LA_SZ + bso[s],         Wh + wo);
                    cpa16(bb + 2 * LA_SZ + LB_SZ + bso[s], Wl + wo);
                }
                CP_COMMIT();
                asm volatile("cp.async.wait_group 1;" ::: "memory");
            } else {
                asm volatile("cp.async.wait_group 0;" ::: "memory");
            }
            __syncthreads();
            uint32_t bufb = sb + buf * LBUF;
            #pragma unroll
            for (int pass = 0; pass < 3; pass++) {
                uint32_t aB = bufb + (pass == 2 ? LA_SZ : 0);
                uint32_t bB = bufb + 2 * LA_SZ + (pass == 1 ? LB_SZ : 0);
                #pragma unroll
                for (int k16 = 0; k16 < 4; k16++) {
                    uint32_t ar = aB + (wm * 32 + (lane & 15)) * SR2 + k16 * 32 + ((lane >> 4) << 4);
                    uint32_t a0[4], a1[4];
                    ldsm4(a0, ar);
                    ldsm4(a1, ar + 16 * SR2);
                    #pragma unroll
                    for (int nt = 0; nt < 2; nt++) {
                        uint32_t br = bB + (wn * 32 + nt * 16 + (lane & 15)) * SR2 + k16 * 32 + ((lane >> 4) << 4);
                        uint32_t bf[4];
                        ldsm4(bf, br);
                        mma16816(acc[0][nt * 2],     a0, bf[0], bf[2]);
                        mma16816(acc[0][nt * 2 + 1], a0, bf[1], bf[3]);
                        mma16816(acc[1][nt * 2],     a1, bf[0], bf[2]);
                        mma16816(acc[1][nt * 2 + 1], a1, bf[1], bf[3]);
                    }
                }
            }
            __syncthreads();
        }
        // stage pre-activations to smem (reuse buffer 0 region)
        float* pre = (float*)sm;
        #pragma unroll
        for (int mt = 0; mt < 2; mt++) {
            int row = wm * 32 + mt * 16 + (lane >> 2);
            #pragma unroll
            for (int n8 = 0; n8 < 4; n8++) {
                int col = wn * 32 + n8 * 8 + (lane & 3) * 2;
                pre[row * PS + col]           = acc[mt][n8][0];
                pre[row * PS + col + 1]       = acc[mt][n8][1];
                pre[(row + 8) * PS + col]     = acc[mt][n8][2];
                pre[(row + 8) * PS + col + 1] = acc[mt][n8][3];
            }
        }
        __syncthreads();
        // fused gate + state update + h/Hseq writes
        #pragma unroll
        for (int r = 0; r < 8; r++) {
            int b_l = r * 8 + wid;
            int bg = b0 + b_l;
            int L = Lb[r];
            bool msk = t < L;
            int u_g = us * 32 + lane;
            size_t xrow = ((size_t)bg * NT + t) * NG;
            float pi = pre[b_l * PS +       lane] + xg[xrow + u_g];
            float pf = pre[b_l * PS +  32 + lane] + xg[xrow + 512 + u_g];
            float pg = pre[b_l * PS +  64 + lane] + xg[xrow + 1024 + u_g];
            float po = pre[b_l * PS +  96 + lane] + xg[xrow + 1536 + u_g];
            float ig = sigm(pi), fg = sigm(pf), gv = tanhf(pg), og = sigm(po);
            float cn = fg * c_st[r] + ig * gv;
            float hn = og * tanhf(cn);
            c_st[r] = msk ? cn : c_st[r];
            float hw = msk ? hn : h_st[r];
            h_st[r] = hw;
            size_t hidx = ((size_t)(dir * 256 + bg)) * 512 + u_g;
            __nv_bfloat16 hh = __float2bfloat16_rn(hw);
            g_hh[wbuf][hidx] = hh;
            g_hl[wbuf][hidx] = __float2bfloat16_rn(hw - __bfloat162float(hh));
            int tout = dir ? (msk ? L - 1 - t : t) : t;
            float ho = msk ? hn : 0.f;
            size_t oidx = ((size_t)bg * NT + tout) * ND + dir * 512 + u_g;
            g_Hseq[oidx] = ho;
            __nv_bfloat16 oh = __float2bfloat16_rn(ho);
            g_Ahi[oidx] = oh;
            g_Alo[oidx] = __float2bfloat16_rn(ho - __bfloat162float(oh));
        }
        grid_barrier();
    }
}

// ---------------- BN / attention / phases (unchanged) ----------------
__global__ void k_colstats() {
    int col = blockIdx.x * 32 + threadIdx.x;
    int r0 = blockIdx.y * (NBT / 32);
    float s = 0.f, q = 0.f;
    for (int r = r0 + threadIdx.y; r < r0 + NBT / 32; r += 8) {
        float v = g_z[(size_t)r * ND + col];
        s += v; q += v * v;
    }
    __shared__ float ss[8][33], qq[8][33];
    ss[threadIdx.y][threadIdx.x] = s;
    qq[threadIdx.y][threadIdx.x] = q;
    __syncthreads();
    if (threadIdx.y == 0) {
        #pragma unroll
        for (int k = 1; k < 8; k++) { s += ss[k][threadIdx.x]; q += qq[k][threadIdx.x]; }
        atomicAdd(&g_colsum[col], s);
        atomicAdd(&g_colsq[col], q);
    }
}

__global__ void k_finalize() {
    int d = blockIdx.x * 256 + threadIdx.x;
    if (d < ND) {
        float mean = g_colsum[d] / (float)NBT;
        float var  = g_colsq[d] / (float)NBT - mean * mean;
        g_mu[d] = mean;
        g_rs[d] = rsqrtf(var + 1e-5f);
    }
}

__global__ void k_alpha(const float* __restrict__ s2w) {
    size_t row = blockIdx.x;
    float p = 0.f;
    for (int d = threadIdx.x; d < ND; d += 256) {
        float v = (g_z[row * ND + d] - g_mu[d]) * g_rs[d];
        p += leakyf(v) * s2w[d];
    }
    p = blockReduceSum(p);
    if (threadIdx.x == 0) g_alpha[row] = p;
}

__global__ void k_asum(const int* __restrict__ lens) {
    int b = blockIdx.x;
    int L = lens[b];
    float s = 0.f;
    for (int t = threadIdx.x; t < L; t += 128) s += g_alpha[b * NT + t];
    s = blockReduceSum(s);
    if (threadIdx.x == 0) g_asum[b] = s + 1e-9f;
}

__global__ void k_U(const int* __restrict__ lens) {
    int b = blockIdx.y;
    int d = blockIdx.x * 256 + threadIdx.x;
    int L = lens[b];
    float inv = 1.f / g_asum[b];
    float s = 0.f;
    for (int t = 0; t < L; t++)
        s += g_alpha[b * NT + t] * g_Hseq[((size_t)b * NT + t) * ND + d];
    g_U[(size_t)b * ND + d] = s * inv;
}

__global__ void k_L(const int* __restrict__ label3, float* __restrict__ outL) {
    for (int i = threadIdx.x; i < NE * NCC; i += 256) outL[i] = 0.f;
    __syncthreads();
    if (threadIdx.x < NE) {
        for (int j = 0; j < 3; j++) {
            int v = label3[threadIdx.x * 3 + j];
            if (v >= 0) outL[threadIdx.x * NCC + v] = 1.f;
        }
    }
}

__global__ void k_chunk() {
    int e = blockIdx.y, n = blockIdx.x;
    const float* __restrict__ emo  = g_U + (size_t)e * ND;
    const float* __restrict__ cau0 = g_U + (size_t)(NE + n * CKS) * ND;
    __shared__ float logits[CKS];
    __shared__ float sc[CKS];
    int w = threadIdx.x >> 5, lane = threadIdx.x & 31;
    float a0 = 0.f, a1 = 0.f;
    for (int d = lane; d < ND; d += 32) {
        float ed = emo[d];
        a0 += ed * cau0[(size_t)(2 * w) * ND + d];
        a1 += ed * cau0[(size_t)(2 * w + 1) * ND + d];
    }
    #pragma unroll
    for (int o = 16; o; o >>= 1) {
        a0 += __shfl_down_sync(0xffffffffu, a0, o);
        a1 += __shfl_down_sync(0xffffffffu, a1, o);
    }
    if (lane == 0) { logits[2 * w] = a0; logits[2 * w + 1] = a1; }
    __syncthreads();
    if (threadIdx.x == 0) {
        float mx = logits[0];
        for (int c = 1; c < CKS; c++) mx = fmaxf(mx, logits[c]);
        float s = 0.f;
        for (int c = 0; c < CKS; c++) { sc[c] = expf(logits[c] - mx); s += sc[c]; }
        float si = 1.f / s;
        for (int c = 0; c < CKS; c++) sc[c] *= si;
    }
    __syncthreads();
    for (int d = threadIdx.x; d < ND; d += 256) {
        float v = 0.f;
        #pragma unroll
        for (int c = 0; c < CKS; c++) v += sc[c] * cau0[(size_t)c * ND + d];
        g_chunk[(size_t)(e * NCK + n) * ND + d] = v;
    }
}

__global__ void k_delta2(const float* __restrict__ pos) {
    int e = blockIdx.y, n = blockIdx.x;
    int row = e * NCK + n;
    const float* __restrict__ emo = g_U + (size_t)e * ND;
    const float* __restrict__ ch  = g_chunk + (size_t)row * ND;
    float p = 0.f;
    for (int d = threadIdx.x; d < ND; d += 256) {
        float dd = emo[d] - ch[d];
        p += dd * dd;
    }
    p = blockReduceSum(p);
    float dist = sqrtf(p);
    size_t base = (size_t)row * NF2;
    for (int f = threadIdx.x; f < NF2; f += 256) {
        float v;
        if (f < ND) v = emo[f];
        else if (f < 2 * ND) v = ch[f - ND];
        else if (f == 2 * ND) v = dist;
        else if (f < 3 * ND + 1) v = emo[f - 2 * ND - 1] * ch[f - 2 * ND - 1];
        else v = pos[(size_t)row * NP + (f - (3 * ND + 1))];
        g_delta2[base + f] = v;
    }
}

__global__ void k_bn2() {
    int e = blockIdx.y;
    int d = blockIdx.x * 256 + threadIdx.x;
    float vals[NCK];
    float s = 0.f, q = 0.f;
    #pragma unroll
    for (int n = 0; n < NCK; n++) {
        float v = g_hid2[(size_t)(e * NCK + n) * ND + d];
        vals[n] = v; s += v; q += v * v;
    }
    float mean = s / (float)NCK;
    float var = q / (float)NCK - mean * mean;
    float r = rsqrtf(var + 1e-5f);
    #pragma unroll
    for (int n = 0; n < NCK; n++)
        g_hid2[(size_t)(e * NCK + n) * ND + d] = leakyf((vals[n] - mean) * r);
}

__global__ void k_out2(const float* __restrict__ Wow, const float* __restrict__ Wob,
                       float* __restrict__ out) {
    int row = blockIdx.x;
    float p0 = 0.f, p1 = 0.f;
    for (int d = threadIdx.x; d < ND; d += 256) {
        float h = g_hid2[(size_t)row * ND + d];
        p0 += h * Wow[d];
        p1 += h * Wow[ND + d];
    }
    p0 = blockReduceSum(p0);
    p1 = blockReduceSum(p1);
    if (threadIdx.x == 0) {
        float l0 = p0 + Wob[0], l1 = p1 + Wob[1];
        float mx = fmaxf(l0, l1);
        float lse = mx + logf(expf(l0 - mx) + expf(l1 - mx));
        out[row * 2 + 0] = l0 - lse;
        out[row * 2 + 1] = l1 - lse;
        g_extra[row] = (l1 > l0) ? 1.f : 0.f;
    }
}

__global__ void k_delta3(const float* __restrict__ dis) {
    int e = blockIdx.y, j = blockIdx.x;
    const float* __restrict__ emo = g_U + (size_t)e * ND;
    const float* __restrict__ y   = g_U + (size_t)(NE + j) * ND;
    float p = 0.f;
    for (int d = threadIdx.x; d < ND; d += 256) {
        float dd = emo[d] - y[d];
        p += dd * dd;
    }
    p = blockReduceSum(p);
    float dist = sqrtf(p);
    float ext = g_extra[e * NCK + (j >> 4)];
    size_t base = (size_t)(e * NCC + j) * NF3;
    for (int f = threadIdx.x; f < NF3; f += 256) {
        float v;
        if (f < ND) v = emo[f];
        else if (f < 2 * ND) v = y[f - ND];
        else if (f == 2 * ND) v = dist;
        else if (f < 3 * ND + 1) v = emo[f - 2 * ND - 1] * y[f - 2 * ND - 1];
        else if (f < 3 * ND + 1 + NP) v = dis[(size_t)(e * NCC + j) * NP + (f - (3 * ND + 1))];
        else v = ext;
        g_delta3[base + f] = v;
    }
}

__global__ void k_bn3() {
    int e = blockIdx.y;
    int d = blockIdx.x * 256 + threadIdx.x;
    float s = 0.f, q = 0.f;
    for (int j = 0; j < NCC; j++) {
        float v = g_h3[(size_t)(e * NCC + j) * ND + d];
        s += v; q += v * v;
    }
    float mean = s / (float)NCC;
    float var = q / (float)NCC - mean * mean;
    float r = rsqrtf(var + 1e-5f);
    for (int j = 0; j < NCC; j++) {
        size_t idx = (size_t)(e * NCC + j) * ND + d;
        g_h3[idx] = leakyf((g_h3[idx] - mean) * r);
    }
}

__global__ void k_cls(const float* __restrict__ clsw, const float* __restrict__ clsb,
                      float* __restrict__ outp) {
    int e = blockIdx.y, j = blockIdx.x;
    int row = e * NCC + j;
    float p0 = 0.f, p1 = 0.f;
    for (int d = threadIdx.x; d < ND; d += 256) {
        float h = g_h3[(size_t)row * ND + d];
        p0 += h * clsw[d];
        p1 += h * clsw[ND + d];
    }
    p0 = blockReduceSum(p0);
    p1 = blockReduceSum(p1);
    if (threadIdx.x == 0) {
        float l0 = p0 + clsb[0], l1 = p1 + clsb[1];
        float mx = fmaxf(l0, l1);
        float lse = mx + logf(expf(l0 - mx) + expf(l1 - mx));
        outp[row * 2 + 0] = l0 - lse;
        outp[row * 2 + 1] = l1 - lse;
    }
}

// ---------------- host launcher ----------------
static inline int cdiv(int a, int b) { return (a + b - 1) / b; }

extern "C" void kernel_launch(void* const* d_in, const int* in_sizes, int n_in,
                              void* d_out, int out_size) {
    const float *word, *pos, *dis, *Wihf, *Whhf, *bihf, *bhhf, *Wihb, *Whhb, *bihb, *bhhb;
    const float *s1w, *s1b, *s2w, *W2w, *W2b, *Wow, *Wob, *W3w, *W3b, *clsw, *clsb;
    const int *lens, *label3;
    if (in_sizes[3] == 256) {
        word = (const float*)d_in[0];  pos = (const float*)d_in[1];  dis = (const float*)d_in[2];
        lens = (const int*)d_in[3];    label3 = (const int*)d_in[4];
        Wihf = (const float*)d_in[7];  Whhf = (const float*)d_in[8];
        bihf = (const float*)d_in[9];  bhhf = (const float*)d_in[10];
        Wihb = (const float*)d_in[11]; Whhb = (const float*)d_in[12];
        bihb = (const float*)d_in[13]; bhhb = (const float*)d_in[14];
        s1w = (const float*)d_in[15];  s1b = (const float*)d_in[16]; s2w = (const float*)d_in[17];
        W2w = (const float*)d_in[18];  W2b = (const float*)d_in[19];
        Wow = (const float*)d_in[20];  Wob = (const float*)d_in[21];
        W3w = (const float*)d_in[22];  W3b = (const float*)d_in[23];
        clsw = (const float*)d_in[24]; clsb = (const float*)d_in[25];
    } else {
        word = (const float*)d_in[0];  pos = (const float*)d_in[1];  dis = (const float*)d_in[2];
        Wihf = (const float*)d_in[3];  Whhf = (const float*)d_in[4];
        bihf = (const float*)d_in[5];  bhhf = (const float*)d_in[6];
        Wihb = (const float*)d_in[7];  Whhb = (const float*)d_in[8];
        bihb = (const float*)d_in[9];  bhhb = (const float*)d_in[10];
        s1w = (const float*)d_in[11];  s1b = (const float*)d_in[12]; s2w = (const float*)d_in[13];
        W2w = (const float*)d_in[14];  W2b = (const float*)d_in[15];
        Wow = (const float*)d_in[16];  Wob = (const float*)d_in[17];
        W3w = (const float*)d_in[18];  W3b = (const float*)d_in[19];
        clsw = (const float*)d_in[20]; clsb = (const float*)d_in[21];
        lens = (const int*)d_in[22];   label3 = (const int*)d_in[23];
    }
    float* out = (float*)d_out;
    float* out_p3 = out + NE * NCK * 2;
    float* out_L  = out_p3 + NE * NCC * 2;

    void *p_xgf, *p_xgb, *p_Hseq, *p_z, *p_rev, *p_bf, *p_bb, *p_d2, *p_h2, *p_d3, *p_h3;
    void *p_Ahi, *p_Alo, *p_Bhi, *p_Blo;
    cudaGetSymbolAddress(&p_xgf, g_xg_f);
    cudaGetSymbolAddress(&p_xgb, g_xg_b);
    cudaGetSymbolAddress(&p_Hseq, g_Hseq);
    cudaGetSymbolAddress(&p_z, g_z);
    cudaGetSymbolAddress(&p_rev, g_rev);
    cudaGetSymbolAddress(&p_bf, g_biasf);
    cudaGetSymbolAddress(&p_bb, g_biasb);
    cudaGetSymbolAddress(&p_d2, g_delta2);
    cudaGetSymbolAddress(&p_h2, g_hid2);
    cudaGetSymbolAddress(&p_d3, g_delta3);
    cudaGetSymbolAddress(&p_h3, g_h3);
    cudaGetSymbolAddress(&p_Ahi, g_Ahi);
    cudaGetSymbolAddress(&p_Alo, g_Alo);
    cudaGetSymbolAddress(&p_Bhi, g_Bhi);
    cudaGetSymbolAddress(&p_Blo, g_Blo);
    __nv_bfloat16* Ahi = (__nv_bfloat16*)p_Ahi;
    __nv_bfloat16* Alo = (__nv_bfloat16*)p_Alo;
    __nv_bfloat16* Bhi = (__nv_bfloat16*)p_Bhi;
    __nv_bfloat16* Blo = (__nv_bfloat16*)p_Blo;

    cudaFuncSetAttribute(k_mgemm, cudaFuncAttributeMaxDynamicSharedMemorySize, MG_SMEM);
    cudaFuncSetAttribute(k_lstm_all, cudaFuncAttributeMaxDynamicSharedMemorySize, LS_SMEM);

    // 1. prep + weight reorder/split
    k_prep<<<1024, 256>>>(bihf, bhhf, bihb, bhhb, lens);
    k_wsplit<<<cdiv(2 * 2048 * 512, 256), 256>>>(Whhf, Whhb);

    // 2. split word + Wih, GEMM xg_f / xg_b
    k_split<<<cdiv(NBT * ND, 256), 256>>>(word, Ahi, Alo, NBT, ND, ND);
    k_split<<<cdiv(NG * ND, 256), 256>>>(Wihf, Bhi, Blo, NG, ND, ND);
    k_mgemm<<<dim3(NG / 128, NBT / 128), 256, MG_SMEM>>>(Ahi, Alo, Bhi, Blo,
        (const float*)p_bf, (float*)p_xgf, NBT, NG, ND, nullptr);
    k_split<<<cdiv(NG * ND, 256), 256>>>(Wihb, Bhi, Blo, NG, ND, ND);
    k_mgemm<<<dim3(NG / 128, NBT / 128), 256, MG_SMEM>>>(Ahi, Alo, Bhi, Blo,
        (const float*)p_bb, (float*)p_xgb, NBT, NG, ND, (const int*)p_rev);

    // 3. persistent bidirectional LSTM (writes Hseq + its bf16 split into Ahi/Alo)
    k_lstm_all<<<LS_CTAS, 256, LS_SMEM>>>(lens);

    // 4. z = Hseq @ s1_w^T + s1_b  (A split already produced by LSTM)
    k_split<<<cdiv(ND * ND, 256), 256>>>(s1w, Bhi, Blo, ND, ND, ND);
    k_mgemm<<<dim3(ND / 128, NBT / 128), 256, MG_SMEM>>>(Ahi, Alo, Bhi, Blo,
        s1b, (float*)p_z, NBT, ND, ND, nullptr);

    // 5. BN stats, alpha, U
    k_colstats<<<dim3(ND / 32, 32), dim3(32, 8)>>>();
    k_finalize<<<4, 256>>>();
    k_alpha<<<NBT, 256>>>(s2w);
    k_asum<<<NB, 128>>>(lens);
    k_U<<<dim3(ND / 256, NB), 256>>>(lens);

    // 6. L output
    k_L<<<1, 256>>>(label3, out_L);

    // 7. phase 2
    k_chunk<<<dim3(NCK, NE), 256>>>();
    k_delta2<<<dim3(NCK, NE), 256>>>(pos);
    k_split<<<cdiv(NE * NCK * KP2, 256), 256>>>((const float*)p_d2, Ahi, Alo, NE * NCK, NF2, KP2);
    k_split<<<cdiv(ND * KP2, 256), 256>>>(W2w, Bhi, Blo, ND, NF2, KP2);
    k_mgemm<<<dim3(ND / 128, (NE * NCK) / 128), 256, MG_SMEM>>>(Ahi, Alo, Bhi, Blo,
        W2b, (float*)p_h2, NE * NCK, ND, KP2, nullptr);
    k_bn2<<<dim3(ND / 256, NE), 256>>>();
    k_out2<<<NE * NCK, 256>>>(Wow, Wob, out);

    // 8. phase 3
    k_delta3<<<dim3(NCC, NE), 256>>>(dis);
    k_split<<<cdiv(NE * NCC * KP3, 256), 256>>>((const float*)p_d3, Ahi, Alo, NE * NCC, NF3, KP3);
    k_split<<<cdiv(ND * KP3, 256), 256>>>(W3w, Bhi, Blo, ND, NF3, KP3);
    k_mgemm<<<dim3(ND / 128, (NE * NCC) / 128), 256, MG_SMEM>>>(Ahi, Alo, Bhi, Blo,
        W3b, (float*)p_h3, NE * NCC, ND, KP3, nullptr);
    k_bn3<<<dim3(ND / 256, NE), 256>>>();
    k_cls<<<dim3(NCC, NE), 256>>>(clsw, clsb, out_p3);
}

// round 5
// speedup vs baseline: 2.8549x; 1.1640x over previous
#include <cuda_runtime.h>
#include <cuda_bf16.h>
#include <math.h>
#include <stdint.h>

#define NB 256
#define NT 128
#define ND 1024
#define NH 512
#define NG 2048
#define NBT (NB*NT)
#define NE 64
#define NCC 128
#define NCK 8
#define CKS 16
#define NP 50
#define NF2 3123
#define NF3 3173
#define KP2 3136
#define KP3 3200

// ---------------- scratch (device globals) ----------------
__device__ float g_xg_f[(size_t)NBT*NG];
__device__ float g_xg_b[(size_t)NBT*NG];
__device__ float g_Hseq[(size_t)NBT*ND];
__device__ float g_z[(size_t)NBT*ND];
__device__ int   g_rev[NBT];
__device__ float g_biasf[NG];
__device__ float g_biasb[NG];
__device__ float g_colsum[ND];
__device__ float g_colsq[ND];
__device__ float g_mu[ND];
__device__ float g_rs[ND];
__device__ float g_alpha[NBT];
__device__ float g_asum[NB];
__device__ float g_U[NB*ND];
__device__ float g_chunk[NE*NCK*ND];
__device__ float g_delta2[NE*NCK*NF2];
__device__ float g_hid2[NE*NCK*ND];
__device__ float g_extra[NE*NCK];
__device__ float g_delta3[(size_t)NE*NCC*NF3];
__device__ float g_h3[(size_t)NE*NCC*ND];
// bf16 split scratch
__device__ __nv_bfloat16 g_Ahi[(size_t)NBT*ND];
__device__ __nv_bfloat16 g_Alo[(size_t)NBT*ND];
__device__ __nv_bfloat16 g_Bhi[3276800];
__device__ __nv_bfloat16 g_Blo[3276800];
// LSTM: reordered+split recurrent weights, ping-pong h state, barrier
__device__ __nv_bfloat16 g_Wrh[2*2048*512];
__device__ __nv_bfloat16 g_Wrl[2*2048*512];
__device__ __nv_bfloat16 g_hh[2][2*256*512];
__device__ __nv_bfloat16 g_hl[2][2*256*512];
__device__ unsigned g_barcnt;
__device__ unsigned g_bargen;

// ---------------- mma.sync helpers ----------------
__device__ __forceinline__ uint32_t smem_u32(const void* p) {
    uint32_t a;
    asm("{ .reg .u64 t; cvta.to.shared.u64 t, %1; cvt.u32.u64 %0, t; }" : "=r"(a) : "l"(p));
    return a;
}
__device__ __forceinline__ void ldsm4(uint32_t* r, uint32_t a) {
    asm volatile("ldmatrix.sync.aligned.m8n8.x4.shared.b16 {%0,%1,%2,%3}, [%4];"
        : "=r"(r[0]), "=r"(r[1]), "=r"(r[2]), "=r"(r[3]) : "r"(a));
}
__device__ __forceinline__ void mma16816(float* c, const uint32_t* a, uint32_t b0, uint32_t b1) {
    asm volatile("mma.sync.aligned.m16n8k16.row.col.f32.bf16.bf16.f32 "
        "{%0,%1,%2,%3}, {%4,%5,%6,%7}, {%8,%9}, {%0,%1,%2,%3};"
        : "+f"(c[0]), "+f"(c[1]), "+f"(c[2]), "+f"(c[3])
        : "r"(a[0]), "r"(a[1]), "r"(a[2]), "r"(a[3]), "r"(b0), "r"(b1));
}
__device__ __forceinline__ void cpa16(uint32_t d, const void* s) {
    asm volatile("cp.async.cg.shared.global [%0], [%1], 16;" :: "r"(d), "l"(s));
}
#define CP_COMMIT() asm volatile("cp.async.commit_group;" ::: "memory")

// ---------------- helpers ----------------
__device__ __forceinline__ float blockReduceSum(float v) {
    __shared__ float sh[33];
    int lane = threadIdx.x & 31, wid = threadIdx.x >> 5;
    #pragma unroll
    for (int o = 16; o; o >>= 1) v += __shfl_down_sync(0xffffffffu, v, o);
    __syncthreads();
    if (lane == 0) sh[wid] = v;
    __syncthreads();
    float r = 0.f;
    int nw = blockDim.x >> 5;
    if (threadIdx.x < nw) r = sh[threadIdx.x];
    if (wid == 0) {
        #pragma unroll
        for (int o = 16; o; o >>= 1) r += __shfl_down_sync(0xffffffffu, r, o);
        if (lane == 0) sh[32] = r;
    }
    __syncthreads();
    return sh[32];
}
__device__ __forceinline__ float leakyf(float v) { return v >= 0.f ? v : 0.01f * v; }
__device__ __forceinline__ float sigm(float v) { return 1.f / (1.f + expf(-v)); }

// ---------------- prep ----------------
__global__ void k_prep(const float* __restrict__ bihf, const float* __restrict__ bhhf,
                       const float* __restrict__ bihb, const float* __restrict__ bhhb,
                       const int* __restrict__ lens) {
    int i = blockIdx.x * blockDim.x + threadIdx.x;
    if (i < NBT) {
        int b = i / NT, t = i % NT, L = lens[b];
        g_rev[i] = b * NT + (t < L ? L - 1 - t : t);
    }
    if (i < NG) { g_biasf[i] = bihf[i] + bhhf[i]; g_biasb[i] = bihb[i] + bhhb[i]; }
    if (i < ND) { g_colsum[i] = 0.f; g_colsq[i] = 0.f; }
    if (i < 2 * 256 * 512) {
        g_hh[0][i] = __float2bfloat16(0.f);
        g_hl[0][i] = __float2bfloat16(0.f);
    }
    if (i == 0) { g_barcnt = 0; g_bargen = 0; }
}

// ---------------- Whh reorder + hi/lo split (once) ----------------
__global__ void k_wsplit(const float* __restrict__ Wf, const float* __restrict__ Wb) {
    size_t i = (size_t)blockIdx.x * 256 + threadIdx.x;
    if (i >= (size_t)2 * 2048 * 512) return;
    int dir = (int)(i / (2048 * 512));
    size_t rem = i % (2048 * 512);
    int gr = (int)(rem / 512), k = (int)(rem % 512);
    int ty = gr >> 9, u = gr & 511;
    int r = (u >> 5) * 128 + ty * 32 + (u & 31);
    float v = (dir ? Wb : Wf)[(size_t)gr * 512 + k];
    __nv_bfloat16 h = __float2bfloat16_rn(v);
    g_Wrh[((size_t)dir * 2048 + r) * 512 + k] = h;
    g_Wrl[((size_t)dir * 2048 + r) * 512 + k] = __float2bfloat16_rn(v - __bfloat162float(h));
}

// ---------------- fp32 -> (hi,lo) bf16 split with K padding ----------------
__global__ void k_split(const float* __restrict__ src, __nv_bfloat16* __restrict__ hi,
                        __nv_bfloat16* __restrict__ lo, int R, int K, int Kp) {
    int i = blockIdx.x * 256 + threadIdx.x;
    if (i >= R * Kp) return;
    int r = i / Kp, k = i - r * Kp;
    float v = (k < K) ? src[(size_t)r * K + k] : 0.f;
    __nv_bfloat16 h = __float2bfloat16_rn(v);
    hi[i] = h;
    lo[i] = __float2bfloat16_rn(v - __bfloat162float(h));
}

// ---------------- mma.sync split-bf16 GEMM ----------------
#define SROWB 80
#define ARRB (128*SROWB)
#define BUFB (4*ARRB)
#define MG_SMEM (2*BUFB)
__global__ __launch_bounds__(256, 2) void k_mgemm(
    const __nv_bfloat16* __restrict__ Ah, const __nv_bfloat16* __restrict__ Al,
    const __nv_bfloat16* __restrict__ Bh, const __nv_bfloat16* __restrict__ Bl,
    const float* __restrict__ bias, float* __restrict__ C,
    int M, int N, int Kp, const int* __restrict__ gather)
{
    extern __shared__ char smem[];
    uint32_t sb = smem_u32(smem);
    const int tid = threadIdx.x, wid = tid >> 5, lane = tid & 31;
    const int m0 = blockIdx.y * 128, n0 = blockIdx.x * 128;
    const int wm = wid & 3, wn = wid >> 2;

    size_t aoff[2], boff[2];
    uint32_t soff[2];
    #pragma unroll
    for (int s = 0; s < 2; s++) {
        int idx = tid + s * 256;
        int r = idx >> 2, j = idx & 3;
        int ra = gather ? gather[m0 + r] : (m0 + r);
        aoff[s] = (size_t)ra * Kp + j * 8;
        boff[s] = (size_t)(n0 + r) * Kp + j * 8;
        soff[s] = r * SROWB + j * 16;
    }

    float acc[2][8][4];
    #pragma unroll
    for (int i = 0; i < 2; i++)
        #pragma unroll
        for (int j = 0; j < 8; j++)
            #pragma unroll
            for (int k = 0; k < 4; k++) acc[i][j][k] = 0.f;

    const int NC = Kp >> 5;
    {
        uint32_t bb = sb;
        #pragma unroll
        for (int s = 0; s < 2; s++) {
            cpa16(bb + soff[s],            Ah + aoff[s]);
            cpa16(bb + ARRB + soff[s],     Al + aoff[s]);
            cpa16(bb + 2 * ARRB + soff[s], Bh + boff[s]);
            cpa16(bb + 3 * ARRB + soff[s], Bl + boff[s]);
        }
        CP_COMMIT();
    }
    for (int i = 0; i < NC; i++) {
        int buf = i & 1;
        if (i + 1 < NC) {
            int k0 = (i + 1) << 5;
            uint32_t bb = sb + (buf ^ 1) * BUFB;
            #pragma unroll
            for (int s = 0; s < 2; s++) {
                cpa16(bb + soff[s],            Ah + aoff[s] + k0);
                cpa16(bb + ARRB + soff[s],     Al + aoff[s] + k0);
                cpa16(bb + 2 * ARRB + soff[s], Bh + boff[s] + k0);
                cpa16(bb + 3 * ARRB + soff[s], Bl + boff[s] + k0);
            }
            CP_COMMIT();
            asm volatile("cp.async.wait_group 1;" ::: "memory");
        } else {
            asm volatile("cp.async.wait_group 0;" ::: "memory");
        }
        __syncthreads();
        uint32_t bufb = sb + buf * BUFB;
        #pragma unroll
        for (int pass = 0; pass < 3; pass++) {
            uint32_t aB = bufb + (pass == 2 ? ARRB : 0);
            uint32_t bB = bufb + 2 * ARRB + (pass == 1 ? ARRB : 0);
            #pragma unroll
            for (int ks = 0; ks < 2; ks++) {
                uint32_t ar = aB + (wm * 32 + (lane & 15)) * SROWB + ks * 32 + ((lane >> 4) << 4);
                uint32_t a0[4], a1[4];
                ldsm4(a0, ar);
                ldsm4(a1, ar + 16 * SROWB);
                #pragma unroll
                for (int nt = 0; nt < 4; nt++) {
                    uint32_t br = bB + (wn * 64 + nt * 16 + (lane & 15)) * SROWB + ks * 32 + ((lane >> 4) << 4);
                    uint32_t bf[4];
                    ldsm4(bf, br);
                    mma16816(acc[0][nt * 2],     a0, bf[0], bf[2]);
                    mma16816(acc[0][nt * 2 + 1], a0, bf[1], bf[3]);
                    mma16816(acc[1][nt * 2],     a1, bf[0], bf[2]);
                    mma16816(acc[1][nt * 2 + 1], a1, bf[1], bf[3]);
                }
            }
        }
        __syncthreads();
    }
    #pragma unroll
    for (int mt = 0; mt < 2; mt++) {
        int m = m0 + wm * 32 + mt * 16 + (lane >> 2);
        #pragma unroll
        for (int nt = 0; nt < 8; nt++) {
            int n = n0 + wn * 64 + nt * 8 + (lane & 3) * 2;
            float b0 = bias ? bias[n] : 0.f, b1 = bias ? bias[n + 1] : 0.f;
            float2 v0 = make_float2(acc[mt][nt][0] + b0, acc[mt][nt][1] + b1);
            float2 v1 = make_float2(acc[mt][nt][2] + b0, acc[mt][nt][3] + b1);
            *(float2*)&C[(size_t)m * N + n] = v0;
            *(float2*)&C[(size_t)(m + 8) * N + n] = v1;
        }
    }
}

// ---------------- persistent bidirectional LSTM ----------------
#define SR2 144
#define LA_SZ (64*SR2)
#define LB_SZ (128*SR2)
#define LBUF (2*LA_SZ + 2*LB_SZ)
#define LS_SMEM (2*LBUF)
#define PS 132
#define LS_CTAS 128

__device__ __forceinline__ void grid_barrier() {
    __syncthreads();
    if (threadIdx.x == 0) {
        unsigned gen;
        asm volatile("ld.relaxed.gpu.u32 %0, [%1];" : "=r"(gen) : "l"(&g_bargen));
        unsigned t;
        asm volatile("atom.add.release.gpu.u32 %0, [%1], 1;" : "=r"(t) : "l"(&g_barcnt) : "memory");
        if (t == LS_CTAS - 1) {
            asm volatile("st.relaxed.gpu.u32 [%0], %1;" :: "l"(&g_barcnt), "r"(0u) : "memory");
            asm volatile("st.release.gpu.u32 [%0], %1;" :: "l"(&g_bargen), "r"(gen + 1) : "memory");
        } else {
            unsigned g2;
            do {
                asm volatile("ld.acquire.gpu.u32 %0, [%1];" : "=r"(g2) : "l"(&g_bargen) : "memory");
            } while (g2 == gen);
        }
    }
    __syncthreads();
}

__global__ __launch_bounds__(256, 1) void k_lstm_all(const int* __restrict__ lens)
{
    extern __shared__ char sm[];
    uint32_t sb = smem_u32(sm);
    const int tid = threadIdx.x, wid = tid >> 5, lane = tid & 31;
    const int cta = blockIdx.x;
    const int dir = cta >> 6;
    const int ms = (cta & 63) >> 4;
    const int us = cta & 15;
    const int b0 = ms * 64;
    const int wm = wid & 1, wn = wid >> 1;
    const float* __restrict__ xg = dir ? g_xg_b : g_xg_f;
    const __nv_bfloat16* __restrict__ Wh = g_Wrh + ((size_t)dir * 2048 + us * 128) * 512;
    const __nv_bfloat16* __restrict__ Wl = g_Wrl + ((size_t)dir * 2048 + us * 128) * 512;

    float c_st[8], h_st[8];
    int Lb[8];
    #pragma unroll
    for (int r = 0; r < 8; r++) {
        c_st[r] = 0.f; h_st[r] = 0.f;
        Lb[r] = lens[b0 + r * 8 + wid];
    }

    uint32_t aso[2], bso[4];
    int arow[2], brow[4];
    #pragma unroll
    for (int s = 0; s < 2; s++) {
        int idx = tid + s * 256;
        arow[s] = idx >> 3;
        aso[s] = (idx >> 3) * SR2 + (idx & 7) * 16;
    }
    #pragma unroll
    for (int s = 0; s < 4; s++) {
        int idx = tid + s * 256;
        brow[s] = idx >> 3;
        bso[s] = (idx >> 3) * SR2 + (idx & 7) * 16;
    }
    int aj[2], bj[4];
    #pragma unroll
    for (int s = 0; s < 2; s++) aj[s] = ((tid + s * 256) & 7) * 8;
    #pragma unroll
    for (int s = 0; s < 4; s++) bj[s] = ((tid + s * 256) & 7) * 8;

    const int u_g = us * 32 + lane;

    for (int t = 0; t < NT; t++) {
        const int rbuf = t & 1, wbuf = rbuf ^ 1;
        const __nv_bfloat16* __restrict__ hhp = g_hh[rbuf];
        const __nv_bfloat16* __restrict__ hlp = g_hl[rbuf];

        float acc[2][4][4];
        #pragma unroll
        for (int i = 0; i < 2; i++)
            #pragma unroll
            for (int j = 0; j < 4; j++)
                #pragma unroll
                for (int k = 0; k < 4; k++) acc[i][j][k] = 0.f;

        // prologue: chunk 0
        {
            uint32_t bb = sb;
            #pragma unroll
            for (int s = 0; s < 2; s++) {
                size_t ho = ((size_t)(dir * 256 + b0 + arow[s])) * 512 + aj[s];
                cpa16(bb + aso[s],         hhp + ho);
                cpa16(bb + LA_SZ + aso[s], hlp + ho);
            }
            #pragma unroll
            for (int s = 0; s < 4; s++) {
                size_t wo = (size_t)brow[s] * 512 + bj[s];
                cpa16(bb + 2 * LA_SZ + bso[s],         Wh + wo);
                cpa16(bb + 2 * LA_SZ + LB_SZ + bso[s], Wl + wo);
            }
            CP_COMMIT();
        }
        // hoisted gate loads: absorb gmem latency under the MMA loop
        float xv[8][4];
        #pragma unroll
        for (int r = 0; r < 8; r++) {
            size_t xrow = ((size_t)(b0 + r * 8 + wid) * NT + t) * NG + u_g;
            xv[r][0] = xg[xrow];
            xv[r][1] = xg[xrow + 512];
            xv[r][2] = xg[xrow + 1024];
            xv[r][3] = xg[xrow + 1536];
        }
        for (int ch = 0; ch < 8; ch++) {
            int buf = ch & 1;
            if (ch + 1 < 8) {
                int k0 = (ch + 1) << 6;
                uint32_t bb = sb + (buf ^ 1) * LBUF;
                #pragma unroll
                for (int s = 0; s < 2; s++) {
                    size_t ho = ((size_t)(dir * 256 + b0 + arow[s])) * 512 + k0 + aj[s];
                    cpa16(bb + aso[s],         hhp + ho);
                    cpa16(bb + LA_SZ + aso[s], hlp + ho);
                }
                #pragma unroll
                for (int s = 0; s < 4; s++) {
                    size_t wo = (size_t)brow[s] * 512 + k0 + bj[s];
                    cpa16(bb + 2 * LA_SZ + bso[s],         Wh + wo);
                    cpa16(bb + 2 * LA_SZ + LB_SZ + bso[s], Wl + wo);
                }
                CP_COMMIT();
                asm volatile("cp.async.wait_group 1;" ::: "memory");
            } else {
                asm volatile("cp.async.wait_group 0;" ::: "memory");
            }
            __syncthreads();
            uint32_t bufb = sb + buf * LBUF;
            #pragma unroll
            for (int pass = 0; pass < 3; pass++) {
                uint32_t aB = bufb + (pass == 2 ? LA_SZ : 0);
                uint32_t bB = bufb + 2 * LA_SZ + (pass == 1 ? LB_SZ : 0);
                #pragma unroll
                for (int k16 = 0; k16 < 4; k16++) {
                    uint32_t ar = aB + (wm * 32 + (lane & 15)) * SR2 + k16 * 32 + ((lane >> 4) << 4);
                    uint32_t a0[4], a1[4];
                    ldsm4(a0, ar);
                    ldsm4(a1, ar + 16 * SR2);
                    #pragma unroll
                    for (int nt = 0; nt < 2; nt++) {
                        uint32_t br = bB + (wn * 32 + nt * 16 + (lane & 15)) * SR2 + k16 * 32 + ((lane >> 4) << 4);
                        uint32_t bf[4];
                        ldsm4(bf, br);
                        mma16816(acc[0][nt * 2],     a0, bf[0], bf[2]);
                        mma16816(acc[0][nt * 2 + 1], a0, bf[1], bf[3]);
                        mma16816(acc[1][nt * 2],     a1, bf[0], bf[2]);
                        mma16816(acc[1][nt * 2 + 1], a1, bf[1], bf[3]);
                    }
                }
            }
            __syncthreads();
        }
        // stage pre-activations to smem
        float* pre = (float*)sm;
        #pragma unroll
        for (int mt = 0; mt < 2; mt++) {
            int row = wm * 32 + mt * 16 + (lane >> 2);
            #pragma unroll
            for (int n8 = 0; n8 < 4; n8++) {
                int col = wn * 32 + n8 * 8 + (lane & 3) * 2;
                pre[row * PS + col]           = acc[mt][n8][0];
                pre[row * PS + col + 1]       = acc[mt][n8][1];
                pre[(row + 8) * PS + col]     = acc[mt][n8][2];
                pre[(row + 8) * PS + col + 1] = acc[mt][n8][3];
            }
        }
        __syncthreads();
        // fused gate + state update + h/Hseq writes
        #pragma unroll
        for (int r = 0; r < 8; r++) {
            int b_l = r * 8 + wid;
            int bg = b0 + b_l;
            int L = Lb[r];
            bool msk = t < L;
            float pi = pre[b_l * PS +       lane] + xv[r][0];
            float pf = pre[b_l * PS +  32 + lane] + xv[r][1];
            float pg = pre[b_l * PS +  64 + lane] + xv[r][2];
            float po = pre[b_l * PS +  96 + lane] + xv[r][3];
            float ig = sigm(pi), fg = sigm(pf), gv = tanhf(pg), og = sigm(po);
            float cn = fg * c_st[r] + ig * gv;
            float hn = og * tanhf(cn);
            c_st[r] = msk ? cn : c_st[r];
            float hw = msk ? hn : h_st[r];
            h_st[r] = hw;
            size_t hidx = ((size_t)(dir * 256 + bg)) * 512 + u_g;
            __nv_bfloat16 hh = __float2bfloat16_rn(hw);
            g_hh[wbuf][hidx] = hh;
            g_hl[wbuf][hidx] = __float2bfloat16_rn(hw - __bfloat162float(hh));
            int tout = dir ? (msk ? L - 1 - t : t) : t;
            float ho = msk ? hn : 0.f;
            size_t oidx = ((size_t)bg * NT + tout) * ND + dir * 512 + u_g;
            g_Hseq[oidx] = ho;
            __nv_bfloat16 oh = __float2bfloat16_rn(ho);
            g_Ahi[oidx] = oh;
            g_Alo[oidx] = __float2bfloat16_rn(ho - __bfloat162float(oh));
        }
        grid_barrier();
    }
}

// ---------------- BN / attention / phases ----------------
__global__ void k_colstats() {
    int col = blockIdx.x * 32 + threadIdx.x;
    int r0 = blockIdx.y * (NBT / 32);
    float s = 0.f, q = 0.f;
    for (int r = r0 + threadIdx.y; r < r0 + NBT / 32; r += 8) {
        float v = g_z[(size_t)r * ND + col];
        s += v; q += v * v;
    }
    __shared__ float ss[8][33], qq[8][33];
    ss[threadIdx.y][threadIdx.x] = s;
    qq[threadIdx.y][threadIdx.x] = q;
    __syncthreads();
    if (threadIdx.y == 0) {
        #pragma unroll
        for (int k = 1; k < 8; k++) { s += ss[k][threadIdx.x]; q += qq[k][threadIdx.x]; }
        atomicAdd(&g_colsum[col], s);
        atomicAdd(&g_colsq[col], q);
    }
}

__global__ void k_finalize() {
    int d = blockIdx.x * 256 + threadIdx.x;
    if (d < ND) {
        float mean = g_colsum[d] / (float)NBT;
        float var  = g_colsq[d] / (float)NBT - mean * mean;
        g_mu[d] = mean;
        g_rs[d] = rsqrtf(var + 1e-5f);
    }
}

__global__ void k_alpha(const float* __restrict__ s2w) {
    size_t row = blockIdx.x;
    float p = 0.f;
    for (int d = threadIdx.x; d < ND; d += 256) {
        float v = (g_z[row * ND + d] - g_mu[d]) * g_rs[d];
        p += leakyf(v) * s2w[d];
    }
    p = blockReduceSum(p);
    if (threadIdx.x == 0) g_alpha[row] = p;
}

__global__ void k_asum(const int* __restrict__ lens) {
    int b = blockIdx.x;
    int L = lens[b];
    float s = 0.f;
    for (int t = threadIdx.x; t < L; t += 128) s += g_alpha[b * NT + t];
    s = blockReduceSum(s);
    if (threadIdx.x == 0) g_asum[b] = s + 1e-9f;
}

__global__ void k_U(const int* __restrict__ lens) {
    int b = blockIdx.y;
    int d = blockIdx.x * 256 + threadIdx.x;
    int L = lens[b];
    float inv = 1.f / g_asum[b];
    float s = 0.f;
    for (int t = 0; t < L; t++)
        s += g_alpha[b * NT + t] * g_Hseq[((size_t)b * NT + t) * ND + d];
    g_U[(size_t)b * ND + d] = s * inv;
}

__global__ void k_L(const int* __restrict__ label3, float* __restrict__ outL) {
    for (int i = threadIdx.x; i < NE * NCC; i += 256) outL[i] = 0.f;
    __syncthreads();
    if (threadIdx.x < NE) {
        for (int j = 0; j < 3; j++) {
            int v = label3[threadIdx.x * 3 + j];
            if (v >= 0) outL[threadIdx.x * NCC + v] = 1.f;
        }
    }
}

__global__ void k_chunk() {
    int e = blockIdx.y, n = blockIdx.x;
    const float* __restrict__ emo  = g_U + (size_t)e * ND;
    const float* __restrict__ cau0 = g_U + (size_t)(NE + n * CKS) * ND;
    __shared__ float logits[CKS];
    __shared__ float sc[CKS];
    int w = threadIdx.x >> 5, lane = threadIdx.x & 31;
    float a0 = 0.f, a1 = 0.f;
    for (int d = lane; d < ND; d += 32) {
        float ed = emo[d];
        a0 += ed * cau0[(size_t)(2 * w) * ND + d];
        a1 += ed * cau0[(size_t)(2 * w + 1) * ND + d];
    }
    #pragma unroll
    for (int o = 16; o; o >>= 1) {
        a0 += __shfl_down_sync(0xffffffffu, a0, o);
        a1 += __shfl_down_sync(0xffffffffu, a1, o);
    }
    if (lane == 0) { logits[2 * w] = a0; logits[2 * w + 1] = a1; }
    __syncthreads();
    if (threadIdx.x == 0) {
        float mx = logits[0];
        for (int c = 1; c < CKS; c++) mx = fmaxf(mx, logits[c]);
        float s = 0.f;
        for (int c = 0; c < CKS; c++) { sc[c] = expf(logits[c] - mx); s += sc[c]; }
        float si = 1.f / s;
        for (int c = 0; c < CKS; c++) sc[c] *= si;
    }
    __syncthreads();
    for (int d = threadIdx.x; d < ND; d += 256) {
        float v = 0.f;
        #pragma unroll
        for (int c = 0; c < CKS; c++) v += sc[c] * cau0[(size_t)c * ND + d];
        g_chunk[(size_t)(e * NCK + n) * ND + d] = v;
    }
}

__global__ void k_delta2(const float* __restrict__ pos) {
    int e = blockIdx.y, n = blockIdx.x;
    int row = e * NCK + n;
    const float* __restrict__ emo = g_U + (size_t)e * ND;
    const float* __restrict__ ch  = g_chunk + (size_t)row * ND;
    float p = 0.f;
    for (int d = threadIdx.x; d < ND; d += 256) {
        float dd = emo[d] - ch[d];
        p += dd * dd;
    }
    p = blockReduceSum(p);
    float dist = sqrtf(p);
    size_t base = (size_t)row * NF2;
    for (int f = threadIdx.x; f < NF2; f += 256) {
        float v;
        if (f < ND) v = emo[f];
        else if (f < 2 * ND) v = ch[f - ND];
        else if (f == 2 * ND) v = dist;
        else if (f < 3 * ND + 1) v = emo[f - 2 * ND - 1] * ch[f - 2 * ND - 1];
        else v = pos[(size_t)row * NP + (f - (3 * ND + 1))];
        g_delta2[base + f] = v;
    }
}

__global__ void k_bn2() {
    int e = blockIdx.y;
    int d = blockIdx.x * 256 + threadIdx.x;
    float vals[NCK];
    float s = 0.f, q = 0.f;
    #pragma unroll
    for (int n = 0; n < NCK; n++) {
        float v = g_hid2[(size_t)(e * NCK + n) * ND + d];
        vals[n] = v; s += v; q += v * v;
    }
    float mean = s / (float)NCK;
    float var = q / (float)NCK - mean * mean;
    float r = rsqrtf(var + 1e-5f);
    #pragma unroll
    for (int n = 0; n < NCK; n++)
        g_hid2[(size_t)(e * NCK + n) * ND + d] = leakyf((vals[n] - mean) * r);
}

__global__ void k_out2(const float* __restrict__ Wow, const float* __restrict__ Wob,
                       float* __restrict__ out) {
    int row = blockIdx.x;
    float p0 = 0.f, p1 = 0.f;
    for (int d = threadIdx.x; d < ND; d += 256) {
        float h = g_hid2[(size_t)row * ND + d];
        p0 += h * Wow[d];
        p1 += h * Wow[ND + d];
    }
    p0 = blockReduceSum(p0);
    p1 = blockReduceSum(p1);
    if (threadIdx.x == 0) {
        float l0 = p0 + Wob[0], l1 = p1 + Wob[1];
        float mx = fmaxf(l0, l1);
        float lse = mx + logf(expf(l0 - mx) + expf(l1 - mx));
        out[row * 2 + 0] = l0 - lse;
        out[row * 2 + 1] = l1 - lse;
        g_extra[row] = (l1 > l0) ? 1.f : 0.f;
    }
}

__global__ void k_delta3(const float* __restrict__ dis) {
    int e = blockIdx.y, j = blockIdx.x;
    const float* __restrict__ emo = g_U + (size_t)e * ND;
    const float* __restrict__ y   = g_U + (size_t)(NE + j) * ND;
    float p = 0.f;
    for (int d = threadIdx.x; d < ND; d += 256) {
        float dd = emo[d] - y[d];
        p += dd * dd;
    }
    p = blockReduceSum(p);
    float dist = sqrtf(p);
    float ext = g_extra[e * NCK + (j >> 4)];
    size_t base = (size_t)(e * NCC + j) * NF3;
    for (int f = threadIdx.x; f < NF3; f += 256) {
        float v;
        if (f < ND) v = emo[f];
        else if (f < 2 * ND) v = y[f - ND];
        else if (f == 2 * ND) v = dist;
        else if (f < 3 * ND + 1) v = emo[f - 2 * ND - 1] * y[f - 2 * ND - 1];
        else if (f < 3 * ND + 1 + NP) v = dis[(size_t)(e * NCC + j) * NP + (f - (3 * ND + 1))];
        else v = ext;
        g_delta3[base + f] = v;
    }
}

__global__ void k_bn3() {
    int e = blockIdx.y;
    int d = blockIdx.x * 256 + threadIdx.x;
    float s = 0.f, q = 0.f;
    for (int j = 0; j < NCC; j++) {
        float v = g_h3[(size_t)(e * NCC + j) * ND + d];
        s += v; q += v * v;
    }
    float mean = s / (float)NCC;
    float var = q / (float)NCC - mean * mean;
    float r = rsqrtf(var + 1e-5f);
    for (int j = 0; j < NCC; j++) {
        size_t idx = (size_t)(e * NCC + j) * ND + d;
        g_h3[idx] = leakyf((g_h3[idx] - mean) * r);
    }
}

__global__ void k_cls(const float* __restrict__ clsw, const float* __restrict__ clsb,
                      float* __restrict__ outp) {
    int e = blockIdx.y, j = blockIdx.x;
    int row = e * NCC + j;
    float p0 = 0.f, p1 = 0.f;
    for (int d = threadIdx.x; d < ND; d += 256) {
        float h = g_h3[(size_t)row * ND + d];
        p0 += h * clsw[d];
        p1 += h * clsw[ND + d];
    }
    p0 = blockReduceSum(p0);
    p1 = blockReduceSum(p1);
    if (threadIdx.x == 0) {
        float l0 = p0 + clsb[0], l1 = p1 + clsb[1];
        float mx = fmaxf(l0, l1);
        float lse = mx + logf(expf(l0 - mx) + expf(l1 - mx));
        outp[row * 2 + 0] = l0 - lse;
        outp[row * 2 + 1] = l1 - lse;
    }
}

// ---------------- host launcher ----------------
static inline int cdiv(int a, int b) { return (a + b - 1) / b; }

extern "C" void kernel_launch(void* const* d_in, const int* in_sizes, int n_in,
                              void* d_out, int out_size) {
    const float *word, *pos, *dis, *Wihf, *Whhf, *bihf, *bhhf, *Wihb, *Whhb, *bihb, *bhhb;
    const float *s1w, *s1b, *s2w, *W2w, *W2b, *Wow, *Wob, *W3w, *W3b, *clsw, *clsb;
    const int *lens, *label3;
    if (in_sizes[3] == 256) {
        word = (const float*)d_in[0];  pos = (const float*)d_in[1];  dis = (const float*)d_in[2];
        lens = (const int*)d_in[3];    label3 = (const int*)d_in[4];
        Wihf = (const float*)d_in[7];  Whhf = (const float*)d_in[8];
        bihf = (const float*)d_in[9];  bhhf = (const float*)d_in[10];
        Wihb = (const float*)d_in[11]; Whhb = (const float*)d_in[12];
        bihb = (const float*)d_in[13]; bhhb = (const float*)d_in[14];
        s1w = (const float*)d_in[15];  s1b = (const float*)d_in[16]; s2w = (const float*)d_in[17];
        W2w = (const float*)d_in[18];  W2b = (const float*)d_in[19];
        Wow = (const float*)d_in[20];  Wob = (const float*)d_in[21];
        W3w = (const float*)d_in[22];  W3b = (const float*)d_in[23];
        clsw = (const float*)d_in[24]; clsb = (const float*)d_in[25];
    } else {
        word = (const float*)d_in[0];  pos = (const float*)d_in[1];  dis = (const float*)d_in[2];
        Wihf = (const float*)d_in[3];  Whhf = (const float*)d_in[4];
        bihf = (const float*)d_in[5];  bhhf = (const float*)d_in[6];
        Wihb = (const float*)d_in[7];  Whhb = (const float*)d_in[8];
        bihb = (const float*)d_in[9];  bhhb = (const float*)d_in[10];
        s1w = (const float*)d_in[11];  s1b = (const float*)d_in[12]; s2w = (const float*)d_in[13];
        W2w = (const float*)d_in[14];  W2b = (const float*)d_in[15];
        Wow = (const float*)d_in[16];  Wob = (const float*)d_in[17];
        W3w = (const float*)d_in[18];  W3b = (const float*)d_in[19];
        clsw = (const float*)d_in[20]; clsb = (const float*)d_in[21];
        lens = (const int*)d_in[22];   label3 = (const int*)d_in[23];
    }
    float* out = (float*)d_out;
    float* out_p3 = out + NE * NCK * 2;
    float* out_L  = out_p3 + NE * NCC * 2;

    void *p_xgf, *p_xgb, *p_Hseq, *p_z, *p_rev, *p_bf, *p_bb, *p_d2, *p_h2, *p_d3, *p_h3;
    void *p_Ahi, *p_Alo, *p_Bhi, *p_Blo;
    cudaGetSymbolAddress(&p_xgf, g_xg_f);
    cudaGetSymbolAddress(&p_xgb, g_xg_b);
    cudaGetSymbolAddress(&p_Hseq, g_Hseq);
    cudaGetSymbolAddress(&p_z, g_z);
    cudaGetSymbolAddress(&p_rev, g_rev);
    cudaGetSymbolAddress(&p_bf, g_biasf);
    cudaGetSymbolAddress(&p_bb, g_biasb);
    cudaGetSymbolAddress(&p_d2, g_delta2);
    cudaGetSymbolAddress(&p_h2, g_hid2);
    cudaGetSymbolAddress(&p_d3, g_delta3);
    cudaGetSymbolAddress(&p_h3, g_h3);
    cudaGetSymbolAddress(&p_Ahi, g_Ahi);
    cudaGetSymbolAddress(&p_Alo, g_Alo);
    cudaGetSymbolAddress(&p_Bhi, g_Bhi);
    cudaGetSymbolAddress(&p_Blo, g_Blo);
    __nv_bfloat16* Ahi = (__nv_bfloat16*)p_Ahi;
    __nv_bfloat16* Alo = (__nv_bfloat16*)p_Alo;
    __nv_bfloat16* Bhi = (__nv_bfloat16*)p_Bhi;
    __nv_bfloat16* Blo = (__nv_bfloat16*)p_Blo;

    cudaFuncSetAttribute(k_mgemm, cudaFuncAttributeMaxDynamicSharedMemorySize, MG_SMEM);
    cudaFuncSetAttribute(k_lstm_all, cudaFuncAttributeMaxDynamicSharedMemorySize, LS_SMEM);

    // 1. prep + weight reorder/split
    k_prep<<<1024, 256>>>(bihf, bhhf, bihb, bhhb, lens);
    k_wsplit<<<cdiv(2 * 2048 * 512, 256), 256>>>(Whhf, Whhb);

    // 2. split word + Wih, GEMM xg_f / xg_b
    k_split<<<cdiv(NBT * ND, 256), 256>>>(word, Ahi, Alo, NBT, ND, ND);
    k_split<<<cdiv(NG * ND, 256), 256>>>(Wihf, Bhi, Blo, NG, ND, ND);
    k_mgemm<<<dim3(NG / 128, NBT / 128), 256, MG_SMEM>>>(Ahi, Alo, Bhi, Blo,
        (const float*)p_bf, (float*)p_xgf, NBT, NG, ND, nullptr);
    k_split<<<cdiv(NG * ND, 256), 256>>>(Wihb, Bhi, Blo, NG, ND, ND);
    k_mgemm<<<dim3(NG / 128, NBT / 128), 256, MG_SMEM>>>(Ahi, Alo, Bhi, Blo,
        (const float*)p_bb, (float*)p_xgb, NBT, NG, ND, (const int*)p_rev);

    // 3. persistent bidirectional LSTM
    k_lstm_all<<<LS_CTAS, 256, LS_SMEM>>>(lens);

    // 4. z = Hseq @ s1_w^T + s1_b
    k_split<<<cdiv(ND * ND, 256), 256>>>(s1w, Bhi, Blo, ND, ND, ND);
    k_mgemm<<<dim3(ND / 128, NBT / 128), 256, MG_SMEM>>>(Ahi, Alo, Bhi, Blo,
        s1b, (float*)p_z, NBT, ND, ND, nullptr);

    // 5. BN stats, alpha, U
    k_colstats<<<dim3(ND / 32, 32), dim3(32, 8)>>>();
    k_finalize<<<4, 256>>>();
    k_alpha<<<NBT, 256>>>(s2w);
    k_asum<<<NB, 128>>>(lens);
    k_U<<<dim3(ND / 256, NB), 256>>>(lens);

    // 6. L output
    k_L<<<1, 256>>>(label3, out_L);

    // 7. phase 2
    k_chunk<<<dim3(NCK, NE), 256>>>();
    k_delta2<<<dim3(NCK, NE), 256>>>(pos);
    k_split<<<cdiv(NE * NCK * KP2, 256), 256>>>((const float*)p_d2, Ahi, Alo, NE * NCK, NF2, KP2);
    k_split<<<cdiv(ND * KP2, 256), 256>>>(W2w, Bhi, Blo, ND, NF2, KP2);
    k_mgemm<<<dim3(ND / 128, (NE * NCK) / 128), 256, MG_SMEM>>>(Ahi, Alo, Bhi, Blo,
        W2b, (float*)p_h2, NE * NCK, ND, KP2, nullptr);
    k_bn2<<<dim3(ND / 256, NE), 256>>>();
    k_out2<<<NE * NCK, 256>>>(Wow, Wob, out);

    // 8. phase 3
    k_delta3<<<dim3(NCC, NE), 256>>>(dis);
    k_split<<<cdiv(NE * NCC * KP3, 256), 256>>>((const float*)p_d3, Ahi, Alo, NE * NCC, NF3, KP3);
    k_split<<<cdiv(ND * KP3, 256), 256>>>(W3w, Bhi, Blo, ND, NF3, KP3);
    k_mgemm<<<dim3(ND / 128, (NE * NCC) / 128), 256, MG_SMEM>>>(Ahi, Alo, Bhi, Blo,
        W3b, (float*)p_h3, NE * NCC, ND, KP3, nullptr);
    k_bn3<<<dim3(ND / 256, NE), 256>>>();
    k_cls<<<dim3(NCC, NE), 256>>>(clsw, clsb, out_p3);
}

// round 8
// speedup vs baseline: 3.0252x; 1.0597x over previous
#include <cuda_runtime.h>
#include <cuda_bf16.h>
#include <math.h>
#include <stdint.h>

#define NB 256
#define NT 128
#define ND 1024
#define NH 512
#define NG 2048
#define NBT (NB*NT)
#define NE 64
#define NCC 128
#define NCK 8
#define CKS 16
#define NP 50
#define NF2 3123
#define NF3 3173
#define KP2 3136
#define KP3 3200

// ---------------- scratch (device globals) ----------------
__device__ float g_xg_f[(size_t)NBT*NG];
__device__ float g_xg_b[(size_t)NBT*NG];
__device__ float g_Hseq[(size_t)NBT*ND];
__device__ float g_z[(size_t)NBT*ND];
__device__ int   g_rev[NBT];
__device__ float g_biasf[NG];
__device__ float g_biasb[NG];
__device__ float g_colsum[ND];
__device__ float g_colsq[ND];
__device__ float g_mu[ND];
__device__ float g_rs[ND];
__device__ float g_alpha[NBT];
__device__ float g_asum[NB];
__device__ float g_U[NB*ND];
__device__ float g_chunk[NE*NCK*ND];
__device__ float g_hid2[NE*NCK*ND];
__device__ float g_extra[NE*NCK];
__device__ float g_h3[(size_t)NE*NCC*ND];
// bf16 split scratch
__device__ __nv_bfloat16 g_Ahi[(size_t)NBT*ND];
__device__ __nv_bfloat16 g_Alo[(size_t)NBT*ND];
__device__ __nv_bfloat16 g_Bhi[3276800];
__device__ __nv_bfloat16 g_Blo[3276800];
// LSTM: reordered+split recurrent weights, ping-pong h state, barrier
__device__ __nv_bfloat16 g_Wrh[2*2048*512];
__device__ __nv_bfloat16 g_Wrl[2*2048*512];
__device__ __nv_bfloat16 g_hh[2][2*256*512];
__device__ __nv_bfloat16 g_hl[2][2*256*512];
__device__ unsigned g_barcnt;
__device__ unsigned g_bargen;

// ---------------- mma.sync helpers ----------------
__device__ __forceinline__ uint32_t smem_u32(const void* p) {
    uint32_t a;
    asm("{ .reg .u64 t; cvta.to.shared.u64 t, %1; cvt.u32.u64 %0, t; }" : "=r"(a) : "l"(p));
    return a;
}
__device__ __forceinline__ void ldsm4(uint32_t* r, uint32_t a) {
    asm volatile("ldmatrix.sync.aligned.m8n8.x4.shared.b16 {%0,%1,%2,%3}, [%4];"
        : "=r"(r[0]), "=r"(r[1]), "=r"(r[2]), "=r"(r[3]) : "r"(a));
}
__device__ __forceinline__ void mma16816(float* c, const uint32_t* a, uint32_t b0, uint32_t b1) {
    asm volatile("mma.sync.aligned.m16n8k16.row.col.f32.bf16.bf16.f32 "
        "{%0,%1,%2,%3}, {%4,%5,%6,%7}, {%8,%9}, {%0,%1,%2,%3};"
        : "+f"(c[0]), "+f"(c[1]), "+f"(c[2]), "+f"(c[3])
        : "r"(a[0]), "r"(a[1]), "r"(a[2]), "r"(a[3]), "r"(b0), "r"(b1));
}
__device__ __forceinline__ void cpa16(uint32_t d, const void* s) {
    asm volatile("cp.async.cg.shared.global [%0], [%1], 16;" :: "r"(d), "l"(s));
}
#define CP_COMMIT() asm volatile("cp.async.commit_group;" ::: "memory")

// ---------------- helpers ----------------
__device__ __forceinline__ float blockReduceSum(float v) {
    __shared__ float sh[33];
    int lane = threadIdx.x & 31, wid = threadIdx.x >> 5;
    #pragma unroll
    for (int o = 16; o; o >>= 1) v += __shfl_down_sync(0xffffffffu, v, o);
    __syncthreads();
    if (lane == 0) sh[wid] = v;
    __syncthreads();
    float r = 0.f;
    int nw = blockDim.x >> 5;
    if (threadIdx.x < nw) r = sh[threadIdx.x];
    if (wid == 0) {
        #pragma unroll
        for (int o = 16; o; o >>= 1) r += __shfl_down_sync(0xffffffffu, r, o);
        if (lane == 0) sh[32] = r;
    }
    __syncthreads();
    return sh[32];
}
__device__ __forceinline__ float leakyf(float v) { return v >= 0.f ? v : 0.01f * v; }
__device__ __forceinline__ float sigm(float v) { return 1.f / (1.f + expf(-v)); }

// ---------------- prep ----------------
__global__ void k_prep(const float* __restrict__ bihf, const float* __restrict__ bhhf,
                       const float* __restrict__ bihb, const float* __restrict__ bhhb,
                       const int* __restrict__ lens) {
    int i = blockIdx.x * blockDim.x + threadIdx.x;
    if (i < NBT) {
        int b = i / NT, t = i % NT, L = lens[b];
        g_rev[i] = b * NT + (t < L ? L - 1 - t : t);
    }
    if (i < NG) { g_biasf[i] = bihf[i] + bhhf[i]; g_biasb[i] = bihb[i] + bhhb[i]; }
    if (i < ND) { g_colsum[i] = 0.f; g_colsq[i] = 0.f; }
    if (i < 2 * 256 * 512) {
        g_hh[0][i] = __float2bfloat16(0.f);
        g_hl[0][i] = __float2bfloat16(0.f);
    }
    if (i == 0) { g_barcnt = 0; g_bargen = 0; }
}

// ---------------- Whh reorder + hi/lo split (once) ----------------
__global__ void k_wsplit(const float* __restrict__ Wf, const float* __restrict__ Wb) {
    size_t i = (size_t)blockIdx.x * 256 + threadIdx.x;
    if (i >= (size_t)2 * 2048 * 512) return;
    int dir = (int)(i / (2048 * 512));
    size_t rem = i % (2048 * 512);
    int gr = (int)(rem / 512), k = (int)(rem % 512);
    int ty = gr >> 9, u = gr & 511;
    int r = (u >> 5) * 128 + ty * 32 + (u & 31);
    float v = (dir ? Wb : Wf)[(size_t)gr * 512 + k];
    __nv_bfloat16 h = __float2bfloat16_rn(v);
    g_Wrh[((size_t)dir * 2048 + r) * 512 + k] = h;
    g_Wrl[((size_t)dir * 2048 + r) * 512 + k] = __float2bfloat16_rn(v - __bfloat162float(h));
}

// ---------------- fp32 -> (hi,lo) bf16 split, 4 elems/thread ----------------
__global__ void k_split(const float* __restrict__ src, __nv_bfloat16* __restrict__ hi,
                        __nv_bfloat16* __restrict__ lo, int R, int K, int Kp) {
    int i4 = blockIdx.x * 256 + threadIdx.x;
    int total4 = (R * Kp) >> 2;
    if (i4 >= total4) return;
    int base = i4 << 2;
    int r = base / Kp, k0 = base - r * Kp;
    __nv_bfloat16 h4[4], l4[4];
    #pragma unroll
    for (int j = 0; j < 4; j++) {
        int k = k0 + j;
        float v = (k < K) ? src[(size_t)r * K + k] : 0.f;
        __nv_bfloat16 h = __float2bfloat16_rn(v);
        h4[j] = h;
        l4[j] = __float2bfloat16_rn(v - __bfloat162float(h));
    }
    *(uint2*)(hi + base) = *(uint2*)h4;
    *(uint2*)(lo + base) = *(uint2*)l4;
}

// ---------------- mma.sync split-bf16 GEMM (fused 3-pass inner loop) ----------------
#define SROWB 80
#define ARRB (128*SROWB)
#define BUFB (4*ARRB)
#define MG_SMEM (2*BUFB)
__global__ __launch_bounds__(256, 2) void k_mgemm(
    const __nv_bfloat16* __restrict__ Ah, const __nv_bfloat16* __restrict__ Al,
    const __nv_bfloat16* __restrict__ Bh, const __nv_bfloat16* __restrict__ Bl,
    const float* __restrict__ bias, float* __restrict__ C,
    int M, int N, int Kp, const int* __restrict__ gather)
{
    extern __shared__ char smem[];
    uint32_t sb = smem_u32(smem);
    const int tid = threadIdx.x, wid = tid >> 5, lane = tid & 31;
    const int m0 = blockIdx.y * 128, n0 = blockIdx.x * 128;
    const int wm = wid & 3, wn = wid >> 2;

    size_t aoff[2], boff[2];
    uint32_t soff[2];
    #pragma unroll
    for (int s = 0; s < 2; s++) {
        int idx = tid + s * 256;
        int r = idx >> 2, j = idx & 3;
        int ra = gather ? gather[m0 + r] : (m0 + r);
        aoff[s] = (size_t)ra * Kp + j * 8;
        boff[s] = (size_t)(n0 + r) * Kp + j * 8;
        soff[s] = r * SROWB + j * 16;
    }

    float acc[2][8][4];
    #pragma unroll
    for (int i = 0; i < 2; i++)
        #pragma unroll
        for (int j = 0; j < 8; j++)
            #pragma unroll
            for (int k = 0; k < 4; k++) acc[i][j][k] = 0.f;

    const int NC = Kp >> 5;
    {
        uint32_t bb = sb;
        #pragma unroll
        for (int s = 0; s < 2; s++) {
            cpa16(bb + soff[s],            Ah + aoff[s]);
            cpa16(bb + ARRB + soff[s],     Al + aoff[s]);
            cpa16(bb + 2 * ARRB + soff[s], Bh + boff[s]);
            cpa16(bb + 3 * ARRB + soff[s], Bl + boff[s]);
        }
        CP_COMMIT();
    }
    for (int i = 0; i < NC; i++) {
        int buf = i & 1;
        if (i + 1 < NC) {
            int k0 = (i + 1) << 5;
            uint32_t bb = sb + (buf ^ 1) * BUFB;
            #pragma unroll
            for (int s = 0; s < 2; s++) {
                cpa16(bb + soff[s],            Ah + aoff[s] + k0);
                cpa16(bb + ARRB + soff[s],     Al + aoff[s] + k0);
                cpa16(bb + 2 * ARRB + soff[s], Bh + boff[s] + k0);
                cpa16(bb + 3 * ARRB + soff[s], Bl + boff[s] + k0);
            }
            CP_COMMIT();
            asm volatile("cp.async.wait_group 1;" ::: "memory");
        } else {
            asm volatile("cp.async.wait_group 0;" ::: "memory");
        }
        __syncthreads();
        uint32_t bufb = sb + buf * BUFB;
        uint32_t aHB = bufb, aLB = bufb + ARRB, bHB = bufb + 2 * ARRB, bLB = bufb + 3 * ARRB;
        #pragma unroll
        for (int ks = 0; ks < 2; ks++) {
            uint32_t aro = (wm * 32 + (lane & 15)) * SROWB + ks * 32 + ((lane >> 4) << 4);
            uint32_t ah0[4], ah1[4], al0[4], al1[4];
            ldsm4(ah0, aHB + aro);
            ldsm4(ah1, aHB + aro + 16 * SROWB);
            ldsm4(al0, aLB + aro);
            ldsm4(al1, aLB + aro + 16 * SROWB);
            #pragma unroll
            for (int nt = 0; nt < 4; nt++) {
                uint32_t bro = (wn * 64 + nt * 16 + (lane & 15)) * SROWB + ks * 32 + ((lane >> 4) << 4);
                uint32_t bh[4], bl[4];
                ldsm4(bh, bHB + bro);
                ldsm4(bl, bLB + bro);
                mma16816(acc[0][nt * 2],     ah0, bh[0], bh[2]);
                mma16816(acc[0][nt * 2 + 1], ah0, bh[1], bh[3]);
                mma16816(acc[1][nt * 2],     ah1, bh[0], bh[2]);
                mma16816(acc[1][nt * 2 + 1], ah1, bh[1], bh[3]);
                mma16816(acc[0][nt * 2],     al0, bh[0], bh[2]);
                mma16816(acc[0][nt * 2 + 1], al0, bh[1], bh[3]);
                mma16816(acc[1][nt * 2],     al1, bh[0], bh[2]);
                mma16816(acc[1][nt * 2 + 1], al1, bh[1], bh[3]);
                mma16816(acc[0][nt * 2],     ah0, bl[0], bl[2]);
                mma16816(acc[0][nt * 2 + 1], ah0, bl[1], bl[3]);
                mma16816(acc[1][nt * 2],     ah1, bl[0], bl[2]);
                mma16816(acc[1][nt * 2 + 1], ah1, bl[1], bl[3]);
            }
        }
        __syncthreads();
    }
    #pragma unroll
    for (int mt = 0; mt < 2; mt++) {
        int m = m0 + wm * 32 + mt * 16 + (lane >> 2);
        #pragma unroll
        for (int nt = 0; nt < 8; nt++) {
            int n = n0 + wn * 64 + nt * 8 + (lane & 3) * 2;
            float b0 = bias ? bias[n] : 0.f, b1 = bias ? bias[n + 1] : 0.f;
            float2 v0 = make_float2(acc[mt][nt][0] + b0, acc[mt][nt][1] + b1);
            float2 v1 = make_float2(acc[mt][nt][2] + b0, acc[mt][nt][3] + b1);
            *(float2*)&C[(size_t)m * N + n] = v0;
            *(float2*)&C[(size_t)(m + 8) * N + n] = v1;
        }
    }
}

// ---------------- persistent bidirectional LSTM (fused 3-pass) ----------------
#define SR2 144
#define LA_SZ (64*SR2)
#define LB_SZ (128*SR2)
#define LBUF (2*LA_SZ + 2*LB_SZ)
#define LS_SMEM (2*LBUF)
#define PS 132
#define LS_CTAS 128

__device__ __forceinline__ void grid_barrier() {
    __syncthreads();
    if (threadIdx.x == 0) {
        unsigned gen;
        asm volatile("ld.relaxed.gpu.u32 %0, [%1];" : "=r"(gen) : "l"(&g_bargen));
        unsigned t;
        asm volatile("atom.add.release.gpu.u32 %0, [%1], 1;" : "=r"(t) : "l"(&g_barcnt) : "memory");
        if (t == LS_CTAS - 1) {
            asm volatile("st.relaxed.gpu.u32 [%0], %1;" :: "l"(&g_barcnt), "r"(0u) : "memory");
            asm volatile("st.release.gpu.u32 [%0], %1;" :: "l"(&g_bargen), "r"(gen + 1) : "memory");
        } else {
            unsigned g2;
            do {
                asm volatile("ld.acquire.gpu.u32 %0, [%1];" : "=r"(g2) : "l"(&g_bargen) : "memory");
            } while (g2 == gen);
        }
    }
    __syncthreads();
}

__global__ __launch_bounds__(256, 1) void k_lstm_all(const int* __restrict__ lens)
{
    extern __shared__ char sm[];
    uint32_t sb = smem_u32(sm);
    const int tid = threadIdx.x, wid = tid >> 5, lane = tid & 31;
    const int cta = blockIdx.x;
    const int dir = cta >> 6;
    const int ms = (cta & 63) >> 4;
    const int us = cta & 15;
    const int b0 = ms * 64;
    const int wm = wid & 1, wn = wid >> 1;
    const float* __restrict__ xg = dir ? g_xg_b : g_xg_f;
    const __nv_bfloat16* __restrict__ Wh = g_Wrh + ((size_t)dir * 2048 + us * 128) * 512;
    const __nv_bfloat16* __restrict__ Wl = g_Wrl + ((size_t)dir * 2048 + us * 128) * 512;

    float c_st[8], h_st[8];
    int Lb[8];
    #pragma unroll
    for (int r = 0; r < 8; r++) {
        c_st[r] = 0.f; h_st[r] = 0.f;
        Lb[r] = lens[b0 + r * 8 + wid];
    }

    uint32_t aso[2], bso[4];
    int arow[2], brow[4];
    #pragma unroll
    for (int s = 0; s < 2; s++) {
        int idx = tid + s * 256;
        arow[s] = idx >> 3;
        aso[s] = (idx >> 3) * SR2 + (idx & 7) * 16;
    }
    #pragma unroll
    for (int s = 0; s < 4; s++) {
        int idx = tid + s * 256;
        brow[s] = idx >> 3;
        bso[s] = (idx >> 3) * SR2 + (idx & 7) * 16;
    }
    int aj[2], bj[4];
    #pragma unroll
    for (int s = 0; s < 2; s++) aj[s] = ((tid + s * 256) & 7) * 8;
    #pragma unroll
    for (int s = 0; s < 4; s++) bj[s] = ((tid + s * 256) & 7) * 8;

    const int u_g = us * 32 + lane;

    for (int t = 0; t < NT; t++) {
        const int rbuf = t & 1, wbuf = rbuf ^ 1;
        const __nv_bfloat16* __restrict__ hhp = g_hh[rbuf];
        const __nv_bfloat16* __restrict__ hlp = g_hl[rbuf];

        float acc[2][4][4];
        #pragma unroll
        for (int i = 0; i < 2; i++)
            #pragma unroll
            for (int j = 0; j < 4; j++)
                #pragma unroll
                for (int k = 0; k < 4; k++) acc[i][j][k] = 0.f;

        {
            uint32_t bb = sb;
            #pragma unroll
            for (int s = 0; s < 2; s++) {
                size_t ho = ((size_t)(dir * 256 + b0 + arow[s])) * 512 + aj[s];
                cpa16(bb + aso[s],         hhp + ho);
                cpa16(bb + LA_SZ + aso[s], hlp + ho);
            }
            #pragma unroll
            for (int s = 0; s < 4; s++) {
                size_t wo = (size_t)brow[s] * 512 + bj[s];
                cpa16(bb + 2 * LA_SZ + bso[s],         Wh + wo);
                cpa16(bb + 2 * LA_SZ + LB_SZ + bso[s], Wl + wo);
            }
            CP_COMMIT();
        }
        // hoisted gate loads
        float xv[8][4];
        #pragma unroll
        for (int r = 0; r < 8; r++) {
            size_t xrow = ((size_t)(b0 + r * 8 + wid) * NT + t) * NG + u_g;
            xv[r][0] = xg[xrow];
            xv[r][1] = xg[xrow + 512];
            xv[r][2] = xg[xrow + 1024];
            xv[r][3] = xg[xrow + 1536];
        }
        for (int ch = 0; ch < 8; ch++) {
            int buf = ch & 1;
            if (ch + 1 < 8) {
                int k0 = (ch + 1) << 6;
                uint32_t bb = sb + (buf ^ 1) * LBUF;
                #pragma unroll
                for (int s = 0; s < 2; s++) {
                    size_t ho = ((size_t)(dir * 256 + b0 + arow[s])) * 512 + k0 + aj[s];
                    cpa16(bb + aso[s],         hhp + ho);
                    cpa16(bb + LA_SZ + aso[s], hlp + ho);
                }
                #pragma unroll
                for (int s = 0; s < 4; s++) {
                    size_t wo = (size_t)brow[s] * 512 + k0 + bj[s];
                    cpa16(bb + 2 * LA_SZ + bso[s],         Wh + wo);
                    cpa16(bb + 2 * LA_SZ + LB_SZ + bso[s], Wl + wo);
                }
                CP_COMMIT();
                asm volatile("cp.async.wait_group 1;" ::: "memory");
            } else {
                asm volatile("cp.async.wait_group 0;" ::: "memory");
            }
            __syncthreads();
            uint32_t bufb = sb + buf * LBUF;
            uint32_t aHB = bufb, aLB = bufb + LA_SZ;
            uint32_t bHB = bufb + 2 * LA_SZ, bLB = bufb + 2 * LA_SZ + LB_SZ;
            #pragma unroll
            for (int k16 = 0; k16 < 4; k16++) {
                uint32_t aro = (wm * 32 + (lane & 15)) * SR2 + k16 * 32 + ((lane >> 4) << 4);
                uint32_t ah0[4], ah1[4], al0[4], al1[4];
                ldsm4(ah0, aHB + aro);
                ldsm4(ah1, aHB + aro + 16 * SR2);
                ldsm4(al0, aLB + aro);
                ldsm4(al1, aLB + aro + 16 * SR2);
                #pragma unroll
                for (int nt = 0; nt < 2; nt++) {
                    uint32_t bro = (wn * 32 + nt * 16 + (lane & 15)) * SR2 + k16 * 32 + ((lane >> 4) << 4);
                    uint32_t bh[4], bl[4];
                    ldsm4(bh, bHB + bro);
                    ldsm4(bl, bLB + bro);
                    mma16816(acc[0][nt * 2],     ah0, bh[0], bh[2]);
                    mma16816(acc[0][nt * 2 + 1], ah0, bh[1], bh[3]);
                    mma16816(acc[1][nt * 2],     ah1, bh[0], bh[2]);
                    mma16816(acc[1][nt * 2 + 1], ah1, bh[1], bh[3]);
                    mma16816(acc[0][nt * 2],     al0, bh[0], bh[2]);
                    mma16816(acc[0][nt * 2 + 1], al0, bh[1], bh[3]);
                    mma16816(acc[1][nt * 2],     al1, bh[0], bh[2]);
                    mma16816(acc[1][nt * 2 + 1], al1, bh[1], bh[3]);
                    mma16816(acc[0][nt * 2],     ah0, bl[0], bl[2]);
                    mma16816(acc[0][nt * 2 + 1], ah0, bl[1], bl[3]);
                    mma16816(acc[1][nt * 2],     ah1, bl[0], bl[2]);
                    mma16816(acc[1][nt * 2 + 1], ah1, bl[1], bl[3]);
                }
            }
            __syncthreads();
        }
        float* pre = (float*)sm;
        #pragma unroll
        for (int mt = 0; mt < 2; mt++) {
            int row = wm * 32 + mt * 16 + (lane >> 2);
            #pragma unroll
            for (int n8 = 0; n8 < 4; n8++) {
                int col = wn * 32 + n8 * 8 + (lane & 3) * 2;
                pre[row * PS + col]           = acc[mt][n8][0];
                pre[row * PS + col + 1]       = acc[mt][n8][1];
                pre[(row + 8) * PS + col]     = acc[mt][n8][2];
                pre[(row + 8) * PS + col + 1] = acc[mt][n8][3];
            }
        }
        __syncthreads();
        #pragma unroll
        for (int r = 0; r < 8; r++) {
            int b_l = r * 8 + wid;
            int bg = b0 + b_l;
            int L = Lb[r];
            bool msk = t < L;
            float pi = pre[b_l * PS +       lane] + xv[r][0];
            float pf = pre[b_l * PS +  32 + lane] + xv[r][1];
            float pg = pre[b_l * PS +  64 + lane] + xv[r][2];
            float po = pre[b_l * PS +  96 + lane] + xv[r][3];
            float ig = sigm(pi), fg = sigm(pf), gv = tanhf(pg), og = sigm(po);
            float cn = fg * c_st[r] + ig * gv;
            float hn = og * tanhf(cn);
            c_st[r] = msk ? cn : c_st[r];
            float hw = msk ? hn : h_st[r];
            h_st[r] = hw;
            size_t hidx = ((size_t)(dir * 256 + bg)) * 512 + u_g;
            __nv_bfloat16 hh = __float2bfloat16_rn(hw);
            g_hh[wbuf][hidx] = hh;
            g_hl[wbuf][hidx] = __float2bfloat16_rn(hw - __bfloat162float(hh));
            int tout = dir ? (msk ? L - 1 - t : t) : t;
            float ho = msk ? hn : 0.f;
            size_t oidx = ((size_t)bg * NT + tout) * ND + dir * 512 + u_g;
            g_Hseq[oidx] = ho;
            __nv_bfloat16 oh = __float2bfloat16_rn(ho);
            g_Ahi[oidx] = oh;
            g_Alo[oidx] = __float2bfloat16_rn(ho - __bfloat162float(oh));
        }
        grid_barrier();
    }
}

// ---------------- BN / attention / phases ----------------
__global__ void k_colstats() {
    int col = blockIdx.x * 32 + threadIdx.x;
    int r0 = blockIdx.y * (NBT / 32);
    float s = 0.f, q = 0.f;
    for (int r = r0 + threadIdx.y; r < r0 + NBT / 32; r += 8) {
        float v = g_z[(size_t)r * ND + col];
        s += v; q += v * v;
    }
    __shared__ float ss[8][33], qq[8][33];
    ss[threadIdx.y][threadIdx.x] = s;
    qq[threadIdx.y][threadIdx.x] = q;
    __syncthreads();
    if (threadIdx.y == 0) {
        #pragma unroll
        for (int k = 1; k < 8; k++) { s += ss[k][threadIdx.x]; q += qq[k][threadIdx.x]; }
        atomicAdd(&g_colsum[col], s);
        atomicAdd(&g_colsq[col], q);
    }
}

__global__ void k_finalize() {
    int d = blockIdx.x * 256 + threadIdx.x;
    if (d < ND) {
        float mean = g_colsum[d] / (float)NBT;
        float var  = g_colsq[d] / (float)NBT - mean * mean;
        g_mu[d] = mean;
        g_rs[d] = rsqrtf(var + 1e-5f);
    }
}

__global__ void k_alpha(const float* __restrict__ s2w) {
    size_t row = blockIdx.x;
    float p = 0.f;
    for (int d = threadIdx.x; d < ND; d += 256) {
        float v = (g_z[row * ND + d] - g_mu[d]) * g_rs[d];
        p += leakyf(v) * s2w[d];
    }
    p = blockReduceSum(p);
    if (threadIdx.x == 0) g_alpha[row] = p;
}

__global__ void k_asum(const int* __restrict__ lens) {
    int b = blockIdx.x;
    int L = lens[b];
    float s = 0.f;
    for (int t = threadIdx.x; t < L; t += 128) s += g_alpha[b * NT + t];
    s = blockReduceSum(s);
    if (threadIdx.x == 0) g_asum[b] = s + 1e-9f;
}

__global__ void k_U(const int* __restrict__ lens) {
    int b = blockIdx.y;
    int d = blockIdx.x * 256 + threadIdx.x;
    int L = lens[b];
    float inv = 1.f / g_asum[b];
    float s = 0.f;
    for (int t = 0; t < L; t++)
        s += g_alpha[b * NT + t] * g_Hseq[((size_t)b * NT + t) * ND + d];
    g_U[(size_t)b * ND + d] = s * inv;
}

__global__ void k_L(const int* __restrict__ label3, float* __restrict__ outL) {
    for (int i = threadIdx.x; i < NE * NCC; i += 256) outL[i] = 0.f;
    __syncthreads();
    if (threadIdx.x < NE) {
        for (int j = 0; j < 3; j++) {
            int v = label3[threadIdx.x * 3 + j];
            if (v >= 0) outL[threadIdx.x * NCC + v] = 1.f;
        }
    }
}

__global__ void k_chunk() {
    int e = blockIdx.y, n = blockIdx.x;
    const float* __restrict__ emo  = g_U + (size_t)e * ND;
    const float* __restrict__ cau0 = g_U + (size_t)(NE + n * CKS) * ND;
    __shared__ float logits[CKS];
    __shared__ float sc[CKS];
    int w = threadIdx.x >> 5, lane = threadIdx.x & 31;
    float a0 = 0.f, a1 = 0.f;
    for (int d = lane; d < ND; d += 32) {
        float ed = emo[d];
        a0 += ed * cau0[(size_t)(2 * w) * ND + d];
        a1 += ed * cau0[(size_t)(2 * w + 1) * ND + d];
    }
    #pragma unroll
    for (int o = 16; o; o >>= 1) {
        a0 += __shfl_down_sync(0xffffffffu, a0, o);
        a1 += __shfl_down_sync(0xffffffffu, a1, o);
    }
    if (lane == 0) { logits[2 * w] = a0; logits[2 * w + 1] = a1; }
    __syncthreads();
    if (threadIdx.x == 0) {
        float mx = logits[0];
        for (int c = 1; c < CKS; c++) mx = fmaxf(mx, logits[c]);
        float s = 0.f;
        for (int c = 0; c < CKS; c++) { sc[c] = expf(logits[c] - mx); s += sc[c]; }
        float si = 1.f / s;
        for (int c = 0; c < CKS; c++) sc[c] *= si;
    }
    __syncthreads();
    for (int d = threadIdx.x; d < ND; d += 256) {
        float v = 0.f;
        #pragma unroll
        for (int c = 0; c < CKS; c++) v += sc[c] * cau0[(size_t)c * ND + d];
        g_chunk[(size_t)(e * NCK + n) * ND + d] = v;
    }
}

// delta2 -> bf16 split direct (rows [0,512), width KP2)
__global__ void k_delta2(const float* __restrict__ pos) {
    int e = blockIdx.y, n = blockIdx.x;
    int row = e * NCK + n;
    const float* __restrict__ emo = g_U + (size_t)e * ND;
    const float* __restrict__ ch  = g_chunk + (size_t)row * ND;
    float p = 0.f;
    for (int d = threadIdx.x; d < ND; d += 256) {
        float dd = emo[d] - ch[d];
        p += dd * dd;
    }
    p = blockReduceSum(p);
    float dist = sqrtf(p);
    size_t base = (size_t)row * KP2;
    for (int f = threadIdx.x; f < KP2; f += 256) {
        float v;
        if (f < ND) v = emo[f];
        else if (f < 2 * ND) v = ch[f - ND];
        else if (f == 2 * ND) v = dist;
        else if (f < 3 * ND + 1) v = emo[f - 2 * ND - 1] * ch[f - 2 * ND - 1];
        else if (f < NF2) v = pos[(size_t)row * NP + (f - (3 * ND + 1))];
        else v = 0.f;
        __nv_bfloat16 h = __float2bfloat16_rn(v);
        g_Ahi[base + f] = h;
        g_Alo[base + f] = __float2bfloat16_rn(v - __bfloat162float(h));
    }
}

__global__ void k_bn2() {
    int e = blockIdx.y;
    int d = blockIdx.x * 256 + threadIdx.x;
    float vals[NCK];
    float s = 0.f, q = 0.f;
    #pragma unroll
    for (int n = 0; n < NCK; n++) {
        float v = g_hid2[(size_t)(e * NCK + n) * ND + d];
        vals[n] = v; s += v; q += v * v;
    }
    float mean = s / (float)NCK;
    float var = q / (float)NCK - mean * mean;
    float r = rsqrtf(var + 1e-5f);
    #pragma unroll
    for (int n = 0; n < NCK; n++)
        g_hid2[(size_t)(e * NCK + n) * ND + d] = leakyf((vals[n] - mean) * r);
}

__global__ void k_out2(const float* __restrict__ Wow, const float* __restrict__ Wob,
                       float* __restrict__ out) {
    int row = blockIdx.x;
    float p0 = 0.f, p1 = 0.f;
    for (int d = threadIdx.x; d < ND; d += 256) {
        float h = g_hid2[(size_t)row * ND + d];
        p0 += h * Wow[d];
        p1 += h * Wow[ND + d];
    }
    p0 = blockReduceSum(p0);
    p1 = blockReduceSum(p1);
    if (threadIdx.x == 0) {
        float l0 = p0 + Wob[0], l1 = p1 + Wob[1];
        float mx = fmaxf(l0, l1);
        float lse = mx + logf(expf(l0 - mx) + expf(l1 - mx));
        out[row * 2 + 0] = l0 - lse;
        out[row * 2 + 1] = l1 - lse;
        g_extra[row] = (l1 > l0) ? 1.f : 0.f;
    }
}

// delta3 -> bf16 split direct (rows [0,8192), width KP3)
__global__ void k_delta3(const float* __restrict__ dis) {
    int e = blockIdx.y, j = blockIdx.x;
    const float* __restrict__ emo = g_U + (size_t)e * ND;
    const float* __restrict__ y   = g_U + (size_t)(NE + j) * ND;
    float p = 0.f;
    for (int d = threadIdx.x; d < ND; d += 256) {
        float dd = emo[d] - y[d];
        p += dd * dd;
    }
    p = blockReduceSum(p);
    float dist = sqrtf(p);
    float ext = g_extra[e * NCK + (j >> 4)];
    size_t base = (size_t)(e * NCC + j) * KP3;
    for (int f = threadIdx.x; f < KP3; f += 256) {
        float v;
        if (f < ND) v = emo[f];
        else if (f < 2 * ND) v = y[f - ND];
        else if (f == 2 * ND) v = dist;
        else if (f < 3 * ND + 1) v = emo[f - 2 * ND - 1] * y[f - 2 * ND - 1];
        else if (f < 3 * ND + 1 + NP) v = dis[(size_t)(e * NCC + j) * NP + (f - (3 * ND + 1))];
        else if (f < NF3) v = ext;
        else v = 0.f;
        __nv_bfloat16 h = __float2bfloat16_rn(v);
        g_Ahi[base + f] = h;
        g_Alo[base + f] = __float2bfloat16_rn(v - __bfloat162float(h));
    }
}

__global__ void k_bn3() {
    int e = blockIdx.y;
    int d = blockIdx.x * 256 + threadIdx.x;
    float s = 0.f, q = 0.f;
    for (int j = 0; j < NCC; j++) {
        float v = g_h3[(size_t)(e * NCC + j) * ND + d];
        s += v; q += v * v;
    }
    float mean = s / (float)NCC;
    float var = q / (float)NCC - mean * mean;
    float r = rsqrtf(var + 1e-5f);
    for (int j = 0; j < NCC; j++) {
        size_t idx = (size_t)(e * NCC + j) * ND + d;
        g_h3[idx] = leakyf((g_h3[idx] - mean) * r);
    }
}

__global__ void k_cls(const float* __restrict__ clsw, const float* __restrict__ clsb,
                      float* __restrict__ outp) {
    int e = blockIdx.y, j = blockIdx.x;
    int row = e * NCC + j;
    float p0 = 0.f, p1 = 0.f;
    for (int d = threadIdx.x; d < ND; d += 256) {
        float h = g_h3[(size_t)row * ND + d];
        p0 += h * clsw[d];
        p1 += h * clsw[ND + d];
    }
    p0 = blockReduceSum(p0);
    p1 = blockReduceSum(p1);
    if (threadIdx.x == 0) {
        float l0 = p0 + clsb[0], l1 = p1 + clsb[1];
        float mx = fmaxf(l0, l1);
        float lse = mx + logf(expf(l0 - mx) + expf(l1 - mx));
        outp[row * 2 + 0] = l0 - lse;
        outp[row * 2 + 1] = l1 - lse;
    }
}

// ---------------- host launcher ----------------
static inline int cdiv(int a, int b) { return (a + b - 1) / b; }

extern "C" void kernel_launch(void* const* d_in, const int* in_sizes, int n_in,
                              void* d_out, int out_size) {
    const float *word, *pos, *dis, *Wihf, *Whhf, *bihf, *bhhf, *Wihb, *Whhb, *bihb, *bhhb;
    const float *s1w, *s1b, *s2w, *W2w, *W2b, *Wow, *Wob, *W3w, *W3b, *clsw, *clsb;
    const int *lens, *label3;
    if (in_sizes[3] == 256) {
        word = (const float*)d_in[0];  pos = (const float*)d_in[1];  dis = (const float*)d_in[2];
        lens = (const int*)d_in[3];    label3 = (const int*)d_in[4];
        Wihf = (const float*)d_in[7];  Whhf = (const float*)d_in[8];
        bihf = (const float*)d_in[9];  bhhf = (const float*)d_in[10];
        Wihb = (const float*)d_in[11]; Whhb = (const float*)d_in[12];
        bihb = (const float*)d_in[13]; bhhb = (const float*)d_in[14];
        s1w = (const float*)d_in[15];  s1b = (const float*)d_in[16]; s2w = (const float*)d_in[17];
        W2w = (const float*)d_in[18];  W2b = (const float*)d_in[19];
        Wow = (const float*)d_in[20];  Wob = (const float*)d_in[21];
        W3w = (const float*)d_in[22];  W3b = (const float*)d_in[23];
        clsw = (const float*)d_in[24]; clsb = (const float*)d_in[25];
    } else {
        word = (const float*)d_in[0];  pos = (const float*)d_in[1];  dis = (const float*)d_in[2];
        Wihf = (const float*)d_in[3];  Whhf = (const float*)d_in[4];
        bihf = (const float*)d_in[5];  bhhf = (const float*)d_in[6];
        Wihb = (const float*)d_in[7];  Whhb = (const float*)d_in[8];
        bihb = (const float*)d_in[9];  bhhb = (const float*)d_in[10];
        s1w = (const float*)d_in[11];  s1b = (const float*)d_in[12]; s2w = (const float*)d_in[13];
        W2w = (const float*)d_in[14];  W2b = (const float*)d_in[15];
        Wow = (const float*)d_in[16];  Wob = (const float*)d_in[17];
        W3w = (const float*)d_in[18];  W3b = (const float*)d_in[19];
        clsw = (const float*)d_in[20]; clsb = (const float*)d_in[21];
        lens = (const int*)d_in[22];   label3 = (const int*)d_in[23];
    }
    float* out = (float*)d_out;
    float* out_p3 = out + NE * NCK * 2;
    float* out_L  = out_p3 + NE * NCC * 2;

    void *p_xgf, *p_xgb, *p_Hseq, *p_z, *p_rev, *p_bf, *p_bb, *p_h2, *p_h3;
    void *p_Ahi, *p_Alo, *p_Bhi, *p_Blo;
    cudaGetSymbolAddress(&p_xgf, g_xg_f);
    cudaGetSymbolAddress(&p_xgb, g_xg_b);
    cudaGetSymbolAddress(&p_Hseq, g_Hseq);
    cudaGetSymbolAddress(&p_z, g_z);
    cudaGetSymbolAddress(&p_rev, g_rev);
    cudaGetSymbolAddress(&p_bf, g_biasf);
    cudaGetSymbolAddress(&p_bb, g_biasb);
    cudaGetSymbolAddress(&p_h2, g_hid2);
    cudaGetSymbolAddress(&p_h3, g_h3);
    cudaGetSymbolAddress(&p_Ahi, g_Ahi);
    cudaGetSymbolAddress(&p_Alo, g_Alo);
    cudaGetSymbolAddress(&p_Bhi, g_Bhi);
    cudaGetSymbolAddress(&p_Blo, g_Blo);
    __nv_bfloat16* Ahi = (__nv_bfloat16*)p_Ahi;
    __nv_bfloat16* Alo = (__nv_bfloat16*)p_Alo;
    __nv_bfloat16* Bhi = (__nv_bfloat16*)p_Bhi;
    __nv_bfloat16* Blo = (__nv_bfloat16*)p_Blo;

    cudaFuncSetAttribute(k_mgemm, cudaFuncAttributeMaxDynamicSharedMemorySize, MG_SMEM);
    cudaFuncSetAttribute(k_lstm_all, cudaFuncAttributeMaxDynamicSharedMemorySize, LS_SMEM);

    // 1. prep + weight reorder/split
    k_prep<<<1024, 256>>>(bihf, bhhf, bihb, bhhb, lens);
    k_wsplit<<<cdiv(2 * 2048 * 512, 256), 256>>>(Whhf, Whhb);

    // 2. split word + Wih, GEMM xg_f / xg_b
    k_split<<<cdiv(NBT * ND / 4, 256), 256>>>(word, Ahi, Alo, NBT, ND, ND);
    k_split<<<cdiv(NG * ND / 4, 256), 256>>>(Wihf, Bhi, Blo, NG, ND, ND);
    k_mgemm<<<dim3(NG / 128, NBT / 128), 256, MG_SMEM>>>(Ahi, Alo, Bhi, Blo,
        (const float*)p_bf, (float*)p_xgf, NBT, NG, ND, nullptr);
    k_split<<<cdiv(NG * ND / 4, 256), 256>>>(Wihb, Bhi, Blo, NG, ND, ND);
    k_mgemm<<<dim3(NG / 128, NBT / 128), 256, MG_SMEM>>>(Ahi, Alo, Bhi, Blo,
        (const float*)p_bb, (float*)p_xgb, NBT, NG, ND, (const int*)p_rev);

    // 3. persistent bidirectional LSTM
    k_lstm_all<<<LS_CTAS, 256, LS_SMEM>>>(lens);

    // 4. z = Hseq @ s1_w^T + s1_b
    k_split<<<cdiv(ND * ND / 4, 256), 256>>>(s1w, Bhi, Blo, ND, ND, ND);
    k_mgemm<<<dim3(ND / 128, NBT / 128), 256, MG_SMEM>>>(Ahi, Alo, Bhi, Blo,
        s1b, (float*)p_z, NBT, ND, ND, nullptr);

    // 5. BN stats, alpha, U
    k_colstats<<<dim3(ND / 32, 32), dim3(32, 8)>>>();
    k_finalize<<<4, 256>>>();
    k_alpha<<<NBT, 256>>>(s2w);
    k_asum<<<NB, 128>>>(lens);
    k_U<<<dim3(ND / 256, NB), 256>>>(lens);

    // 6. L output
    k_L<<<1, 256>>>(label3, out_L);

    // 7. phase 2 (delta2 writes split directly)
    k_chunk<<<dim3(NCK, NE), 256>>>();
    k_delta2<<<dim3(NCK, NE), 256>>>(pos);
    k_split<<<cdiv(ND * KP2 / 4, 256), 256>>>(W2w, Bhi, Blo, ND, NF2, KP2);
    k_mgemm<<<dim3(ND / 128, (NE * NCK) / 128), 256, MG_SMEM>>>(Ahi, Alo, Bhi, Blo,
        W2b, (float*)p_h2, NE * NCK, ND, KP2, nullptr);
    k_bn2<<<dim3(ND / 256, NE), 256>>>();
    k_out2<<<NE * NCK, 256>>>(Wow, Wob, out);

    // 8. phase 3 (delta3 writes split directly)
    k_delta3<<<dim3(NCC, NE), 256>>>(dis);
    k_split<<<cdiv(ND * KP3 / 4, 256), 256>>>(W3w, Bhi, Blo, ND, NF3, KP3);
    k_mgemm<<<dim3(ND / 128, (NE * NCC) / 128), 256, MG_SMEM>>>(Ahi, Alo, Bhi, Blo,
        W3b, (float*)p_h3, NE * NCC, ND, KP3, nullptr);
    k_bn3<<<dim3(ND / 256, NE), 256>>>();
    k_cls<<<dim3(NCC, NE), 256>>>(clsw, clsb, out_p3);
}

// round 10
// speedup vs baseline: 3.0983x; 1.0242x over previous
#include <cuda_runtime.h>
#include <cuda_bf16.h>
#include <math.h>
#include <stdint.h>

#define NB 256
#define NT 128
#define ND 1024
#define NH 512
#define NG 2048
#define NBT (NB*NT)
#define NE 64
#define NCC 128
#define NCK 8
#define CKS 16
#define NP 50
#define NF2 3123
#define NF3 3173
#define KP2 3136
#define KP3 3200

// ---------------- scratch (device globals) ----------------
__device__ float g_xg_f[(size_t)NBT*NG];
__device__ float g_xg_b[(size_t)NBT*NG];
__device__ float g_Hseq[(size_t)NBT*ND];
__device__ float g_z[(size_t)NBT*ND];
__device__ int   g_rev[NBT];
__device__ float g_biasf[NG];
__device__ float g_biasb[NG];
__device__ float g_colsum[ND];
__device__ float g_colsq[ND];
__device__ float g_mu[ND];
__device__ float g_rs[ND];
__device__ float g_alpha[NBT];
__device__ float g_asum[NB];
__device__ float g_U[NB*ND];
__device__ float g_chunk[NE*NCK*ND];
__device__ float g_hid2[NE*NCK*ND];
__device__ float g_extra[NE*NCK];
__device__ float g_h3[(size_t)NE*NCC*ND];
// bf16 split scratch
__device__ __nv_bfloat16 g_Ahi[(size_t)NBT*ND];
__device__ __nv_bfloat16 g_Alo[(size_t)NBT*ND];
__device__ __nv_bfloat16 g_Bhi[3276800];
__device__ __nv_bfloat16 g_Blo[3276800];
// LSTM: reordered+split recurrent weights, ping-pong h state, barrier
__device__ __nv_bfloat16 g_Wrh[2*2048*512];
__device__ __nv_bfloat16 g_Wrl[2*2048*512];
__device__ __nv_bfloat16 g_hh[2][2*256*512];
__device__ __nv_bfloat16 g_hl[2][2*256*512];
__device__ unsigned g_barcnt;
__device__ unsigned g_bargen;

// ---------------- mma.sync helpers ----------------
__device__ __forceinline__ uint32_t smem_u32(const void* p) {
    uint32_t a;
    asm("{ .reg .u64 t; cvta.to.shared.u64 t, %1; cvt.u32.u64 %0, t; }" : "=r"(a) : "l"(p));
    return a;
}
__device__ __forceinline__ void ldsm4(uint32_t* r, uint32_t a) {
    asm volatile("ldmatrix.sync.aligned.m8n8.x4.shared.b16 {%0,%1,%2,%3}, [%4];"
        : "=r"(r[0]), "=r"(r[1]), "=r"(r[2]), "=r"(r[3]) : "r"(a));
}
__device__ __forceinline__ void mma16816(float* c, const uint32_t* a, uint32_t b0, uint32_t b1) {
    asm volatile("mma.sync.aligned.m16n8k16.row.col.f32.bf16.bf16.f32 "
        "{%0,%1,%2,%3}, {%4,%5,%6,%7}, {%8,%9}, {%0,%1,%2,%3};"
        : "+f"(c[0]), "+f"(c[1]), "+f"(c[2]), "+f"(c[3])
        : "r"(a[0]), "r"(a[1]), "r"(a[2]), "r"(a[3]), "r"(b0), "r"(b1));
}
__device__ __forceinline__ void cpa16(uint32_t d, const void* s) {
    asm volatile("cp.async.cg.shared.global [%0], [%1], 16;" :: "r"(d), "l"(s));
}
#define CP_COMMIT() asm volatile("cp.async.commit_group;" ::: "memory")

// ---------------- helpers ----------------
__device__ __forceinline__ float blockReduceSum(float v) {
    __shared__ float sh[33];
    int lane = threadIdx.x & 31, wid = threadIdx.x >> 5;
    #pragma unroll
    for (int o = 16; o; o >>= 1) v += __shfl_down_sync(0xffffffffu, v, o);
    __syncthreads();
    if (lane == 0) sh[wid] = v;
    __syncthreads();
    float r = 0.f;
    int nw = blockDim.x >> 5;
    if (threadIdx.x < nw) r = sh[threadIdx.x];
    if (wid == 0) {
        #pragma unroll
        for (int o = 16; o; o >>= 1) r += __shfl_down_sync(0xffffffffu, r, o);
        if (lane == 0) sh[32] = r;
    }
    __syncthreads();
    return sh[32];
}
__device__ __forceinline__ float leakyf(float v) { return v >= 0.f ? v : 0.01f * v; }
__device__ __forceinline__ float sigm(float v) { return 1.f / (1.f + expf(-v)); }

// ---------------- prep ----------------
__global__ void k_prep(const float* __restrict__ bihf, const float* __restrict__ bhhf,
                       const float* __restrict__ bihb, const float* __restrict__ bhhb,
                       const int* __restrict__ lens) {
    int i = blockIdx.x * blockDim.x + threadIdx.x;
    if (i < NBT) {
        int b = i / NT, t = i % NT, L = lens[b];
        g_rev[i] = b * NT + (t < L ? L - 1 - t : t);
    }
    if (i < NG) { g_biasf[i] = bihf[i] + bhhf[i]; g_biasb[i] = bihb[i] + bhhb[i]; }
    if (i < ND) { g_colsum[i] = 0.f; g_colsq[i] = 0.f; }
    if (i < 2 * 256 * 512) {
        g_hh[0][i] = __float2bfloat16(0.f);
        g_hl[0][i] = __float2bfloat16(0.f);
    }
    if (i == 0) { g_barcnt = 0; g_bargen = 0; }
}

// ---------------- Whh reorder + hi/lo split (once) ----------------
__global__ void k_wsplit(const float* __restrict__ Wf, const float* __restrict__ Wb) {
    size_t i = (size_t)blockIdx.x * 256 + threadIdx.x;
    if (i >= (size_t)2 * 2048 * 512) return;
    int dir = (int)(i / (2048 * 512));
    size_t rem = i % (2048 * 512);
    int gr = (int)(rem / 512), k = (int)(rem % 512);
    int ty = gr >> 9, u = gr & 511;
    int r = (u >> 5) * 128 + ty * 32 + (u & 31);
    float v = (dir ? Wb : Wf)[(size_t)gr * 512 + k];
    __nv_bfloat16 h = __float2bfloat16_rn(v);
    g_Wrh[((size_t)dir * 2048 + r) * 512 + k] = h;
    g_Wrl[((size_t)dir * 2048 + r) * 512 + k] = __float2bfloat16_rn(v - __bfloat162float(h));
}

// ---------------- fp32 -> (hi,lo) bf16 split, 4 elems/thread ----------------
__global__ void k_split(const float* __restrict__ src, __nv_bfloat16* __restrict__ hi,
                        __nv_bfloat16* __restrict__ lo, int R, int K, int Kp) {
    int i4 = blockIdx.x * 256 + threadIdx.x;
    int total4 = (R * Kp) >> 2;
    if (i4 >= total4) return;
    int base = i4 << 2;
    int r = base / Kp, k0 = base - r * Kp;
    __nv_bfloat16 h4[4], l4[4];
    #pragma unroll
    for (int j = 0; j < 4; j++) {
        int k = k0 + j;
        float v = (k < K) ? src[(size_t)r * K + k] : 0.f;
        __nv_bfloat16 h = __float2bfloat16_rn(v);
        h4[j] = h;
        l4[j] = __float2bfloat16_rn(v - __bfloat162float(h));
    }
    *(uint2*)(hi + base) = *(uint2*)h4;
    *(uint2*)(lo + base) = *(uint2*)l4;
}

// ---------------- mma.sync split-bf16 GEMM (fused 3-pass inner loop) ----------------
#define SROWB 80
#define ARRB (128*SROWB)
#define BUFB (4*ARRB)
#define MG_SMEM (2*BUFB)
__global__ __launch_bounds__(256, 2) void k_mgemm(
    const __nv_bfloat16* __restrict__ Ah, const __nv_bfloat16* __restrict__ Al,
    const __nv_bfloat16* __restrict__ Bh, const __nv_bfloat16* __restrict__ Bl,
    const float* __restrict__ bias, float* __restrict__ C,
    int M, int N, int Kp, const int* __restrict__ gather)
{
    extern __shared__ char smem[];
    uint32_t sb = smem_u32(smem);
    const int tid = threadIdx.x, wid = tid >> 5, lane = tid & 31;
    const int m0 = blockIdx.y * 128, n0 = blockIdx.x * 128;
    const int wm = wid & 3, wn = wid >> 2;

    size_t aoff[2], boff[2];
    uint32_t soff[2];
    #pragma unroll
    for (int s = 0; s < 2; s++) {
        int idx = tid + s * 256;
        int r = idx >> 2, j = idx & 3;
        int ra = gather ? gather[m0 + r] : (m0 + r);
        aoff[s] = (size_t)ra * Kp + j * 8;
        boff[s] = (size_t)(n0 + r) * Kp + j * 8;
        soff[s] = r * SROWB + j * 16;
    }

    float acc[2][8][4];
    #pragma unroll
    for (int i = 0; i < 2; i++)
        #pragma unroll
        for (int j = 0; j < 8; j++)
            #pragma unroll
            for (int k = 0; k < 4; k++) acc[i][j][k] = 0.f;

    const int NC = Kp >> 5;
    {
        uint32_t bb = sb;
        #pragma unroll
        for (int s = 0; s < 2; s++) {
            cpa16(bb + soff[s],            Ah + aoff[s]);
            cpa16(bb + ARRB + soff[s],     Al + aoff[s]);
            cpa16(bb + 2 * ARRB + soff[s], Bh + boff[s]);
            cpa16(bb + 3 * ARRB + soff[s], Bl + boff[s]);
        }
        CP_COMMIT();
    }
    for (int i = 0; i < NC; i++) {
        int buf = i & 1;
        if (i + 1 < NC) {
            int k0 = (i + 1) << 5;
            uint32_t bb = sb + (buf ^ 1) * BUFB;
            #pragma unroll
            for (int s = 0; s < 2; s++) {
                cpa16(bb + soff[s],            Ah + aoff[s] + k0);
                cpa16(bb + ARRB + soff[s],     Al + aoff[s] + k0);
                cpa16(bb + 2 * ARRB + soff[s], Bh + boff[s] + k0);
                cpa16(bb + 3 * ARRB + soff[s], Bl + boff[s] + k0);
            }
            CP_COMMIT();
            asm volatile("cp.async.wait_group 1;" ::: "memory");
        } else {
            asm volatile("cp.async.wait_group 0;" ::: "memory");
        }
        __syncthreads();
        uint32_t bufb = sb + buf * BUFB;
        uint32_t aHB = bufb, aLB = bufb + ARRB, bHB = bufb + 2 * ARRB, bLB = bufb + 3 * ARRB;
        #pragma unroll
        for (int ks = 0; ks < 2; ks++) {
            uint32_t aro = (wm * 32 + (lane & 15)) * SROWB + ks * 32 + ((lane >> 4) << 4);
            uint32_t ah0[4], ah1[4], al0[4], al1[4];
            ldsm4(ah0, aHB + aro);
            ldsm4(ah1, aHB + aro + 16 * SROWB);
            ldsm4(al0, aLB + aro);
            ldsm4(al1, aLB + aro + 16 * SROWB);
            #pragma unroll
            for (int nt = 0; nt < 4; nt++) {
                uint32_t bro = (wn * 64 + nt * 16 + (lane & 15)) * SROWB + ks * 32 + ((lane >> 4) << 4);
                uint32_t bh[4], bl[4];
                ldsm4(bh, bHB + bro);
                ldsm4(bl, bLB + bro);
                mma16816(acc[0][nt * 2],     ah0, bh[0], bh[2]);
                mma16816(acc[0][nt * 2 + 1], ah0, bh[1], bh[3]);
                mma16816(acc[1][nt * 2],     ah1, bh[0], bh[2]);
                mma16816(acc[1][nt * 2 + 1], ah1, bh[1], bh[3]);
                mma16816(acc[0][nt * 2],     al0, bh[0], bh[2]);
                mma16816(acc[0][nt * 2 + 1], al0, bh[1], bh[3]);
                mma16816(acc[1][nt * 2],     al1, bh[0], bh[2]);
                mma16816(acc[1][nt * 2 + 1], al1, bh[1], bh[3]);
                mma16816(acc[0][nt * 2],     ah0, bl[0], bl[2]);
                mma16816(acc[0][nt * 2 + 1], ah0, bl[1], bl[3]);
                mma16816(acc[1][nt * 2],     ah1, bl[0], bl[2]);
                mma16816(acc[1][nt * 2 + 1], ah1, bl[1], bl[3]);
            }
        }
        __syncthreads();
    }
    #pragma unroll
    for (int mt = 0; mt < 2; mt++) {
        int m = m0 + wm * 32 + mt * 16 + (lane >> 2);
        #pragma unroll
        for (int nt = 0; nt < 8; nt++) {
            int n = n0 + wn * 64 + nt * 8 + (lane & 3) * 2;
            float b0 = bias ? bias[n] : 0.f, b1 = bias ? bias[n + 1] : 0.f;
            float2 v0 = make_float2(acc[mt][nt][0] + b0, acc[mt][nt][1] + b1);
            float2 v1 = make_float2(acc[mt][nt][2] + b0, acc[mt][nt][3] + b1);
            *(float2*)&C[(size_t)m * N + n] = v0;
            *(float2*)&C[(size_t)(m + 8) * N + n] = v1;
        }
    }
}

// ---------------- persistent bidirectional LSTM (Wh smem-resident) ----------------
// smem: [0, WH_SZ): persistent Wh tile 128 rows x 512 cols, row stride 1040 B.
//       [WL_OFF, +2*WLB): Wl streaming double buffer (128x64 per chunk, stride 144).
//       [H_OFF,  +2*HB):  h hi/lo streaming double buffer (64x64 each, stride 144).
//       pre[] aliases the h-buffer region after the last chunk's compute.
#define WH_STRIDE 1040
#define WH_SZ (128*WH_STRIDE)
#define WLB (128*144)
#define WL_OFF WH_SZ
#define HB (2*64*144)
#define H_OFF (WH_SZ + 2*WLB)
#define LS_SMEM (H_OFF + 2*HB)
#define PS 132
#define LS_CTAS 128

__device__ __forceinline__ void grid_barrier() {
    __syncthreads();
    if (threadIdx.x == 0) {
        unsigned gen;
        asm volatile("ld.relaxed.gpu.u32 %0, [%1];" : "=r"(gen) : "l"(&g_bargen));
        unsigned t;
        asm volatile("atom.add.release.gpu.u32 %0, [%1], 1;" : "=r"(t) : "l"(&g_barcnt) : "memory");
        if (t == LS_CTAS - 1) {
            asm volatile("st.relaxed.gpu.u32 [%0], %1;" :: "l"(&g_barcnt), "r"(0u) : "memory");
            asm volatile("st.release.gpu.u32 [%0], %1;" :: "l"(&g_bargen), "r"(gen + 1) : "memory");
        } else {
            unsigned g2;
            do {
                asm volatile("ld.acquire.gpu.u32 %0, [%1];" : "=r"(g2) : "l"(&g_bargen) : "memory");
            } while (g2 == gen);
        }
    }
    __syncthreads();
}

__global__ __launch_bounds__(256, 1) void k_lstm_all(const int* __restrict__ lens)
{
    extern __shared__ char sm[];
    uint32_t sb = smem_u32(sm);
    const int tid = threadIdx.x, wid = tid >> 5, lane = tid & 31;
    const int cta = blockIdx.x;
    const int dir = cta >> 6;
    const int ms = (cta & 63) >> 4;
    const int us = cta & 15;
    const int b0 = ms * 64;
    const int wm = wid & 1, wn = wid >> 1;
    const float* __restrict__ xg = dir ? g_xg_b : g_xg_f;
    const __nv_bfloat16* __restrict__ Wh = g_Wrh + ((size_t)dir * 2048 + us * 128) * 512;
    const __nv_bfloat16* __restrict__ Wl = g_Wrl + ((size_t)dir * 2048 + us * 128) * 512;

    // load persistent Wh into smem (128 rows x 512 cols, stride 1040)
    for (int i = tid; i < 8192; i += 256) {
        int r = i >> 6, c = i & 63;
        cpa16(sb + r * WH_STRIDE + c * 16, Wh + (size_t)r * 512 + c * 8);
    }
    CP_COMMIT();
    asm volatile("cp.async.wait_group 0;" ::: "memory");
    __syncthreads();

    float c_st[8], h_st[8];
    int Lb[8];
    #pragma unroll
    for (int r = 0; r < 8; r++) {
        c_st[r] = 0.f; h_st[r] = 0.f;
        Lb[r] = lens[b0 + r * 8 + wid];
    }

    // per-thread cp.async mapping (per chunk of 64 cols)
    // Wl: 128 rows x 4 x 16B -> 4 slots/thread; h hi/lo: 64 rows x 8 x 16B -> 2 slots each
    int wlr[4], wlj[4];
    #pragma unroll
    for (int s = 0; s < 4; s++) {
        int idx = tid + s * 256;
        wlr[s] = idx >> 3; wlj[s] = idx & 7;
    }
    int hr_[2], hj_[2];
    #pragma unroll
    for (int s = 0; s < 2; s++) {
        int idx = tid + s * 256;
        hr_[s] = idx >> 3; hj_[s] = idx & 7;
    }

    const int u_g = us * 32 + lane;

    for (int t = 0; t < NT; t++) {
        const int rbuf = t & 1, wbuf = rbuf ^ 1;
        const __nv_bfloat16* __restrict__ hhp = g_hh[rbuf];
        const __nv_bfloat16* __restrict__ hlp = g_hl[rbuf];

        float acc[2][4][4];
        #pragma unroll
        for (int i = 0; i < 2; i++)
            #pragma unroll
            for (int j = 0; j < 4; j++)
                #pragma unroll
                for (int k = 0; k < 4; k++) acc[i][j][k] = 0.f;

        // prologue: chunk 0 (Wl + h hi/lo)
        {
            uint32_t wlb = sb + WL_OFF;
            uint32_t hbf = sb + H_OFF;
            #pragma unroll
            for (int s = 0; s < 4; s++)
                cpa16(wlb + wlr[s] * 144 + wlj[s] * 16, Wl + (size_t)wlr[s] * 512 + wlj[s] * 8);
            #pragma unroll
            for (int s = 0; s < 2; s++) {
                size_t ho = ((size_t)(dir * 256 + b0 + hr_[s])) * 512 + hj_[s] * 8;
                cpa16(hbf +        hr_[s] * 144 + hj_[s] * 16, hhp + ho);
                cpa16(hbf + 9216 + hr_[s] * 144 + hj_[s] * 16, hlp + ho);
            }
            CP_COMMIT();
        }
        // hoisted gate loads
        float xv[8][4];
        #pragma unroll
        for (int r = 0; r < 8; r++) {
            size_t xrow = ((size_t)(b0 + r * 8 + wid) * NT + t) * NG + u_g;
            xv[r][0] = xg[xrow];
            xv[r][1] = xg[xrow + 512];
            xv[r][2] = xg[xrow + 1024];
            xv[r][3] = xg[xrow + 1536];
        }
        for (int ch = 0; ch < 8; ch++) {
            int buf = ch & 1;
            if (ch + 1 < 8) {
                int k0 = (ch + 1) << 6;
                uint32_t wlb = sb + WL_OFF + (buf ^ 1) * WLB;
                uint32_t hbf = sb + H_OFF + (buf ^ 1) * HB;
                #pragma unroll
                for (int s = 0; s < 4; s++)
                    cpa16(wlb + wlr[s] * 144 + wlj[s] * 16, Wl + (size_t)wlr[s] * 512 + k0 + wlj[s] * 8);
                #pragma unroll
                for (int s = 0; s < 2; s++) {
                    size_t ho = ((size_t)(dir * 256 + b0 + hr_[s])) * 512 + k0 + hj_[s] * 8;
                    cpa16(hbf +        hr_[s] * 144 + hj_[s] * 16, hhp + ho);
                    cpa16(hbf + 9216 + hr_[s] * 144 + hj_[s] * 16, hlp + ho);
                }
                CP_COMMIT();
                asm volatile("cp.async.wait_group 1;" ::: "memory");
            } else {
                asm volatile("cp.async.wait_group 0;" ::: "memory");
            }
            __syncthreads();
            uint32_t hbf = sb + H_OFF + buf * HB;
            uint32_t wlb = sb + WL_OFF + buf * WLB;
            #pragma unroll
            for (int k16 = 0; k16 < 4; k16++) {
                uint32_t aro = (wm * 32 + (lane & 15)) * 144 + k16 * 32 + ((lane >> 4) << 4);
                uint32_t ah0[4], ah1[4], al0[4], al1[4];
                ldsm4(ah0, hbf + aro);
                ldsm4(ah1, hbf + aro + 16 * 144);
                ldsm4(al0, hbf + 9216 + aro);
                ldsm4(al1, hbf + 9216 + aro + 16 * 144);
                uint32_t broW = (wn * 32 + (lane & 15)) * WH_STRIDE + ch * 128 + k16 * 32 + ((lane >> 4) << 4);
                uint32_t brol = (wn * 32 + (lane & 15)) * 144 + k16 * 32 + ((lane >> 4) << 4);
                uint32_t bh0[4], bh1[4], bl0[4], bl1[4];
                ldsm4(bh0, sb + broW);
                ldsm4(bh1, sb + broW + 16 * WH_STRIDE);
                ldsm4(bl0, wlb + brol);
                ldsm4(bl1, wlb + brol + 16 * 144);
                // pass hi*hi: 8 acc groups
                mma16816(acc[0][0], ah0, bh0[0], bh0[2]);
                mma16816(acc[0][1], ah0, bh0[1], bh0[3]);
                mma16816(acc[0][2], ah0, bh1[0], bh1[2]);
                mma16816(acc[0][3], ah0, bh1[1], bh1[3]);
                mma16816(acc[1][0], ah1, bh0[0], bh0[2]);
                mma16816(acc[1][1], ah1, bh0[1], bh0[3]);
                mma16816(acc[1][2], ah1, bh1[0], bh1[2]);
                mma16816(acc[1][3], ah1, bh1[1], bh1[3]);
                // pass lo*hi
                mma16816(acc[0][0], al0, bh0[0], bh0[2]);
                mma16816(acc[0][1], al0, bh0[1], bh0[3]);
                mma16816(acc[0][2], al0, bh1[0], bh1[2]);
                mma16816(acc[0][3], al0, bh1[1], bh1[3]);
                mma16816(acc[1][0], al1, bh0[0], bh0[2]);
                mma16816(acc[1][1], al1, bh0[1], bh0[3]);
                mma16816(acc[1][2], al1, bh1[0], bh1[2]);
                mma16816(acc[1][3], al1, bh1[1], bh1[3]);
                // pass hi*lo
                mma16816(acc[0][0], ah0, bl0[0], bl0[2]);
                mma16816(acc[0][1], ah0, bl0[1], bl0[3]);
                mma16816(acc[0][2], ah0, bl1[0], bl1[2]);
                mma16816(acc[0][3], ah0, bl1[1], bl1[3]);
                mma16816(acc[1][0], ah1, bl0[0], bl0[2]);
                mma16816(acc[1][1], ah1, bl0[1], bl0[3]);
                mma16816(acc[1][2], ah1, bl1[0], bl1[2]);
                mma16816(acc[1][3], ah1, bl1[1], bl1[3]);
            }
            __syncthreads();
        }
        // stage pre-activations to smem (aliases h buffers; safe after last sync)
        float* pre = (float*)(sm + H_OFF);
        #pragma unroll
        for (int mt = 0; mt < 2; mt++) {
            int row = wm * 32 + mt * 16 + (lane >> 2);
            #pragma unroll
            for (int n8 = 0; n8 < 4; n8++) {
                int col = wn * 32 + n8 * 8 + (lane & 3) * 2;
                pre[row * PS + col]           = acc[mt][n8][0];
                pre[row * PS + col + 1]       = acc[mt][n8][1];
                pre[(row + 8) * PS + col]     = acc[mt][n8][2];
                pre[(row + 8) * PS + col + 1] = acc[mt][n8][3];
            }
        }
        __syncthreads();
        #pragma unroll
        for (int r = 0; r < 8; r++) {
            int b_l = r * 8 + wid;
            int bg = b0 + b_l;
            int L = Lb[r];
            bool msk = t < L;
            float pi = pre[b_l * PS +       lane] + xv[r][0];
            float pf = pre[b_l * PS +  32 + lane] + xv[r][1];
            float pg = pre[b_l * PS +  64 + lane] + xv[r][2];
            float po = pre[b_l * PS +  96 + lane] + xv[r][3];
            float ig = sigm(pi), fg = sigm(pf), gv = tanhf(pg), og = sigm(po);
            float cn = fg * c_st[r] + ig * gv;
            float hn = og * tanhf(cn);
            c_st[r] = msk ? cn : c_st[r];
            float hw = msk ? hn : h_st[r];
            h_st[r] = hw;
            size_t hidx = ((size_t)(dir * 256 + bg)) * 512 + u_g;
            __nv_bfloat16 hh = __float2bfloat16_rn(hw);
            g_hh[wbuf][hidx] = hh;
            g_hl[wbuf][hidx] = __float2bfloat16_rn(hw - __bfloat162float(hh));
            int tout = dir ? (msk ? L - 1 - t : t) : t;
            float ho = msk ? hn : 0.f;
            size_t oidx = ((size_t)bg * NT + tout) * ND + dir * 512 + u_g;
            g_Hseq[oidx] = ho;
            __nv_bfloat16 oh = __float2bfloat16_rn(ho);
            g_Ahi[oidx] = oh;
            g_Alo[oidx] = __float2bfloat16_rn(ho - __bfloat162float(oh));
        }
        grid_barrier();
    }
}

// ---------------- BN / attention / phases ----------------
__global__ void k_colstats() {
    int col = blockIdx.x * 32 + threadIdx.x;
    int r0 = blockIdx.y * (NBT / 32);
    float s = 0.f, q = 0.f;
    for (int r = r0 + threadIdx.y; r < r0 + NBT / 32; r += 8) {
        float v = g_z[(size_t)r * ND + col];
        s += v; q += v * v;
    }
    __shared__ float ss[8][33], qq[8][33];
    ss[threadIdx.y][threadIdx.x] = s;
    qq[threadIdx.y][threadIdx.x] = q;
    __syncthreads();
    if (threadIdx.y == 0) {
        #pragma unroll
        for (int k = 1; k < 8; k++) { s += ss[k][threadIdx.x]; q += qq[k][threadIdx.x]; }
        atomicAdd(&g_colsum[col], s);
        atomicAdd(&g_colsq[col], q);
    }
}

__global__ void k_finalize() {
    int d = blockIdx.x * 256 + threadIdx.x;
    if (d < ND) {
        float mean = g_colsum[d] / (float)NBT;
        float var  = g_colsq[d] / (float)NBT - mean * mean;
        g_mu[d] = mean;
        g_rs[d] = rsqrtf(var + 1e-5f);
    }
}

__global__ void k_alpha(const float* __restrict__ s2w) {
    size_t row = blockIdx.x;
    float p = 0.f;
    for (int d = threadIdx.x; d < ND; d += 256) {
        float v = (g_z[row * ND + d] - g_mu[d]) * g_rs[d];
        p += leakyf(v) * s2w[d];
    }
    p = blockReduceSum(p);
    if (threadIdx.x == 0) g_alpha[row] = p;
}

__global__ void k_asum(const int* __restrict__ lens) {
    int b = blockIdx.x;
    int L = lens[b];
    float s = 0.f;
    for (int t = threadIdx.x; t < L; t += 128) s += g_alpha[b * NT + t];
    s = blockReduceSum(s);
    if (threadIdx.x == 0) g_asum[b] = s + 1e-9f;
}

__global__ void k_U(const int* __restrict__ lens) {
    int b = blockIdx.y;
    int d = blockIdx.x * 256 + threadIdx.x;
    int L = lens[b];
    float inv = 1.f / g_asum[b];
    float s = 0.f;
    for (int t = 0; t < L; t++)
        s += g_alpha[b * NT + t] * g_Hseq[((size_t)b * NT + t) * ND + d];
    g_U[(size_t)b * ND + d] = s * inv;
}

__global__ void k_L(const int* __restrict__ label3, float* __restrict__ outL) {
    for (int i = threadIdx.x; i < NE * NCC; i += 256) outL[i] = 0.f;
    __syncthreads();
    if (threadIdx.x < NE) {
        for (int j = 0; j < 3; j++) {
            int v = label3[threadIdx.x * 3 + j];
            if (v >= 0) outL[threadIdx.x * NCC + v] = 1.f;
        }
    }
}

__global__ void k_chunk() {
    int e = blockIdx.y, n = blockIdx.x;
    const float* __restrict__ emo  = g_U + (size_t)e * ND;
    const float* __restrict__ cau0 = g_U + (size_t)(NE + n * CKS) * ND;
    __shared__ float logits[CKS];
    __shared__ float sc[CKS];
    int w = threadIdx.x >> 5, lane = threadIdx.x & 31;
    float a0 = 0.f, a1 = 0.f;
    for (int d = lane; d < ND; d += 32) {
        float ed = emo[d];
        a0 += ed * cau0[(size_t)(2 * w) * ND + d];
        a1 += ed * cau0[(size_t)(2 * w + 1) * ND + d];
    }
    #pragma unroll
    for (int o = 16; o; o >>= 1) {
        a0 += __shfl_down_sync(0xffffffffu, a0, o);
        a1 += __shfl_down_sync(0xffffffffu, a1, o);
    }
    if (lane == 0) { logits[2 * w] = a0; logits[2 * w + 1] = a1; }
    __syncthreads();
    if (threadIdx.x == 0) {
        float mx = logits[0];
        for (int c = 1; c < CKS; c++) mx = fmaxf(mx, logits[c]);
        float s = 0.f;
        for (int c = 0; c < CKS; c++) { sc[c] = expf(logits[c] - mx); s += sc[c]; }
        float si = 1.f / s;
        for (int c = 0; c < CKS; c++) sc[c] *= si;
    }
    __syncthreads();
    for (int d = threadIdx.x; d < ND; d += 256) {
        float v = 0.f;
        #pragma unroll
        for (int c = 0; c < CKS; c++) v += sc[c] * cau0[(size_t)c * ND + d];
        g_chunk[(size_t)(e * NCK + n) * ND + d] = v;
    }
}

// delta2 -> bf16 split direct (rows [0,512), width KP2)
__global__ void k_delta2(const float* __restrict__ pos) {
    int e = blockIdx.y, n = blockIdx.x;
    int row = e * NCK + n;
    const float* __restrict__ emo = g_U + (size_t)e * ND;
    const float* __restrict__ ch  = g_chunk + (size_t)row * ND;
    float p = 0.f;
    for (int d = threadIdx.x; d < ND; d += 256) {
        float dd = emo[d] - ch[d];
        p += dd * dd;
    }
    p = blockReduceSum(p);
    float dist = sqrtf(p);
    size_t base = (size_t)row * KP2;
    for (int f = threadIdx.x; f < KP2; f += 256) {
        float v;
        if (f < ND) v = emo[f];
        else if (f < 2 * ND) v = ch[f - ND];
        else if (f == 2 * ND) v = dist;
        else if (f < 3 * ND + 1) v = emo[f - 2 * ND - 1] * ch[f - 2 * ND - 1];
        else if (f < NF2) v = pos[(size_t)row * NP + (f - (3 * ND + 1))];
        else v = 0.f;
        __nv_bfloat16 h = __float2bfloat16_rn(v);
        g_Ahi[base + f] = h;
        g_Alo[base + f] = __float2bfloat16_rn(v - __bfloat162float(h));
    }
}

__global__ void k_bn2() {
    int e = blockIdx.y;
    int d = blockIdx.x * 256 + threadIdx.x;
    float vals[NCK];
    float s = 0.f, q = 0.f;
    #pragma unroll
    for (int n = 0; n < NCK; n++) {
        float v = g_hid2[(size_t)(e * NCK + n) * ND + d];
        vals[n] = v; s += v; q += v * v;
    }
    float mean = s / (float)NCK;
    float var = q / (float)NCK - mean * mean;
    float r = rsqrtf(var + 1e-5f);
    #pragma unroll
    for (int n = 0; n < NCK; n++)
        g_hid2[(size_t)(e * NCK + n) * ND + d] = leakyf((vals[n] - mean) * r);
}

__global__ void k_out2(const float* __restrict__ Wow, const float* __restrict__ Wob,
                       float* __restrict__ out) {
    int row = blockIdx.x;
    float p0 = 0.f, p1 = 0.f;
    for (int d = threadIdx.x; d < ND; d += 256) {
        float h = g_hid2[(size_t)row * ND + d];
        p0 += h * Wow[d];
        p1 += h * Wow[ND + d];
    }
    p0 = blockReduceSum(p0);
    p1 = blockReduceSum(p1);
    if (threadIdx.x == 0) {
        float l0 = p0 + Wob[0], l1 = p1 + Wob[1];
        float mx = fmaxf(l0, l1);
        float lse = mx + logf(expf(l0 - mx) + expf(l1 - mx));
        out[row * 2 + 0] = l0 - lse;
        out[row * 2 + 1] = l1 - lse;
        g_extra[row] = (l1 > l0) ? 1.f : 0.f;
    }
}

// delta3 -> bf16 split direct (rows [0,8192), width KP3)
__global__ void k_delta3(const float* __restrict__ dis) {
    int e = blockIdx.y, j = blockIdx.x;
    const float* __restrict__ emo = g_U + (size_t)e * ND;
    const float* __restrict__ y   = g_U + (size_t)(NE + j) * ND;
    float p = 0.f;
    for (int d = threadIdx.x; d < ND; d += 256) {
        float dd = emo[d] - y[d];
        p += dd * dd;
    }
    p = blockReduceSum(p);
    float dist = sqrtf(p);
    float ext = g_extra[e * NCK + (j >> 4)];
    size_t base = (size_t)(e * NCC + j) * KP3;
    for (int f = threadIdx.x; f < KP3; f += 256) {
        float v;
        if (f < ND) v = emo[f];
        else if (f < 2 * ND) v = y[f - ND];
        else if (f == 2 * ND) v = dist;
        else if (f < 3 * ND + 1) v = emo[f - 2 * ND - 1] * y[f - 2 * ND - 1];
        else if (f < 3 * ND + 1 + NP) v = dis[(size_t)(e * NCC + j) * NP + (f - (3 * ND + 1))];
        else if (f < NF3) v = ext;
        else v = 0.f;
        __nv_bfloat16 h = __float2bfloat16_rn(v);
        g_Ahi[base + f] = h;
        g_Alo[base + f] = __float2bfloat16_rn(v - __bfloat162float(h));
    }
}

__global__ void k_bn3() {
    int e = blockIdx.y;
    int d = blockIdx.x * 256 + threadIdx.x;
    float s = 0.f, q = 0.f;
    for (int j = 0; j < NCC; j++) {
        float v = g_h3[(size_t)(e * NCC + j) * ND + d];
        s += v; q += v * v;
    }
    float mean = s / (float)NCC;
    float var = q / (float)NCC - mean * mean;
    float r = rsqrtf(var + 1e-5f);
    for (int j = 0; j < NCC; j++) {
        size_t idx = (size_t)(e * NCC + j) * ND + d;
        g_h3[idx] = leakyf((g_h3[idx] - mean) * r);
    }
}

__global__ void k_cls(const float* __restrict__ clsw, const float* __restrict__ clsb,
                      float* __restrict__ outp) {
    int e = blockIdx.y, j = blockIdx.x;
    int row = e * NCC + j;
    float p0 = 0.f, p1 = 0.f;
    for (int d = threadIdx.x; d < ND; d += 256) {
        float h = g_h3[(size_t)row * ND + d];
        p0 += h * clsw[d];
        p1 += h * clsw[ND + d];
    }
    p0 = blockReduceSum(p0);
    p1 = blockReduceSum(p1);
    if (threadIdx.x == 0) {
        float l0 = p0 + clsb[0], l1 = p1 + clsb[1];
        float mx = fmaxf(l0, l1);
        float lse = mx + logf(expf(l0 - mx) + expf(l1 - mx));
        outp[row * 2 + 0] = l0 - lse;
        outp[row * 2 + 1] = l1 - lse;
    }
}

// ---------------- host launcher ----------------
static inline int cdiv(int a, int b) { return (a + b - 1) / b; }

extern "C" void kernel_launch(void* const* d_in, const int* in_sizes, int n_in,
                              void* d_out, int out_size) {
    const float *word, *pos, *dis, *Wihf, *Whhf, *bihf, *bhhf, *Wihb, *Whhb, *bihb, *bhhb;
    const float *s1w, *s1b, *s2w, *W2w, *W2b, *Wow, *Wob, *W3w, *W3b, *clsw, *clsb;
    const int *lens, *label3;
    if (in_sizes[3] == 256) {
        word = (const float*)d_in[0];  pos = (const float*)d_in[1];  dis = (const float*)d_in[2];
        lens = (const int*)d_in[3];    label3 = (const int*)d_in[4];
        Wihf = (const float*)d_in[7];  Whhf = (const float*)d_in[8];
        bihf = (const float*)d_in[9];  bhhf = (const float*)d_in[10];
        Wihb = (const float*)d_in[11]; Whhb = (const float*)d_in[12];
        bihb = (const float*)d_in[13]; bhhb = (const float*)d_in[14];
        s1w = (const float*)d_in[15];  s1b = (const float*)d_in[16]; s2w = (const float*)d_in[17];
        W2w = (const float*)d_in[18];  W2b = (const float*)d_in[19];
        Wow = (const float*)d_in[20];  Wob = (const float*)d_in[21];
        W3w = (const float*)d_in[22];  W3b = (const float*)d_in[23];
        clsw = (const float*)d_in[24]; clsb = (const float*)d_in[25];
    } else {
        word = (const float*)d_in[0];  pos = (const float*)d_in[1];  dis = (const float*)d_in[2];
        Wihf = (const float*)d_in[3];  Whhf = (const float*)d_in[4];
        bihf = (const float*)d_in[5];  bhhf = (const float*)d_in[6];
        Wihb = (const float*)d_in[7];  Whhb = (const float*)d_in[8];
        bihb = (const float*)d_in[9];  bhhb = (const float*)d_in[10];
        s1w = (const float*)d_in[11];  s1b = (const float*)d_in[12]; s2w = (const float*)d_in[13];
        W2w = (const float*)d_in[14];  W2b = (const float*)d_in[15];
        Wow = (const float*)d_in[16];  Wob = (const float*)d_in[17];
        W3w = (const float*)d_in[18];  W3b = (const float*)d_in[19];
        clsw = (const float*)d_in[20]; clsb = (const float*)d_in[21];
        lens = (const int*)d_in[22];   label3 = (const int*)d_in[23];
    }
    float* out = (float*)d_out;
    float* out_p3 = out + NE * NCK * 2;
    float* out_L  = out_p3 + NE * NCC * 2;

    void *p_xgf, *p_xgb, *p_Hseq, *p_z, *p_rev, *p_bf, *p_bb, *p_h2, *p_h3;
    void *p_Ahi, *p_Alo, *p_Bhi, *p_Blo;
    cudaGetSymbolAddress(&p_xgf, g_xg_f);
    cudaGetSymbolAddress(&p_xgb, g_xg_b);
    cudaGetSymbolAddress(&p_Hseq, g_Hseq);
    cudaGetSymbolAddress(&p_z, g_z);
    cudaGetSymbolAddress(&p_rev, g_rev);
    cudaGetSymbolAddress(&p_bf, g_biasf);
    cudaGetSymbolAddress(&p_bb, g_biasb);
    cudaGetSymbolAddress(&p_h2, g_hid2);
    cudaGetSymbolAddress(&p_h3, g_h3);
    cudaGetSymbolAddress(&p_Ahi, g_Ahi);
    cudaGetSymbolAddress(&p_Alo, g_Alo);
    cudaGetSymbolAddress(&p_Bhi, g_Bhi);
    cudaGetSymbolAddress(&p_Blo, g_Blo);
    __nv_bfloat16* Ahi = (__nv_bfloat16*)p_Ahi;
    __nv_bfloat16* Alo = (__nv_bfloat16*)p_Alo;
    __nv_bfloat16* Bhi = (__nv_bfloat16*)p_Bhi;
    __nv_bfloat16* Blo = (__nv_bfloat16*)p_Blo;

    cudaFuncSetAttribute(k_mgemm, cudaFuncAttributeMaxDynamicSharedMemorySize, MG_SMEM);
    cudaFuncSetAttribute(k_lstm_all, cudaFuncAttributeMaxDynamicSharedMemorySize, LS_SMEM);

    // 1. prep + weight reorder/split
    k_prep<<<1024, 256>>>(bihf, bhhf, bihb, bhhb, lens);
    k_wsplit<<<cdiv(2 * 2048 * 512, 256), 256>>>(Whhf, Whhb);

    // 2. split word + Wih, GEMM xg_f / xg_b
    k_split<<<cdiv(NBT * ND / 4, 256), 256>>>(word, Ahi, Alo, NBT, ND, ND);
    k_split<<<cdiv(NG * ND / 4, 256), 256>>>(Wihf, Bhi, Blo, NG, ND, ND);
    k_mgemm<<<dim3(NG / 128, NBT / 128), 256, MG_SMEM>>>(Ahi, Alo, Bhi, Blo,
        (const float*)p_bf, (float*)p_xgf, NBT, NG, ND, nullptr);
    k_split<<<cdiv(NG * ND / 4, 256), 256>>>(Wihb, Bhi, Blo, NG, ND, ND);
    k_mgemm<<<dim3(NG / 128, NBT / 128), 256, MG_SMEM>>>(Ahi, Alo, Bhi, Blo,
        (const float*)p_bb, (float*)p_xgb, NBT, NG, ND, (const int*)p_rev);

    // 3. persistent bidirectional LSTM (Wh smem-resident)
    k_lstm_all<<<LS_CTAS, 256, LS_SMEM>>>(lens);

    // 4. z = Hseq @ s1_w^T + s1_b
    k_split<<<cdiv(ND * ND / 4, 256), 256>>>(s1w, Bhi, Blo, ND, ND, ND);
    k_mgemm<<<dim3(ND / 128, NBT / 128), 256, MG_SMEM>>>(Ahi, Alo, Bhi, Blo,
        s1b, (float*)p_z, NBT, ND, ND, nullptr);

    // 5. BN stats, alpha, U
    k_colstats<<<dim3(ND / 32, 32), dim3(32, 8)>>>();
    k_finalize<<<4, 256>>>();
    k_alpha<<<NBT, 256>>>(s2w);
    k_asum<<<NB, 128>>>(lens);
    k_U<<<dim3(ND / 256, NB), 256>>>(lens);

    // 6. L output
    k_L<<<1, 256>>>(label3, out_L);

    // 7. phase 2 (delta2 writes split directly)
    k_chunk<<<dim3(NCK, NE), 256>>>();
    k_delta2<<<dim3(NCK, NE), 256>>>(pos);
    k_split<<<cdiv(ND * KP2 / 4, 256), 256>>>(W2w, Bhi, Blo, ND, NF2, KP2);
    k_mgemm<<<dim3(ND / 128, (NE * NCK) / 128), 256, MG_SMEM>>>(Ahi, Alo, Bhi, Blo,
        W2b, (float*)p_h2, NE * NCK, ND, KP2, nullptr);
    k_bn2<<<dim3(ND / 256, NE), 256>>>();
    k_out2<<<NE * NCK, 256>>>(Wow, Wob, out);

    // 8. phase 3 (delta3 writes split directly)
    k_delta3<<<dim3(NCC, NE), 256>>>(dis);
    k_split<<<cdiv(ND * KP3 / 4, 256), 256>>>(W3w, Bhi, Blo, ND, NF3, KP3);
    k_mgemm<<<dim3(ND / 128, (NE * NCC) / 128), 256, MG_SMEM>>>(Ahi, Alo, Bhi, Blo,
        W3b, (float*)p_h3, NE * NCC, ND, KP3, nullptr);
    k_bn3<<<dim3(ND / 256, NE), 256>>>();
    k_cls<<<dim3(NCC, NE), 256>>>(clsw, clsb, out_p3);
}

// round 11
// speedup vs baseline: 3.1054x; 1.0023x over previous
#include <cuda_runtime.h>
#include <cuda_bf16.h>
#include <math.h>
#include <stdint.h>

#define NB 256
#define NT 128
#define ND 1024
#define NH 512
#define NG 2048
#define NBT (NB*NT)
#define NE 64
#define NCC 128
#define NCK 8
#define CKS 16
#define NP 50
#define NF2 3123
#define NF3 3173
#define KP2 3136
#define KP3 3200

// ---------------- scratch (device globals) ----------------
__device__ float g_xg_f[(size_t)NBT*NG];
__device__ float g_xg_b[(size_t)NBT*NG];
__device__ float g_z[(size_t)NBT*ND];
__device__ int   g_rev[NBT];
__device__ float g_biasf[NG];
__device__ float g_biasb[NG];
__device__ float g_colsum[ND];
__device__ float g_colsq[ND];
__device__ float g_mu[ND];
__device__ float g_rs[ND];
__device__ float g_alpha[NBT];
__device__ float g_asum[NB];
__device__ float g_U[NB*ND];
__device__ float g_chunk[NE*NCK*ND];
__device__ float g_hid2[NE*NCK*ND];
__device__ float g_extra[NE*NCK];
__device__ float g_h3[(size_t)NE*NCC*ND];
// bf16 split scratch (Ahi/Alo also serve as the bf16 Hseq)
__device__ __nv_bfloat16 g_Ahi[(size_t)NBT*ND];
__device__ __nv_bfloat16 g_Alo[(size_t)NBT*ND];
__device__ __nv_bfloat16 g_Bhi[3276800];
__device__ __nv_bfloat16 g_Blo[3276800];
// LSTM: reordered+split recurrent weights, ping-pong h state, group barriers
__device__ __nv_bfloat16 g_Wrh[2*2048*512];
__device__ __nv_bfloat16 g_Wrl[2*2048*512];
__device__ __nv_bfloat16 g_hh[2][2*256*512];
__device__ __nv_bfloat16 g_hl[2][2*256*512];
__device__ unsigned g_barcnt8[8];
__device__ unsigned g_bargen8[8];

// ---------------- mma.sync helpers ----------------
__device__ __forceinline__ uint32_t smem_u32(const void* p) {
    uint32_t a;
    asm("{ .reg .u64 t; cvta.to.shared.u64 t, %1; cvt.u32.u64 %0, t; }" : "=r"(a) : "l"(p));
    return a;
}
__device__ __forceinline__ void ldsm4(uint32_t* r, uint32_t a) {
    asm volatile("ldmatrix.sync.aligned.m8n8.x4.shared.b16 {%0,%1,%2,%3}, [%4];"
        : "=r"(r[0]), "=r"(r[1]), "=r"(r[2]), "=r"(r[3]) : "r"(a));
}
__device__ __forceinline__ void mma16816(float* c, const uint32_t* a, uint32_t b0, uint32_t b1) {
    asm volatile("mma.sync.aligned.m16n8k16.row.col.f32.bf16.bf16.f32 "
        "{%0,%1,%2,%3}, {%4,%5,%6,%7}, {%8,%9}, {%0,%1,%2,%3};"
        : "+f"(c[0]), "+f"(c[1]), "+f"(c[2]), "+f"(c[3])
        : "r"(a[0]), "r"(a[1]), "r"(a[2]), "r"(a[3]), "r"(b0), "r"(b1));
}
__device__ __forceinline__ void cpa16(uint32_t d, const void* s) {
    asm volatile("cp.async.cg.shared.global [%0], [%1], 16;" :: "r"(d), "l"(s));
}
#define CP_COMMIT() asm volatile("cp.async.commit_group;" ::: "memory")

// ---------------- helpers ----------------
__device__ __forceinline__ float blockReduceSum(float v) {
    __shared__ float sh[33];
    int lane = threadIdx.x & 31, wid = threadIdx.x >> 5;
    #pragma unroll
    for (int o = 16; o; o >>= 1) v += __shfl_down_sync(0xffffffffu, v, o);
    __syncthreads();
    if (lane == 0) sh[wid] = v;
    __syncthreads();
    float r = 0.f;
    int nw = blockDim.x >> 5;
    if (threadIdx.x < nw) r = sh[threadIdx.x];
    if (wid == 0) {
        #pragma unroll
        for (int o = 16; o; o >>= 1) r += __shfl_down_sync(0xffffffffu, r, o);
        if (lane == 0) sh[32] = r;
    }
    __syncthreads();
    return sh[32];
}
__device__ __forceinline__ float leakyf(float v) { return v >= 0.f ? v : 0.01f * v; }
__device__ __forceinline__ float sigm(float v) { return 1.f / (1.f + expf(-v)); }

// ---------------- prep ----------------
__global__ void k_prep(const float* __restrict__ bihf, const float* __restrict__ bhhf,
                       const float* __restrict__ bihb, const float* __restrict__ bhhb,
                       const int* __restrict__ lens) {
    int i = blockIdx.x * blockDim.x + threadIdx.x;
    if (i < NBT) {
        int b = i / NT, t = i % NT, L = lens[b];
        g_rev[i] = b * NT + (t < L ? L - 1 - t : t);
    }
    if (i < NG) { g_biasf[i] = bihf[i] + bhhf[i]; g_biasb[i] = bihb[i] + bhhb[i]; }
    if (i < ND) { g_colsum[i] = 0.f; g_colsq[i] = 0.f; }
    if (i < 2 * 256 * 512) {
        g_hh[0][i] = __float2bfloat16(0.f);
        g_hl[0][i] = __float2bfloat16(0.f);
    }
    if (i < 8) { g_barcnt8[i] = 0; g_bargen8[i] = 0; }
}

// ---------------- Whh reorder + hi/lo split (once) ----------------
__global__ void k_wsplit(const float* __restrict__ Wf, const float* __restrict__ Wb) {
    size_t i = (size_t)blockIdx.x * 256 + threadIdx.x;
    if (i >= (size_t)2 * 2048 * 512) return;
    int dir = (int)(i / (2048 * 512));
    size_t rem = i % (2048 * 512);
    int gr = (int)(rem / 512), k = (int)(rem % 512);
    int ty = gr >> 9, u = gr & 511;
    int r = (u >> 5) * 128 + ty * 32 + (u & 31);
    float v = (dir ? Wb : Wf)[(size_t)gr * 512 + k];
    __nv_bfloat16 h = __float2bfloat16_rn(v);
    g_Wrh[((size_t)dir * 2048 + r) * 512 + k] = h;
    g_Wrl[((size_t)dir * 2048 + r) * 512 + k] = __float2bfloat16_rn(v - __bfloat162float(h));
}

// ---------------- fp32 -> (hi,lo) bf16 split, 4 elems/thread ----------------
__global__ void k_split(const float* __restrict__ src, __nv_bfloat16* __restrict__ hi,
                        __nv_bfloat16* __restrict__ lo, int R, int K, int Kp) {
    int i4 = blockIdx.x * 256 + threadIdx.x;
    int total4 = (R * Kp) >> 2;
    if (i4 >= total4) return;
    int base = i4 << 2;
    int r = base / Kp, k0 = base - r * Kp;
    __nv_bfloat16 h4[4], l4[4];
    #pragma unroll
    for (int j = 0; j < 4; j++) {
        int k = k0 + j;
        float v = (k < K) ? src[(size_t)r * K + k] : 0.f;
        __nv_bfloat16 h = __float2bfloat16_rn(v);
        h4[j] = h;
        l4[j] = __float2bfloat16_rn(v - __bfloat162float(h));
    }
    *(uint2*)(hi + base) = *(uint2*)h4;
    *(uint2*)(lo + base) = *(uint2*)l4;
}

// ---------------- mma.sync split-bf16 GEMM (fused 3-pass inner loop) ----------------
#define SROWB 80
#define ARRB (128*SROWB)
#define BUFB (4*ARRB)
#define MG_SMEM (2*BUFB)
__global__ __launch_bounds__(256, 2) void k_mgemm(
    const __nv_bfloat16* __restrict__ Ah, const __nv_bfloat16* __restrict__ Al,
    const __nv_bfloat16* __restrict__ Bh, const __nv_bfloat16* __restrict__ Bl,
    const float* __restrict__ bias, float* __restrict__ C,
    int M, int N, int Kp, const int* __restrict__ gather)
{
    extern __shared__ char smem[];
    uint32_t sb = smem_u32(smem);
    const int tid = threadIdx.x, wid = tid >> 5, lane = tid & 31;
    const int m0 = blockIdx.y * 128, n0 = blockIdx.x * 128;
    const int wm = wid & 3, wn = wid >> 2;

    size_t aoff[2], boff[2];
    uint32_t soff[2];
    #pragma unroll
    for (int s = 0; s < 2; s++) {
        int idx = tid + s * 256;
        int r = idx >> 2, j = idx & 3;
        int ra = gather ? gather[m0 + r] : (m0 + r);
        aoff[s] = (size_t)ra * Kp + j * 8;
        boff[s] = (size_t)(n0 + r) * Kp + j * 8;
        soff[s] = r * SROWB + j * 16;
    }

    float acc[2][8][4];
    #pragma unroll
    for (int i = 0; i < 2; i++)
        #pragma unroll
        for (int j = 0; j < 8; j++)
            #pragma unroll
            for (int k = 0; k < 4; k++) acc[i][j][k] = 0.f;

    const int NC = Kp >> 5;
    {
        uint32_t bb = sb;
        #pragma unroll
        for (int s = 0; s < 2; s++) {
            cpa16(bb + soff[s],            Ah + aoff[s]);
            cpa16(bb + ARRB + soff[s],     Al + aoff[s]);
            cpa16(bb + 2 * ARRB + soff[s], Bh + boff[s]);
            cpa16(bb + 3 * ARRB + soff[s], Bl + boff[s]);
        }
        CP_COMMIT();
    }
    for (int i = 0; i < NC; i++) {
        int buf = i & 1;
        if (i + 1 < NC) {
            int k0 = (i + 1) << 5;
            uint32_t bb = sb + (buf ^ 1) * BUFB;
            #pragma unroll
            for (int s = 0; s < 2; s++) {
                cpa16(bb + soff[s],            Ah + aoff[s] + k0);
                cpa16(bb + ARRB + soff[s],     Al + aoff[s] + k0);
                cpa16(bb + 2 * ARRB + soff[s], Bh + boff[s] + k0);
                cpa16(bb + 3 * ARRB + soff[s], Bl + boff[s] + k0);
            }
            CP_COMMIT();
            asm volatile("cp.async.wait_group 1;" ::: "memory");
        } else {
            asm volatile("cp.async.wait_group 0;" ::: "memory");
        }
        __syncthreads();
        uint32_t bufb = sb + buf * BUFB;
        uint32_t aHB = bufb, aLB = bufb + ARRB, bHB = bufb + 2 * ARRB, bLB = bufb + 3 * ARRB;
        #pragma unroll
        for (int ks = 0; ks < 2; ks++) {
            uint32_t aro = (wm * 32 + (lane & 15)) * SROWB + ks * 32 + ((lane >> 4) << 4);
            uint32_t ah0[4], ah1[4], al0[4], al1[4];
            ldsm4(ah0, aHB + aro);
            ldsm4(ah1, aHB + aro + 16 * SROWB);
            ldsm4(al0, aLB + aro);
            ldsm4(al1, aLB + aro + 16 * SROWB);
            #pragma unroll
            for (int nt = 0; nt < 4; nt++) {
                uint32_t bro = (wn * 64 + nt * 16 + (lane & 15)) * SROWB + ks * 32 + ((lane >> 4) << 4);
                uint32_t bh[4], bl[4];
                ldsm4(bh, bHB + bro);
                ldsm4(bl, bLB + bro);
                mma16816(acc[0][nt * 2],     ah0, bh[0], bh[2]);
                mma16816(acc[0][nt * 2 + 1], ah0, bh[1], bh[3]);
                mma16816(acc[1][nt * 2],     ah1, bh[0], bh[2]);
                mma16816(acc[1][nt * 2 + 1], ah1, bh[1], bh[3]);
                mma16816(acc[0][nt * 2],     al0, bh[0], bh[2]);
                mma16816(acc[0][nt * 2 + 1], al0, bh[1], bh[3]);
                mma16816(acc[1][nt * 2],     al1, bh[0], bh[2]);
                mma16816(acc[1][nt * 2 + 1], al1, bh[1], bh[3]);
                mma16816(acc[0][nt * 2],     ah0, bl[0], bl[2]);
                mma16816(acc[0][nt * 2 + 1], ah0, bl[1], bl[3]);
                mma16816(acc[1][nt * 2],     ah1, bl[0], bl[2]);
                mma16816(acc[1][nt * 2 + 1], ah1, bl[1], bl[3]);
            }
        }
        __syncthreads();
    }
    #pragma unroll
    for (int mt = 0; mt < 2; mt++) {
        int m = m0 + wm * 32 + mt * 16 + (lane >> 2);
        #pragma unroll
        for (int nt = 0; nt < 8; nt++) {
            int n = n0 + wn * 64 + nt * 8 + (lane & 3) * 2;
            float b0 = bias ? bias[n] : 0.f, b1 = bias ? bias[n + 1] : 0.f;
            float2 v0 = make_float2(acc[mt][nt][0] + b0, acc[mt][nt][1] + b1);
            float2 v1 = make_float2(acc[mt][nt][2] + b0, acc[mt][nt][3] + b1);
            *(float2*)&C[(size_t)m * N + n] = v0;
            *(float2*)&C[(size_t)(m + 8) * N + n] = v1;
        }
    }
}

// ---------------- persistent bidirectional LSTM (Wh smem-resident, group barriers) ----------------
#define WH_STRIDE 1040
#define WH_SZ (128*WH_STRIDE)
#define WLB (128*144)
#define WL_OFF WH_SZ
#define HB (2*64*144)
#define H_OFF (WH_SZ + 2*WLB)
#define LS_SMEM (H_OFF + 2*HB)
#define PS 132
#define LS_CTAS 128
#define LS_GRP 16

// barrier over the 16 CTAs of group g = (dir, ms); only they exchange h state.
__device__ __forceinline__ void group_barrier(int g) {
    __syncthreads();
    if (threadIdx.x == 0) {
        unsigned* cnt = &g_barcnt8[g];
        unsigned* gnp = &g_bargen8[g];
        unsigned gen;
        asm volatile("ld.relaxed.gpu.u32 %0, [%1];" : "=r"(gen) : "l"(gnp));
        unsigned t;
        asm volatile("atom.add.release.gpu.u32 %0, [%1], 1;" : "=r"(t) : "l"(cnt) : "memory");
        if (t == LS_GRP - 1) {
            asm volatile("st.relaxed.gpu.u32 [%0], %1;" :: "l"(cnt), "r"(0u) : "memory");
            asm volatile("st.release.gpu.u32 [%0], %1;" :: "l"(gnp), "r"(gen + 1) : "memory");
        } else {
            unsigned g2;
            do {
                asm volatile("ld.acquire.gpu.u32 %0, [%1];" : "=r"(g2) : "l"(gnp) : "memory");
            } while (g2 == gen);
        }
    }
    __syncthreads();
}

__global__ __launch_bounds__(256, 1) void k_lstm_all(const int* __restrict__ lens)
{
    extern __shared__ char sm[];
    uint32_t sb = smem_u32(sm);
    const int tid = threadIdx.x, wid = tid >> 5, lane = tid & 31;
    const int cta = blockIdx.x;
    const int dir = cta >> 6;
    const int ms = (cta & 63) >> 4;
    const int us = cta & 15;
    const int grp = cta >> 4;          // (dir, ms) group of 16 CTAs
    const int b0 = ms * 64;
    const int wm = wid & 1, wn = wid >> 1;
    const float* __restrict__ xg = dir ? g_xg_b : g_xg_f;
    const __nv_bfloat16* __restrict__ Wh = g_Wrh + ((size_t)dir * 2048 + us * 128) * 512;
    const __nv_bfloat16* __restrict__ Wl = g_Wrl + ((size_t)dir * 2048 + us * 128) * 512;

    // load persistent Wh into smem
    for (int i = tid; i < 8192; i += 256) {
        int r = i >> 6, c = i & 63;
        cpa16(sb + r * WH_STRIDE + c * 16, Wh + (size_t)r * 512 + c * 8);
    }
    CP_COMMIT();
    asm volatile("cp.async.wait_group 0;" ::: "memory");
    __syncthreads();

    float c_st[8], h_st[8];
    int Lb[8];
    #pragma unroll
    for (int r = 0; r < 8; r++) {
        c_st[r] = 0.f; h_st[r] = 0.f;
        Lb[r] = lens[b0 + r * 8 + wid];
    }

    int wlr[4], wlj[4];
    #pragma unroll
    for (int s = 0; s < 4; s++) {
        int idx = tid + s * 256;
        wlr[s] = idx >> 3; wlj[s] = idx & 7;
    }
    int hr_[2], hj_[2];
    #pragma unroll
    for (int s = 0; s < 2; s++) {
        int idx = tid + s * 256;
        hr_[s] = idx >> 3; hj_[s] = idx & 7;
    }

    const int u_g = us * 32 + lane;

    for (int t = 0; t < NT; t++) {
        const int rbuf = t & 1, wbuf = rbuf ^ 1;
        const __nv_bfloat16* __restrict__ hhp = g_hh[rbuf];
        const __nv_bfloat16* __restrict__ hlp = g_hl[rbuf];

        float acc[2][4][4];
        #pragma unroll
        for (int i = 0; i < 2; i++)
            #pragma unroll
            for (int j = 0; j < 4; j++)
                #pragma unroll
                for (int k = 0; k < 4; k++) acc[i][j][k] = 0.f;

        {
            uint32_t wlb = sb + WL_OFF;
            uint32_t hbf = sb + H_OFF;
            #pragma unroll
            for (int s = 0; s < 4; s++)
                cpa16(wlb + wlr[s] * 144 + wlj[s] * 16, Wl + (size_t)wlr[s] * 512 + wlj[s] * 8);
            #pragma unroll
            for (int s = 0; s < 2; s++) {
                size_t ho = ((size_t)(dir * 256 + b0 + hr_[s])) * 512 + hj_[s] * 8;
                cpa16(hbf +        hr_[s] * 144 + hj_[s] * 16, hhp + ho);
                cpa16(hbf + 9216 + hr_[s] * 144 + hj_[s] * 16, hlp + ho);
            }
            CP_COMMIT();
        }
        float xv[8][4];
        #pragma unroll
        for (int r = 0; r < 8; r++) {
            size_t xrow = ((size_t)(b0 + r * 8 + wid) * NT + t) * NG + u_g;
            xv[r][0] = xg[xrow];
            xv[r][1] = xg[xrow + 512];
            xv[r][2] = xg[xrow + 1024];
            xv[r][3] = xg[xrow + 1536];
        }
        for (int ch = 0; ch < 8; ch++) {
            int buf = ch & 1;
            if (ch + 1 < 8) {
                int k0 = (ch + 1) << 6;
                uint32_t wlb = sb + WL_OFF + (buf ^ 1) * WLB;
                uint32_t hbf = sb + H_OFF + (buf ^ 1) * HB;
                #pragma unroll
                for (int s = 0; s < 4; s++)
                    cpa16(wlb + wlr[s] * 144 + wlj[s] * 16, Wl + (size_t)wlr[s] * 512 + k0 + wlj[s] * 8);
                #pragma unroll
                for (int s = 0; s < 2; s++) {
                    size_t ho = ((size_t)(dir * 256 + b0 + hr_[s])) * 512 + k0 + hj_[s] * 8;
                    cpa16(hbf +        hr_[s] * 144 + hj_[s] * 16, hhp + ho);
                    cpa16(hbf + 9216 + hr_[s] * 144 + hj_[s] * 16, hlp + ho);
                }
                CP_COMMIT();
                asm volatile("cp.async.wait_group 1;" ::: "memory");
            } else {
                asm volatile("cp.async.wait_group 0;" ::: "memory");
            }
            __syncthreads();
            uint32_t hbf = sb + H_OFF + buf * HB;
            uint32_t wlb = sb + WL_OFF + buf * WLB;
            #pragma unroll
            for (int k16 = 0; k16 < 4; k16++) {
                uint32_t aro = (wm * 32 + (lane & 15)) * 144 + k16 * 32 + ((lane >> 4) << 4);
                uint32_t ah0[4], ah1[4], al0[4], al1[4];
                ldsm4(ah0, hbf + aro);
                ldsm4(ah1, hbf + aro + 16 * 144);
                ldsm4(al0, hbf + 9216 + aro);
                ldsm4(al1, hbf + 9216 + aro + 16 * 144);
                uint32_t broW = (wn * 32 + (lane & 15)) * WH_STRIDE + ch * 128 + k16 * 32 + ((lane >> 4) << 4);
                uint32_t brol = (wn * 32 + (lane & 15)) * 144 + k16 * 32 + ((lane >> 4) << 4);
                uint32_t bh0[4], bh1[4], bl0[4], bl1[4];
                ldsm4(bh0, sb + broW);
                ldsm4(bh1, sb + broW + 16 * WH_STRIDE);
                ldsm4(bl0, wlb + brol);
                ldsm4(bl1, wlb + brol + 16 * 144);
                mma16816(acc[0][0], ah0, bh0[0], bh0[2]);
                mma16816(acc[0][1], ah0, bh0[1], bh0[3]);
                mma16816(acc[0][2], ah0, bh1[0], bh1[2]);
                mma16816(acc[0][3], ah0, bh1[1], bh1[3]);
                mma16816(acc[1][0], ah1, bh0[0], bh0[2]);
                mma16816(acc[1][1], ah1, bh0[1], bh0[3]);
                mma16816(acc[1][2], ah1, bh1[0], bh1[2]);
                mma16816(acc[1][3], ah1, bh1[1], bh1[3]);
                mma16816(acc[0][0], al0, bh0[0], bh0[2]);
                mma16816(acc[0][1], al0, bh0[1], bh0[3]);
                mma16816(acc[0][2], al0, bh1[0], bh1[2]);
                mma16816(acc[0][3], al0, bh1[1], bh1[3]);
                mma16816(acc[1][0], al1, bh0[0], bh0[2]);
                mma16816(acc[1][1], al1, bh0[1], bh0[3]);
                mma16816(acc[1][2], al1, bh1[0], bh1[2]);
                mma16816(acc[1][3], al1, bh1[1], bh1[3]);
                mma16816(acc[0][0], ah0, bl0[0], bl0[2]);
                mma16816(acc[0][1], ah0, bl0[1], bl0[3]);
                mma16816(acc[0][2], ah0, bl1[0], bl1[2]);
                mma16816(acc[0][3], ah0, bl1[1], bl1[3]);
                mma16816(acc[1][0], ah1, bl0[0], bl0[2]);
                mma16816(acc[1][1], ah1, bl0[1], bl0[3]);
                mma16816(acc[1][2], ah1, bl1[0], bl1[2]);
                mma16816(acc[1][3], ah1, bl1[1], bl1[3]);
            }
            __syncthreads();
        }
        float* pre = (float*)(sm + H_OFF);
        #pragma unroll
        for (int mt = 0; mt < 2; mt++) {
            int row = wm * 32 + mt * 16 + (lane >> 2);
            #pragma unroll
            for (int n8 = 0; n8 < 4; n8++) {
                int col = wn * 32 + n8 * 8 + (lane & 3) * 2;
                pre[row * PS + col]           = acc[mt][n8][0];
                pre[row * PS + col + 1]       = acc[mt][n8][1];
                pre[(row + 8) * PS + col]     = acc[mt][n8][2];
                pre[(row + 8) * PS + col + 1] = acc[mt][n8][3];
            }
        }
        __syncthreads();
        #pragma unroll
        for (int r = 0; r < 8; r++) {
            int b_l = r * 8 + wid;
            int bg = b0 + b_l;
            int L = Lb[r];
            bool msk = t < L;
            float pi = pre[b_l * PS +       lane] + xv[r][0];
            float pf = pre[b_l * PS +  32 + lane] + xv[r][1];
            float pg = pre[b_l * PS +  64 + lane] + xv[r][2];
            float po = pre[b_l * PS +  96 + lane] + xv[r][3];
            float ig = sigm(pi), fg = sigm(pf), gv = tanhf(pg), og = sigm(po);
            float cn = fg * c_st[r] + ig * gv;
            float hn = og * tanhf(cn);
            c_st[r] = msk ? cn : c_st[r];
            float hw = msk ? hn : h_st[r];
            h_st[r] = hw;
            size_t hidx = ((size_t)(dir * 256 + bg)) * 512 + u_g;
            __nv_bfloat16 hh = __float2bfloat16_rn(hw);
            g_hh[wbuf][hidx] = hh;
            g_hl[wbuf][hidx] = __float2bfloat16_rn(hw - __bfloat162float(hh));
            int tout = dir ? (msk ? L - 1 - t : t) : t;
            float ho = msk ? hn : 0.f;
            size_t oidx = ((size_t)bg * NT + tout) * ND + dir * 512 + u_g;
            __nv_bfloat16 oh = __float2bfloat16_rn(ho);
            g_Ahi[oidx] = oh;
            g_Alo[oidx] = __float2bfloat16_rn(ho - __bfloat162float(oh));
        }
        group_barrier(grp);
    }
}

// ---------------- BN / attention / phases ----------------
__global__ void k_colstats() {
    int col = blockIdx.x * 32 + threadIdx.x;
    int r0 = blockIdx.y * (NBT / 32);
    float s = 0.f, q = 0.f;
    for (int r = r0 + threadIdx.y; r < r0 + NBT / 32; r += 8) {
        float v = g_z[(size_t)r * ND + col];
        s += v; q += v * v;
    }
    __shared__ float ss[8][33], qq[8][33];
    ss[threadIdx.y][threadIdx.x] = s;
    qq[threadIdx.y][threadIdx.x] = q;
    __syncthreads();
    if (threadIdx.y == 0) {
        #pragma unroll
        for (int k = 1; k < 8; k++) { s += ss[k][threadIdx.x]; q += qq[k][threadIdx.x]; }
        atomicAdd(&g_colsum[col], s);
        atomicAdd(&g_colsq[col], q);
    }
}

__global__ void k_finalize() {
    int d = blockIdx.x * 256 + threadIdx.x;
    if (d < ND) {
        float mean = g_colsum[d] / (float)NBT;
        float var  = g_colsq[d] / (float)NBT - mean * mean;
        g_mu[d] = mean;
        g_rs[d] = rsqrtf(var + 1e-5f);
    }
}

__global__ void k_alpha(const float* __restrict__ s2w) {
    size_t row = blockIdx.x;
    float p = 0.f;
    for (int d = threadIdx.x; d < ND; d += 256) {
        float v = (g_z[row * ND + d] - g_mu[d]) * g_rs[d];
        p += leakyf(v) * s2w[d];
    }
    p = blockReduceSum(p);
    if (threadIdx.x == 0) g_alpha[row] = p;
}

__global__ void k_asum(const int* __restrict__ lens) {
    int b = blockIdx.x;
    int L = lens[b];
    float s = 0.f;
    for (int t = threadIdx.x; t < L; t += 128) s += g_alpha[b * NT + t];
    s = blockReduceSum(s);
    if (threadIdx.x == 0) g_asum[b] = s + 1e-9f;
}

// U from bf16 hi/lo Hseq (exact reconstruction to 2^-16)
__global__ void k_U(const int* __restrict__ lens) {
    int b = blockIdx.y;
    int d = blockIdx.x * 256 + threadIdx.x;
    int L = lens[b];
    float inv = 1.f / g_asum[b];
    float s = 0.f;
    for (int t = 0; t < L; t++) {
        size_t idx = ((size_t)b * NT + t) * ND + d;
        float h = __bfloat162float(g_Ahi[idx]) + __bfloat162float(g_Alo[idx]);
        s += g_alpha[b * NT + t] * h;
    }
    g_U[(size_t)b * ND + d] = s * inv;
}

__global__ void k_L(const int* __restrict__ label3, float* __restrict__ outL) {
    for (int i = threadIdx.x; i < NE * NCC; i += 256) outL[i] = 0.f;
    __syncthreads();
    if (threadIdx.x < NE) {
        for (int j = 0; j < 3; j++) {
            int v = label3[threadIdx.x * 3 + j];
            if (v >= 0) outL[threadIdx.x * NCC + v] = 1.f;
        }
    }
}

__global__ void k_chunk() {
    int e = blockIdx.y, n = blockIdx.x;
    const float* __restrict__ emo  = g_U + (size_t)e * ND;
    const float* __restrict__ cau0 = g_U + (size_t)(NE + n * CKS) * ND;
    __shared__ float logits[CKS];
    __shared__ float sc[CKS];
    int w = threadIdx.x >> 5, lane = threadIdx.x & 31;
    float a0 = 0.f, a1 = 0.f;
    for (int d = lane; d < ND; d += 32) {
        float ed = emo[d];
        a0 += ed * cau0[(size_t)(2 * w) * ND + d];
        a1 += ed * cau0[(size_t)(2 * w + 1) * ND + d];
    }
    #pragma unroll
    for (int o = 16; o; o >>= 1) {
        a0 += __shfl_down_sync(0xffffffffu, a0, o);
        a1 += __shfl_down_sync(0xffffffffu, a1, o);
    }
    if (lane == 0) { logits[2 * w] = a0; logits[2 * w + 1] = a1; }
    __syncthreads();
    if (threadIdx.x == 0) {
        float mx = logits[0];
        for (int c = 1; c < CKS; c++) mx = fmaxf(mx, logits[c]);
        float s = 0.f;
        for (int c = 0; c < CKS; c++) { sc[c] = expf(logits[c] - mx); s += sc[c]; }
        float si = 1.f / s;
        for (int c = 0; c < CKS; c++) sc[c] *= si;
    }
    __syncthreads();
    for (int d = threadIdx.x; d < ND; d += 256) {
        float v = 0.f;
        #pragma unroll
        for (int c = 0; c < CKS; c++) v += sc[c] * cau0[(size_t)c * ND + d];
        g_chunk[(size_t)(e * NCK + n) * ND + d] = v;
    }
}

// delta2 -> bf16 split direct
__global__ void k_delta2(const float* __restrict__ pos) {
    int e = blockIdx.y, n = blockIdx.x;
    int row = e * NCK + n;
    const float* __restrict__ emo = g_U + (size_t)e * ND;
    const float* __restrict__ ch  = g_chunk + (size_t)row * ND;
    float p = 0.f;
    for (int d = threadIdx.x; d < ND; d += 256) {
        float dd = emo[d] - ch[d];
        p += dd * dd;
    }
    p = blockReduceSum(p);
    float dist = sqrtf(p);
    size_t base = (size_t)row * KP2;
    for (int f = threadIdx.x; f < KP2; f += 256) {
        float v;
        if (f < ND) v = emo[f];
        else if (f < 2 * ND) v = ch[f - ND];
        else if (f == 2 * ND) v = dist;
        else if (f < 3 * ND + 1) v = emo[f - 2 * ND - 1] * ch[f - 2 * ND - 1];
        else if (f < NF2) v = pos[(size_t)row * NP + (f - (3 * ND + 1))];
        else v = 0.f;
        __nv_bfloat16 h = __float2bfloat16_rn(v);
        g_Ahi[base + f] = h;
        g_Alo[base + f] = __float2bfloat16_rn(v - __bfloat162float(h));
    }
}

__global__ void k_bn2() {
    int e = blockIdx.y;
    int d = blockIdx.x * 256 + threadIdx.x;
    float vals[NCK];
    float s = 0.f, q = 0.f;
    #pragma unroll
    for (int n = 0; n < NCK; n++) {
        float v = g_hid2[(size_t)(e * NCK + n) * ND + d];
        vals[n] = v; s += v; q += v * v;
    }
    float mean = s / (float)NCK;
    float var = q / (float)NCK - mean * mean;
    float r = rsqrtf(var + 1e-5f);
    #pragma unroll
    for (int n = 0; n < NCK; n++)
        g_hid2[(size_t)(e * NCK + n) * ND + d] = leakyf((vals[n] - mean) * r);
}

__global__ void k_out2(const float* __restrict__ Wow, const float* __restrict__ Wob,
                       float* __restrict__ out) {
    int row = blockIdx.x;
    float p0 = 0.f, p1 = 0.f;
    for (int d = threadIdx.x; d < ND; d += 256) {
        float h = g_hid2[(size_t)row * ND + d];
        p0 += h * Wow[d];
        p1 += h * Wow[ND + d];
    }
    p0 = blockReduceSum(p0);
    p1 = blockReduceSum(p1);
    if (threadIdx.x == 0) {
        float l0 = p0 + Wob[0], l1 = p1 + Wob[1];
        float mx = fmaxf(l0, l1);
        float lse = mx + logf(expf(l0 - mx) + expf(l1 - mx));
        out[row * 2 + 0] = l0 - lse;
        out[row * 2 + 1] = l1 - lse;
        g_extra[row] = (l1 > l0) ? 1.f : 0.f;
    }
}

// delta3 -> bf16 split direct
__global__ void k_delta3(const float* __restrict__ dis) {
    int e = blockIdx.y, j = blockIdx.x;
    const float* __restrict__ emo = g_U + (size_t)e * ND;
    const float* __restrict__ y   = g_U + (size_t)(NE + j) * ND;
    float p = 0.f;
    for (int d = threadIdx.x; d < ND; d += 256) {
        float dd = emo[d] - y[d];
        p += dd * dd;
    }
    p = blockReduceSum(p);
    float dist = sqrtf(p);
    float ext = g_extra[e * NCK + (j >> 4)];
    size_t base = (size_t)(e * NCC + j) * KP3;
    for (int f = threadIdx.x; f < KP3; f += 256) {
        float v;
        if (f < ND) v = emo[f];
        else if (f < 2 * ND) v = y[f - ND];
        else if (f == 2 * ND) v = dist;
        else if (f < 3 * ND + 1) v = emo[f - 2 * ND - 1] * y[f - 2 * ND - 1];
        else if (f < 3 * ND + 1 + NP) v = dis[(size_t)(e * NCC + j) * NP + (f - (3 * ND + 1))];
        else if (f < NF3) v = ext;
        else v = 0.f;
        __nv_bfloat16 h = __float2bfloat16_rn(v);
        g_Ahi[base + f] = h;
        g_Alo[base + f] = __float2bfloat16_rn(v - __bfloat162float(h));
    }
}

__global__ void k_bn3() {
    int e = blockIdx.y;
    int d = blockIdx.x * 256 + threadIdx.x;
    float s = 0.f, q = 0.f;
    for (int j = 0; j < NCC; j++) {
        float v = g_h3[(size_t)(e * NCC + j) * ND + d];
        s += v; q += v * v;
    }
    float mean = s / (float)NCC;
    float var = q / (float)NCC - mean * mean;
    float r = rsqrtf(var + 1e-5f);
    for (int j = 0; j < NCC; j++) {
        size_t idx = (size_t)(e * NCC + j) * ND + d;
        g_h3[idx] = leakyf((g_h3[idx] - mean) * r);
    }
}

__global__ void k_cls(const float* __restrict__ clsw, const float* __restrict__ clsb,
                      float* __restrict__ outp) {
    int e = blockIdx.y, j = blockIdx.x;
    int row = e * NCC + j;
    float p0 = 0.f, p1 = 0.f;
    for (int d = threadIdx.x; d < ND; d += 256) {
        float h = g_h3[(size_t)row * ND + d];
        p0 += h * clsw[d];
        p1 += h * clsw[ND + d];
    }
    p0 = blockReduceSum(p0);
    p1 = blockReduceSum(p1);
    if (threadIdx.x == 0) {
        float l0 = p0 + clsb[0], l1 = p1 + clsb[1];
        float mx = fmaxf(l0, l1);
        float lse = mx + logf(expf(l0 - mx) + expf(l1 - mx));
        outp[row * 2 + 0] = l0 - lse;
        outp[row * 2 + 1] = l1 - lse;
    }
}

// ---------------- host launcher ----------------
static inline int cdiv(int a, int b) { return (a + b - 1) / b; }

extern "C" void kernel_launch(void* const* d_in, const int* in_sizes, int n_in,
                              void* d_out, int out_size) {
    const float *word, *pos, *dis, *Wihf, *Whhf, *bihf, *bhhf, *Wihb, *Whhb, *bihb, *bhhb;
    const float *s1w, *s1b, *s2w, *W2w, *W2b, *Wow, *Wob, *W3w, *W3b, *clsw, *clsb;
    const int *lens, *label3;
    if (in_sizes[3] == 256) {
        word = (const float*)d_in[0];  pos = (const float*)d_in[1];  dis = (const float*)d_in[2];
        lens = (const int*)d_in[3];    label3 = (const int*)d_in[4];
        Wihf = (const float*)d_in[7];  Whhf = (const float*)d_in[8];
        bihf = (const float*)d_in[9];  bhhf = (const float*)d_in[10];
        Wihb = (const float*)d_in[11]; Whhb = (const float*)d_in[12];
        bihb = (const float*)d_in[13]; bhhb = (const float*)d_in[14];
        s1w = (const float*)d_in[15];  s1b = (const float*)d_in[16]; s2w = (const float*)d_in[17];
        W2w = (const float*)d_in[18];  W2b = (const float*)d_in[19];
        Wow = (const float*)d_in[20];  Wob = (const float*)d_in[21];
        W3w = (const float*)d_in[22];  W3b = (const float*)d_in[23];
        clsw = (const float*)d_in[24]; clsb = (const float*)d_in[25];
    } else {
        word = (const float*)d_in[0];  pos = (const float*)d_in[1];  dis = (const float*)d_in[2];
        Wihf = (const float*)d_in[3];  Whhf = (const float*)d_in[4];
        bihf = (const float*)d_in[5];  bhhf = (const float*)d_in[6];
        Wihb = (const float*)d_in[7];  Whhb = (const float*)d_in[8];
        bihb = (const float*)d_in[9];  bhhb = (const float*)d_in[10];
        s1w = (const float*)d_in[11];  s1b = (const float*)d_in[12]; s2w = (const float*)d_in[13];
        W2w = (const float*)d_in[14];  W2b = (const float*)d_in[15];
        Wow = (const float*)d_in[16];  Wob = (const float*)d_in[17];
        W3w = (const float*)d_in[18];  W3b = (const float*)d_in[19];
        clsw = (const float*)d_in[20]; clsb = (const float*)d_in[21];
        lens = (const int*)d_in[22];   label3 = (const int*)d_in[23];
    }
    float* out = (float*)d_out;
    float* out_p3 = out + NE * NCK * 2;
    float* out_L  = out_p3 + NE * NCC * 2;

    void *p_xgf, *p_xgb, *p_z, *p_rev, *p_bf, *p_bb, *p_h2, *p_h3;
    void *p_Ahi, *p_Alo, *p_Bhi, *p_Blo;
    cudaGetSymbolAddress(&p_xgf, g_xg_f);
    cudaGetSymbolAddress(&p_xgb, g_xg_b);
    cudaGetSymbolAddress(&p_z, g_z);
    cudaGetSymbolAddress(&p_rev, g_rev);
    cudaGetSymbolAddress(&p_bf, g_biasf);
    cudaGetSymbolAddress(&p_bb, g_biasb);
    cudaGetSymbolAddress(&p_h2, g_hid2);
    cudaGetSymbolAddress(&p_h3, g_h3);
    cudaGetSymbolAddress(&p_Ahi, g_Ahi);
    cudaGetSymbolAddress(&p_Alo, g_Alo);
    cudaGetSymbolAddress(&p_Bhi, g_Bhi);
    cudaGetSymbolAddress(&p_Blo, g_Blo);
    __nv_bfloat16* Ahi = (__nv_bfloat16*)p_Ahi;
    __nv_bfloat16* Alo = (__nv_bfloat16*)p_Alo;
    __nv_bfloat16* Bhi = (__nv_bfloat16*)p_Bhi;
    __nv_bfloat16* Blo = (__nv_bfloat16*)p_Blo;

    cudaFuncSetAttribute(k_mgemm, cudaFuncAttributeMaxDynamicSharedMemorySize, MG_SMEM);
    cudaFuncSetAttribute(k_lstm_all, cudaFuncAttributeMaxDynamicSharedMemorySize, LS_SMEM);

    // 1. prep + weight reorder/split
    k_prep<<<1024, 256>>>(bihf, bhhf, bihb, bhhb, lens);
    k_wsplit<<<cdiv(2 * 2048 * 512, 256), 256>>>(Whhf, Whhb);

    // 2. split word + Wih, GEMM xg_f / xg_b
    k_split<<<cdiv(NBT * ND / 4, 256), 256>>>(word, Ahi, Alo, NBT, ND, ND);
    k_split<<<cdiv(NG * ND / 4, 256), 256>>>(Wihf, Bhi, Blo, NG, ND, ND);
    k_mgemm<<<dim3(NG / 128, NBT / 128), 256, MG_SMEM>>>(Ahi, Alo, Bhi, Blo,
        (const float*)p_bf, (float*)p_xgf, NBT, NG, ND, nullptr);
    k_split<<<cdiv(NG * ND / 4, 256), 256>>>(Wihb, Bhi, Blo, NG, ND, ND);
    k_mgemm<<<dim3(NG / 128, NBT / 128), 256, MG_SMEM>>>(Ahi, Alo, Bhi, Blo,
        (const float*)p_bb, (float*)p_xgb, NBT, NG, ND, (const int*)p_rev);

    // 3. persistent bidirectional LSTM (group barriers; writes bf16 Hseq into Ahi/Alo)
    k_lstm_all<<<LS_CTAS, 256, LS_SMEM>>>(lens);

    // 4. z = Hseq @ s1_w^T + s1_b
    k_split<<<cdiv(ND * ND / 4, 256), 256>>>(s1w, Bhi, Blo, ND, ND, ND);
    k_mgemm<<<dim3(ND / 128, NBT / 128), 256, MG_SMEM>>>(Ahi, Alo, Bhi, Blo,
        s1b, (float*)p_z, NBT, ND, ND, nullptr);

    // 5. BN stats, alpha, U
    k_colstats<<<dim3(ND / 32, 32), dim3(32, 8)>>>();
    k_finalize<<<4, 256>>>();
    k_alpha<<<NBT, 256>>>(s2w);
    k_asum<<<NB, 128>>>(lens);
    k_U<<<dim3(ND / 256, NB), 256>>>(lens);

    // 6. L output
    k_L<<<1, 256>>>(label3, out_L);

    // 7. phase 2
    k_chunk<<<dim3(NCK, NE), 256>>>();
    k_delta2<<<dim3(NCK, NE), 256>>>(pos);
    k_split<<<cdiv(ND * KP2 / 4, 256), 256>>>(W2w, Bhi, Blo, ND, NF2, KP2);
    k_mgemm<<<dim3(ND / 128, (NE * NCK) / 128), 256, MG_SMEM>>>(Ahi, Alo, Bhi, Blo,
        W2b, (float*)p_h2, NE * NCK, ND, KP2, nullptr);
    k_bn2<<<dim3(ND / 256, NE), 256>>>();
    k_out2<<<NE * NCK, 256>>>(Wow, Wob, out);

    // 8. phase 3
    k_delta3<<<dim3(NCC, NE), 256>>>(dis);
    k_split<<<cdiv(ND * KP3 / 4, 256), 256>>>(W3w, Bhi, Blo, ND, NF3, KP3);
    k_mgemm<<<dim3(ND / 128, (NE * NCC) / 128), 256, MG_SMEM>>>(Ahi, Alo, Bhi, Blo,
        W3b, (float*)p_h3, NE * NCC, ND, KP3, nullptr);
    k_bn3<<<dim3(ND / 256, NE), 256>>>();
    k_cls<<<dim3(NCC, NE), 256>>>(clsw, clsb, out_p3);
}